// round 5
// baseline (speedup 1.0000x reference)
#include <cuda_runtime.h>
#include <cuda_bf16.h>
#include <stdint.h>
#include <math.h>

// ---------------------------------------------------------------------------
// DiT block. Round 5: RNA tf32 rounding everywhere (accuracy margin),
// 128x256 GEMM block tile with 64x64 warp tiles, fused QKV launch.
//   B=2, N=2048, C=1024, H=16, D=64, F=4096, M=B*N=4096
// ---------------------------------------------------------------------------

#define Mrows 4096
#define Cdim  1024
#define Fdim  4096
#define Bb    2
#define Nn_   2048
#define Hh    16
#define Dd    64

#define OFF_H   ((size_t)0)
#define OFF_Q   ((size_t)4194304)
#define OFF_K   ((size_t)8388608)
#define OFF_V   ((size_t)12582912)
#define OFF_ATT ((size_t)16777216)
#define OFF_X2  ((size_t)20971520)
#define OFF_MLP ((size_t)25165824)
__device__ float g_scratch[41943040];

__device__ __forceinline__ uint32_t f2tf32(float x) {
    uint32_t t;
    asm("cvt.rna.tf32.f32 %0, %1;" : "=r"(t) : "f"(x));
    return t;
}

#define MMA_TF32(d, a, b)                                                     \
    asm volatile(                                                             \
        "mma.sync.aligned.m16n8k8.row.col.f32.tf32.tf32.f32 "                 \
        "{%0,%1,%2,%3}, {%4,%5,%6,%7}, {%8,%9}, {%0,%1,%2,%3};"               \
        : "+f"(d[0]), "+f"(d[1]), "+f"(d[2]), "+f"(d[3])                      \
        : "r"(a[0]), "r"(a[1]), "r"(a[2]), "r"(a[3]), "r"(b[0]), "r"(b[1]))

#define CP_ASYNC16(dst_u32, src_ptr)                                          \
    asm volatile("cp.async.cg.shared.global [%0], [%1], 16;"                  \
                 :: "r"(dst_u32), "l"(src_ptr))
#define CP_COMMIT()  asm volatile("cp.async.commit_group;")
#define CP_WAIT(n)   asm volatile("cp.async.wait_group %0;" :: "n"(n))

// ---------------------------------------------------------------------------
// LayerNorm: one block (256 thr) per row of 1024
// ---------------------------------------------------------------------------
__global__ void __launch_bounds__(256) ln_kernel(
    const float* __restrict__ x, const float* __restrict__ g,
    const float* __restrict__ b, float* __restrict__ out)
{
    __shared__ float red[16];
    const int row = blockIdx.x;
    const int t = threadIdx.x;
    const float4 xv = ((const float4*)(x + (size_t)row * Cdim))[t];
    float s  = xv.x + xv.y + xv.z + xv.w;
    float ss = xv.x*xv.x + xv.y*xv.y + xv.z*xv.z + xv.w*xv.w;
    #pragma unroll
    for (int o = 16; o > 0; o >>= 1) {
        s  += __shfl_xor_sync(0xffffffffu, s,  o);
        ss += __shfl_xor_sync(0xffffffffu, ss, o);
    }
    const int w = t >> 5;
    if ((t & 31) == 0) { red[w] = s; red[8 + w] = ss; }
    __syncthreads();
    float ts = 0.f, tss = 0.f;
    #pragma unroll
    for (int i = 0; i < 8; i++) { ts += red[i]; tss += red[8 + i]; }
    const float mean = ts * (1.0f / Cdim);
    const float var  = tss * (1.0f / Cdim) - mean * mean;
    const float inv  = rsqrtf(var + 1e-6f);
    const float4 gv = ((const float4*)g)[t];
    const float4 bv = ((const float4*)b)[t];
    float4 o;
    o.x = (xv.x - mean) * inv * gv.x + bv.x;
    o.y = (xv.y - mean) * inv * gv.y + bv.y;
    o.z = (xv.z - mean) * inv * gv.z + bv.z;
    o.w = (xv.w - mean) * inv * gv.w + bv.w;
    ((float4*)(out + (size_t)row * Cdim))[t] = o;
}

// ---------------------------------------------------------------------------
// tf32 GEMM, cp.async double-buffered, 128x256 block tile.
// out[z][M,Nc] = A[M,K] @ W[z][Nc,K]^T + bias[z] (+GELU)(+resid)
// 256 threads = 8 warps (2 M x 4 N), warp tile 64x64.
// smem: A[2][128][36] + B[2][256][36] floats = 110592 B.
// ---------------------------------------------------------------------------
#define GS 36
#define ABUF (128 * GS)
#define BBUF (256 * GS)
#define BOFF (2 * ABUF)
#define GEMM_SMEM ((2 * ABUF + 2 * BBUF) * 4)

struct GemmSet {
    const float* W[3];
    const float* bias[3];
    float*       out[3];
};

__global__ void __launch_bounds__(256, 1) tgemm_kernel(
    const float* __restrict__ A, GemmSet gs, const float* __restrict__ residual,
    int M, int Nc, int K, int gelu)
{
    extern __shared__ float smf[];
    const uint32_t sb = (uint32_t)__cvta_generic_to_shared(smf);

    const int z = blockIdx.z;
    const float* __restrict__ Wp   = gs.W[z];
    const float* __restrict__ bias = gs.bias[z];
    float* __restrict__ out        = gs.out[z];

    const int tid  = threadIdx.x;
    const int wid  = tid >> 5;
    const int lane = tid & 31;
    const int lr   = lane >> 2;
    const int lc   = lane & 3;
    const int warpM = (wid & 1) * 64;
    const int warpN = (wid >> 1) * 64;
    const int bm = blockIdx.y * 128, bn = blockIdx.x * 256;

    float acc[4][8][4];
    #pragma unroll
    for (int i = 0; i < 4; i++)
        #pragma unroll
        for (int j = 0; j < 8; j++)
            #pragma unroll
            for (int r = 0; r < 4; r++) acc[i][j][r] = 0.f;

    const int nk = K >> 5;

    #define LOAD_TILE(buf, k0)                                                \
    do {                                                                      \
        _Pragma("unroll")                                                     \
        for (int p = 0; p < 4; p++) {                                         \
            const int idx = tid + p * 256;                                    \
            const int row = idx >> 3;                                         \
            const int col = (idx & 7) << 2;                                   \
            const uint32_t da = sb + (uint32_t)((((buf) * ABUF) + row * GS + col) * 4); \
            CP_ASYNC16(da, A + (size_t)(bm + row) * K + (k0) + col);          \
        }                                                                     \
        _Pragma("unroll")                                                     \
        for (int p = 0; p < 8; p++) {                                         \
            const int idx = tid + p * 256;                                    \
            const int row = idx >> 3;                                         \
            const int col = (idx & 7) << 2;                                   \
            const uint32_t db = sb + (uint32_t)((BOFF + (buf) * BBUF + row * GS + col) * 4); \
            CP_ASYNC16(db, Wp + (size_t)(bn + row) * K + (k0) + col);         \
        }                                                                     \
    } while (0)

    LOAD_TILE(0, 0);
    CP_COMMIT();

    for (int kt = 0; kt < nk; kt++) {
        const int buf = kt & 1;
        if (kt + 1 < nk) {
            LOAD_TILE(buf ^ 1, (kt + 1) << 5);
            CP_COMMIT();
            CP_WAIT(1);
        } else {
            CP_WAIT(0);
        }
        __syncthreads();

        const float* Ab  = smf + buf * ABUF;
        const float* Bbf = smf + BOFF + buf * BBUF;
        #pragma unroll
        for (int ks = 0; ks < 4; ks++) {
            const int kk = ks * 8;
            uint32_t af[4][4], bf[8][2];
            #pragma unroll
            for (int i = 0; i < 4; i++) {
                const int rb = warpM + i * 16;
                af[i][0] = f2tf32(Ab[(rb + lr) * GS + kk + lc]);
                af[i][1] = f2tf32(Ab[(rb + lr + 8) * GS + kk + lc]);
                af[i][2] = f2tf32(Ab[(rb + lr) * GS + kk + lc + 4]);
                af[i][3] = f2tf32(Ab[(rb + lr + 8) * GS + kk + lc + 4]);
            }
            #pragma unroll
            for (int j = 0; j < 8; j++) {
                const int cb = warpN + j * 8;
                bf[j][0] = f2tf32(Bbf[(cb + lr) * GS + kk + lc]);
                bf[j][1] = f2tf32(Bbf[(cb + lr) * GS + kk + lc + 4]);
            }
            #pragma unroll
            for (int i = 0; i < 4; i++)
                #pragma unroll
                for (int j = 0; j < 8; j++)
                    MMA_TF32(acc[i][j], af[i], bf[j]);
        }
        __syncthreads();
    }

    // epilogue
    #pragma unroll
    for (int i = 0; i < 4; i++) {
        const int row0 = bm + warpM + i * 16 + lr;
        #pragma unroll
        for (int j = 0; j < 8; j++) {
            const int col = bn + warpN + j * 8 + (lc << 1);
            const float b0 = __ldg(&bias[col]);
            const float b1 = __ldg(&bias[col + 1]);
            float v0 = acc[i][j][0] + b0;
            float v1 = acc[i][j][1] + b1;
            float v2 = acc[i][j][2] + b0;
            float v3 = acc[i][j][3] + b1;
            if (gelu) {
                v0 = 0.5f * v0 * (1.0f + erff(v0 * 0.70710678118654752f));
                v1 = 0.5f * v1 * (1.0f + erff(v1 * 0.70710678118654752f));
                v2 = 0.5f * v2 * (1.0f + erff(v2 * 0.70710678118654752f));
                v3 = 0.5f * v3 * (1.0f + erff(v3 * 0.70710678118654752f));
            }
            if (residual) {
                v0 += residual[(size_t)row0 * Nc + col];
                v1 += residual[(size_t)row0 * Nc + col + 1];
                v2 += residual[(size_t)(row0 + 8) * Nc + col];
                v3 += residual[(size_t)(row0 + 8) * Nc + col + 1];
            }
            *(float2*)(out + (size_t)row0 * Nc + col)       = make_float2(v0, v1);
            *(float2*)(out + (size_t)(row0 + 8) * Nc + col) = make_float2(v2, v3);
        }
    }
}

// ---------------------------------------------------------------------------
// RoPE applied in place to q or k laid out as [B*N, C] with col = h*64 + d
// ---------------------------------------------------------------------------
__global__ void __launch_bounds__(256) rope_kernel(
    float* __restrict__ t, const float* __restrict__ cosb,
    const float* __restrict__ sinb)
{
    int idx = blockIdx.x * 256 + threadIdx.x;
    const int d = idx & 31; idx >>= 5;
    const int h = idx & (Hh - 1); idx >>= 4;
    const int n = idx & (Nn_ - 1); idx >>= 11;
    const int b = idx;
    const size_t base = ((size_t)(b * Nn_ + n)) * Cdim + h * Dd;
    const float x1 = t[base + d];
    const float x2 = t[base + d + 32];
    const float c1 = cosb[n * Dd + d],      s1 = sinb[n * Dd + d];
    const float c2 = cosb[n * Dd + d + 32], s2 = sinb[n * Dd + d + 32];
    t[base + d]      = x1 * c1 - x2 * s1;
    t[base + d + 32] = x2 * c2 + x1 * s2;
}

// ---------------------------------------------------------------------------
// Flash attention on tensor cores (tf32 mma RNA-rounded, fp32 accumulate).
// ---------------------------------------------------------------------------
#define QSS 68
#define VSS 72
#define F_QS 0
#define F_KS (128 * QSS)
#define F_VS (F_KS + 64 * QSS)
#define F_PS (F_VS + 64 * VSS)
#define FLASH_SMEM ((F_PS + 128 * QSS) * 4)

__global__ void __launch_bounds__(256) flash_kernel(
    const float* __restrict__ q, const float* __restrict__ k,
    const float* __restrict__ v, float* __restrict__ out)
{
    extern __shared__ float sm[];
    float* Qs = sm + F_QS;
    float* Ks = sm + F_KS;
    float* Vs = sm + F_VS;
    float* Ps = sm + F_PS;

    const int tid  = threadIdx.x;
    const int wid  = tid >> 5;
    const int lane = tid & 31;
    const int lr   = lane >> 2;
    const int lc   = lane & 3;
    const int rm   = wid * 16;

    const int bh = blockIdx.y;
    const int b = bh >> 4;
    const int h = bh & 15;
    const int q0 = blockIdx.x * 128;
    const float qscale = 0.125f * 1.4426950408889634f;  // D^-1/2 * log2(e)

    const float* qb = q + ((size_t)(b * Nn_ + q0)) * Cdim + h * Dd;
    #pragma unroll
    for (int i = 0; i < 8; i++) {
        const int idx = tid + i * 256;
        const int r = idx >> 4;
        const int c = (idx & 15) << 2;
        float4 t4 = *(const float4*)(qb + (size_t)r * Cdim + c);
        t4.x *= qscale; t4.y *= qscale; t4.z *= qscale; t4.w *= qscale;
        *(float4*)&Qs[r * QSS + c] = t4;
    }

    float m0 = -1e30f, m1 = -1e30f, l0 = 0.f, l1 = 0.f;
    float oacc[8][4];
    #pragma unroll
    for (int nt = 0; nt < 8; nt++)
        #pragma unroll
        for (int r = 0; r < 4; r++) oacc[nt][r] = 0.f;

    for (int kv0 = 0; kv0 < Nn_; kv0 += 64) {
        __syncthreads();
        const float* kb = k + ((size_t)(b * Nn_ + kv0)) * Cdim + h * Dd;
        const float* vb = v + ((size_t)(b * Nn_ + kv0)) * Cdim + h * Dd;
        #pragma unroll
        for (int i = 0; i < 4; i++) {
            const int idx = tid + i * 256;
            const int r = idx >> 4;
            const int c = (idx & 15) << 2;
            *(float4*)&Ks[r * QSS + c] = *(const float4*)(kb + (size_t)r * Cdim + c);
            *(float4*)&Vs[r * VSS + c] = *(const float4*)(vb + (size_t)r * Cdim + c);
        }
        __syncthreads();

        // S = Qs @ Ks^T
        float sacc[8][4];
        #pragma unroll
        for (int nt = 0; nt < 8; nt++)
            #pragma unroll
            for (int r = 0; r < 4; r++) sacc[nt][r] = 0.f;
        #pragma unroll
        for (int ks = 0; ks < 8; ks++) {
            const int kk = ks * 8;
            uint32_t af[4];
            af[0] = f2tf32(Qs[(rm + lr) * QSS + kk + lc]);
            af[1] = f2tf32(Qs[(rm + lr + 8) * QSS + kk + lc]);
            af[2] = f2tf32(Qs[(rm + lr) * QSS + kk + lc + 4]);
            af[3] = f2tf32(Qs[(rm + lr + 8) * QSS + kk + lc + 4]);
            #pragma unroll
            for (int nt = 0; nt < 8; nt++) {
                uint32_t bf[2];
                bf[0] = f2tf32(Ks[(nt * 8 + lr) * QSS + kk + lc]);
                bf[1] = f2tf32(Ks[(nt * 8 + lr) * QSS + kk + lc + 4]);
                MMA_TF32(sacc[nt], af, bf);
            }
        }

        // online softmax
        float mx0 = -1e30f, mx1 = -1e30f;
        #pragma unroll
        for (int nt = 0; nt < 8; nt++) {
            mx0 = fmaxf(mx0, fmaxf(sacc[nt][0], sacc[nt][1]));
            mx1 = fmaxf(mx1, fmaxf(sacc[nt][2], sacc[nt][3]));
        }
        #pragma unroll
        for (int o = 1; o < 4; o <<= 1) {
            mx0 = fmaxf(mx0, __shfl_xor_sync(0xffffffffu, mx0, o, 4));
            mx1 = fmaxf(mx1, __shfl_xor_sync(0xffffffffu, mx1, o, 4));
        }
        const float mn0 = fmaxf(m0, mx0);
        const float mn1 = fmaxf(m1, mx1);
        const float al0 = exp2f(m0 - mn0);
        const float al1 = exp2f(m1 - mn1);
        float rs0 = 0.f, rs1 = 0.f;
        #pragma unroll
        for (int nt = 0; nt < 8; nt++) {
            const float p0 = exp2f(sacc[nt][0] - mn0);
            const float p1 = exp2f(sacc[nt][1] - mn0);
            const float p2 = exp2f(sacc[nt][2] - mn1);
            const float p3 = exp2f(sacc[nt][3] - mn1);
            rs0 += p0 + p1; rs1 += p2 + p3;
            *(float2*)&Ps[(rm + lr) * QSS + nt * 8 + 2 * lc]     = make_float2(p0, p1);
            *(float2*)&Ps[(rm + lr + 8) * QSS + nt * 8 + 2 * lc] = make_float2(p2, p3);
        }
        #pragma unroll
        for (int o = 1; o < 4; o <<= 1) {
            rs0 += __shfl_xor_sync(0xffffffffu, rs0, o, 4);
            rs1 += __shfl_xor_sync(0xffffffffu, rs1, o, 4);
        }
        l0 = l0 * al0 + rs0;  m0 = mn0;
        l1 = l1 * al1 + rs1;  m1 = mn1;
        #pragma unroll
        for (int nt = 0; nt < 8; nt++) {
            oacc[nt][0] *= al0; oacc[nt][1] *= al0;
            oacc[nt][2] *= al1; oacc[nt][3] *= al1;
        }
        __syncwarp();

        // O += P @ V
        #pragma unroll
        for (int ks = 0; ks < 8; ks++) {
            const int kk = ks * 8;
            uint32_t af[4];
            af[0] = f2tf32(Ps[(rm + lr) * QSS + kk + lc]);
            af[1] = f2tf32(Ps[(rm + lr + 8) * QSS + kk + lc]);
            af[2] = f2tf32(Ps[(rm + lr) * QSS + kk + lc + 4]);
            af[3] = f2tf32(Ps[(rm + lr + 8) * QSS + kk + lc + 4]);
            #pragma unroll
            for (int nt = 0; nt < 8; nt++) {
                uint32_t bf[2];
                bf[0] = f2tf32(Vs[(kk + lc) * VSS + nt * 8 + lr]);
                bf[1] = f2tf32(Vs[(kk + lc + 4) * VSS + nt * 8 + lr]);
                MMA_TF32(oacc[nt], af, bf);
            }
        }
    }

    const float il0 = 1.0f / l0;
    const float il1 = 1.0f / l1;
    float* ob = out + ((size_t)(b * Nn_ + q0 + rm)) * Cdim + h * Dd;
    #pragma unroll
    for (int nt = 0; nt < 8; nt++) {
        const int col = nt * 8 + 2 * lc;
        *(float2*)(ob + (size_t)lr * Cdim + col) =
            make_float2(oacc[nt][0] * il0, oacc[nt][1] * il0);
        *(float2*)(ob + (size_t)(lr + 8) * Cdim + col) =
            make_float2(oacc[nt][2] * il1, oacc[nt][3] * il1);
    }
}

// ---------------------------------------------------------------------------
extern "C" void kernel_launch(void* const* d_in, const int* in_sizes, int n_in,
                              void* d_out, int out_size)
{
    const float* x    = (const float*)d_in[0];
    const float* rcos = (const float*)d_in[1];
    const float* rsin = (const float*)d_in[2];
    const float* g1   = (const float*)d_in[3];
    const float* be1  = (const float*)d_in[4];
    const float* Wq   = (const float*)d_in[5];
    const float* bq   = (const float*)d_in[6];
    const float* Wk   = (const float*)d_in[7];
    const float* bk   = (const float*)d_in[8];
    const float* Wv   = (const float*)d_in[9];
    const float* bv   = (const float*)d_in[10];
    const float* Wo   = (const float*)d_in[11];
    const float* bo   = (const float*)d_in[12];
    const float* g2   = (const float*)d_in[13];
    const float* be2  = (const float*)d_in[14];
    const float* W1   = (const float*)d_in[15];
    const float* b1   = (const float*)d_in[16];
    const float* W2   = (const float*)d_in[17];
    const float* b2   = (const float*)d_in[18];
    float* out = (float*)d_out;

    float* base = nullptr;
    cudaGetSymbolAddress((void**)&base, g_scratch);
    float* p_h   = base + OFF_H;
    float* p_q   = base + OFF_Q;
    float* p_k   = base + OFF_K;
    float* p_v   = base + OFF_V;
    float* p_att = base + OFF_ATT;
    float* p_x2  = base + OFF_X2;
    float* p_mlp = base + OFF_MLP;

    cudaFuncSetAttribute(flash_kernel,
                         cudaFuncAttributeMaxDynamicSharedMemorySize, FLASH_SMEM);
    cudaFuncSetAttribute(tgemm_kernel,
                         cudaFuncAttributeMaxDynamicSharedMemorySize, GEMM_SMEM);

    // 1. LN1
    ln_kernel<<<Mrows, 256>>>(x, g1, be1, p_h);

    // 2. fused QKV projections: grid.z selects W/bias/out
    GemmSet qkv;
    qkv.W[0] = Wq; qkv.W[1] = Wk; qkv.W[2] = Wv;
    qkv.bias[0] = bq; qkv.bias[1] = bk; qkv.bias[2] = bv;
    qkv.out[0] = p_q; qkv.out[1] = p_k; qkv.out[2] = p_v;
    tgemm_kernel<<<dim3(Cdim / 256, Mrows / 128, 3), 256, GEMM_SMEM>>>(
        p_h, qkv, nullptr, Mrows, Cdim, Cdim, 0);

    // 3. RoPE
    const int rblocks = (Bb * Nn_ * Hh * 32) / 256;
    rope_kernel<<<rblocks, 256>>>(p_q, rcos, rsin);
    rope_kernel<<<rblocks, 256>>>(p_k, rcos, rsin);

    // 4. attention
    flash_kernel<<<dim3(Nn_ / 128, Bb * Hh), 256, FLASH_SMEM>>>(p_q, p_k, p_v, p_att);

    // 5. output projection + residual
    GemmSet so;
    so.W[0] = Wo; so.bias[0] = bo; so.out[0] = p_x2;
    so.W[1] = so.W[2] = nullptr; so.bias[1] = so.bias[2] = nullptr;
    so.out[1] = so.out[2] = nullptr;
    tgemm_kernel<<<dim3(Cdim / 256, Mrows / 128, 1), 256, GEMM_SMEM>>>(
        p_att, so, x, Mrows, Cdim, Cdim, 0);

    // 6. LN2
    ln_kernel<<<Mrows, 256>>>(p_x2, g2, be2, p_h);

    // 7. MLP up + GELU
    GemmSet s1;
    s1.W[0] = W1; s1.bias[0] = b1; s1.out[0] = p_mlp;
    s1.W[1] = s1.W[2] = nullptr; s1.bias[1] = s1.bias[2] = nullptr;
    s1.out[1] = s1.out[2] = nullptr;
    tgemm_kernel<<<dim3(Fdim / 256, Mrows / 128, 1), 256, GEMM_SMEM>>>(
        p_h, s1, nullptr, Mrows, Fdim, Cdim, 1);

    // 8. MLP down + residual -> output
    GemmSet s2;
    s2.W[0] = W2; s2.bias[0] = b2; s2.out[0] = out;
    s2.W[1] = s2.W[2] = nullptr; s2.bias[1] = s2.bias[2] = nullptr;
    s2.out[1] = s2.out[2] = nullptr;
    tgemm_kernel<<<dim3(Cdim / 256, Mrows / 128, 1), 256, GEMM_SMEM>>>(
        p_mlp, s2, p_x2, Mrows, Cdim, Fdim, 0);
}

// round 6
// speedup vs baseline: 1.0669x; 1.0669x over previous
#include <cuda_runtime.h>
#include <cuda_bf16.h>
#include <stdint.h>
#include <math.h>

// ---------------------------------------------------------------------------
// DiT block. Round 6: R4 GEMM skeleton (128x128, 2 CTA/SM) + 3-stage cp.async
// single-sync pipeline + producer-side RNA tf32 rounding (mainloop cvt-free),
// flash with register-staged K/V prefetch.
//   B=2, N=2048, C=1024, H=16, D=64, F=4096, M=B*N=4096
// ---------------------------------------------------------------------------

#define Mrows 4096
#define Cdim  1024
#define Fdim  4096
#define Bb    2
#define Nn_   2048
#define Hh    16
#define Dd    64

#define OFF_H   ((size_t)0)
#define OFF_Q   ((size_t)4194304)
#define OFF_K   ((size_t)8388608)
#define OFF_V   ((size_t)12582912)
#define OFF_ATT ((size_t)16777216)
#define OFF_X2  ((size_t)20971520)
#define OFF_MLP ((size_t)25165824)
#define OFF_WQ  ((size_t)41943040)
#define OFF_WK  ((size_t)42991616)
#define OFF_WV  ((size_t)44040192)
#define OFF_WO  ((size_t)45088768)
#define OFF_W1  ((size_t)46137344)
#define OFF_W2  ((size_t)50331648)
// total = 54525952 floats = 218 MB
__device__ float g_scratch[54525952];

__device__ __forceinline__ uint32_t f2tf32(float x) {
    uint32_t t;
    asm("cvt.rna.tf32.f32 %0, %1;" : "=r"(t) : "f"(x));
    return t;
}
__device__ __forceinline__ float rnd_tf32(float x) {
    return __uint_as_float(f2tf32(x));
}

#define MMA_TF32(d, a, b)                                                     \
    asm volatile(                                                             \
        "mma.sync.aligned.m16n8k8.row.col.f32.tf32.tf32.f32 "                 \
        "{%0,%1,%2,%3}, {%4,%5,%6,%7}, {%8,%9}, {%0,%1,%2,%3};"               \
        : "+f"(d[0]), "+f"(d[1]), "+f"(d[2]), "+f"(d[3])                      \
        : "r"(a[0]), "r"(a[1]), "r"(a[2]), "r"(a[3]), "r"(b[0]), "r"(b[1]))

#define CP_ASYNC16(dst_u32, src_ptr)                                          \
    asm volatile("cp.async.cg.shared.global [%0], [%1], 16;"                  \
                 :: "r"(dst_u32), "l"(src_ptr))
#define CP_COMMIT()  asm volatile("cp.async.commit_group;")
#define CP_WAIT(n)   asm volatile("cp.async.wait_group %0;" :: "n"(n))

// ---------------------------------------------------------------------------
// Round an array to tf32 precision (RNA), float4-vectorized.
// ---------------------------------------------------------------------------
__global__ void __launch_bounds__(256) round_tf32_kernel(
    const float4* __restrict__ in, float4* __restrict__ out, int n4)
{
    int i = blockIdx.x * 256 + threadIdx.x;
    const int stride = gridDim.x * 256;
    for (; i < n4; i += stride) {
        float4 v = in[i];
        v.x = rnd_tf32(v.x); v.y = rnd_tf32(v.y);
        v.z = rnd_tf32(v.z); v.w = rnd_tf32(v.w);
        out[i] = v;
    }
}

// ---------------------------------------------------------------------------
// LayerNorm: one block (256 thr) per row of 1024. Output RNA-rounded to tf32
// (it is only ever consumed as a GEMM A operand).
// ---------------------------------------------------------------------------
__global__ void __launch_bounds__(256) ln_kernel(
    const float* __restrict__ x, const float* __restrict__ g,
    const float* __restrict__ b, float* __restrict__ out)
{
    __shared__ float red[16];
    const int row = blockIdx.x;
    const int t = threadIdx.x;
    const float4 xv = ((const float4*)(x + (size_t)row * Cdim))[t];
    float s  = xv.x + xv.y + xv.z + xv.w;
    float ss = xv.x*xv.x + xv.y*xv.y + xv.z*xv.z + xv.w*xv.w;
    #pragma unroll
    for (int o = 16; o > 0; o >>= 1) {
        s  += __shfl_xor_sync(0xffffffffu, s,  o);
        ss += __shfl_xor_sync(0xffffffffu, ss, o);
    }
    const int w = t >> 5;
    if ((t & 31) == 0) { red[w] = s; red[8 + w] = ss; }
    __syncthreads();
    float ts = 0.f, tss = 0.f;
    #pragma unroll
    for (int i = 0; i < 8; i++) { ts += red[i]; tss += red[8 + i]; }
    const float mean = ts * (1.0f / Cdim);
    const float var  = tss * (1.0f / Cdim) - mean * mean;
    const float inv  = rsqrtf(var + 1e-6f);
    const float4 gv = ((const float4*)g)[t];
    const float4 bv = ((const float4*)b)[t];
    float4 o;
    o.x = rnd_tf32((xv.x - mean) * inv * gv.x + bv.x);
    o.y = rnd_tf32((xv.y - mean) * inv * gv.y + bv.y);
    o.z = rnd_tf32((xv.z - mean) * inv * gv.z + bv.z);
    o.w = rnd_tf32((xv.w - mean) * inv * gv.w + bv.w);
    ((float4*)(out + (size_t)row * Cdim))[t] = o;
}

// ---------------------------------------------------------------------------
// tf32 GEMM, 3-stage cp.async pipeline, ONE sync per k-iteration.
// Operands must already be tf32-representable (raw-bit fragments).
// out[z][M,Nc] = A[M,K] @ W[z][Nc,K]^T + bias[z] (+GELU)(+resid)(+round_out)
// 128x128 tile, BK=32, 256 threads (8 warps 2Mx4N), warp tile 64x32.
// smem: 3 stages x (As[128][36] + Bs[128][36]) = 110592 B.
// ---------------------------------------------------------------------------
#define GS 36
#define TBUF (128 * GS)
#define BOFF (3 * TBUF)
#define GEMM_SMEM (6 * TBUF * 4)

struct GemmSet {
    const float* W[3];
    const float* bias[3];
    float*       out[3];
};

__global__ void __launch_bounds__(256, 2) tgemm_kernel(
    const float* __restrict__ A, GemmSet gs, const float* __restrict__ residual,
    int M, int Nc, int K, int gelu, int round_out)
{
    extern __shared__ float smf[];
    const uint32_t sb = (uint32_t)__cvta_generic_to_shared(smf);

    const int z = blockIdx.z;
    const float* __restrict__ Wp   = gs.W[z];
    const float* __restrict__ bias = gs.bias[z];
    float* __restrict__ out        = gs.out[z];

    const int tid  = threadIdx.x;
    const int wid  = tid >> 5;
    const int lane = tid & 31;
    const int lr   = lane >> 2;
    const int lc   = lane & 3;
    const int warpM = (wid & 1) * 64;
    const int warpN = (wid >> 1) * 32;
    const int bm = blockIdx.y * 128, bn = blockIdx.x * 128;

    const int lrow = tid >> 3;          // 0..31
    const int lcol = (tid & 7) << 2;    // 0,4,...,28

    float acc[4][4][4];
    #pragma unroll
    for (int i = 0; i < 4; i++)
        #pragma unroll
        for (int j = 0; j < 4; j++)
            #pragma unroll
            for (int r = 0; r < 4; r++) acc[i][j][r] = 0.f;

    const int nk = K >> 5;

    #define LOAD_TILE(stg, k0)                                                \
    do {                                                                      \
        _Pragma("unroll")                                                     \
        for (int p = 0; p < 4; p++) {                                         \
            const int row = lrow + p * 32;                                    \
            const uint32_t da = sb + (uint32_t)((((stg) * TBUF) + row * GS + lcol) * 4); \
            const uint32_t db = da + (uint32_t)(BOFF * 4);                    \
            CP_ASYNC16(da, A + (size_t)(bm + row) * K + (k0) + lcol);         \
            CP_ASYNC16(db, Wp + (size_t)(bn + row) * K + (k0) + lcol);        \
        }                                                                     \
    } while (0)

    LOAD_TILE(0, 0);
    CP_COMMIT();
    if (nk > 1) { LOAD_TILE(1, 32); }
    CP_COMMIT();

    int stg = 0;
    for (int kt = 0; kt < nk; kt++) {
        if (kt + 1 < nk) { CP_WAIT(1); } else { CP_WAIT(0); }
        __syncthreads();

        if (kt + 2 < nk) {
            const int ns = (stg + 2 >= 3) ? stg - 1 : stg + 2;
            LOAD_TILE(ns, (kt + 2) << 5);
            CP_COMMIT();
        }

        const float* Ab  = smf + stg * TBUF;
        const float* Bbf = smf + BOFF + stg * TBUF;
        #pragma unroll
        for (int ks = 0; ks < 4; ks++) {
            const int kk = ks * 8;
            uint32_t af[4][4], bf[4][2];
            #pragma unroll
            for (int i = 0; i < 4; i++) {
                const int rb = warpM + i * 16;
                af[i][0] = __float_as_uint(Ab[(rb + lr) * GS + kk + lc]);
                af[i][1] = __float_as_uint(Ab[(rb + lr + 8) * GS + kk + lc]);
                af[i][2] = __float_as_uint(Ab[(rb + lr) * GS + kk + lc + 4]);
                af[i][3] = __float_as_uint(Ab[(rb + lr + 8) * GS + kk + lc + 4]);
            }
            #pragma unroll
            for (int j = 0; j < 4; j++) {
                const int cb = warpN + j * 8;
                bf[j][0] = __float_as_uint(Bbf[(cb + lr) * GS + kk + lc]);
                bf[j][1] = __float_as_uint(Bbf[(cb + lr) * GS + kk + lc + 4]);
            }
            #pragma unroll
            for (int i = 0; i < 4; i++)
                #pragma unroll
                for (int j = 0; j < 4; j++)
                    MMA_TF32(acc[i][j], af[i], bf[j]);
        }
        stg = (stg + 1 >= 3) ? 0 : stg + 1;
    }

    // epilogue
    #pragma unroll
    for (int i = 0; i < 4; i++) {
        const int row0 = bm + warpM + i * 16 + lr;
        #pragma unroll
        for (int j = 0; j < 4; j++) {
            const int col = bn + warpN + j * 8 + (lc << 1);
            const float b0 = __ldg(&bias[col]);
            const float b1 = __ldg(&bias[col + 1]);
            float v0 = acc[i][j][0] + b0;
            float v1 = acc[i][j][1] + b1;
            float v2 = acc[i][j][2] + b0;
            float v3 = acc[i][j][3] + b1;
            if (gelu) {
                v0 = 0.5f * v0 * (1.0f + erff(v0 * 0.70710678118654752f));
                v1 = 0.5f * v1 * (1.0f + erff(v1 * 0.70710678118654752f));
                v2 = 0.5f * v2 * (1.0f + erff(v2 * 0.70710678118654752f));
                v3 = 0.5f * v3 * (1.0f + erff(v3 * 0.70710678118654752f));
            }
            if (residual) {
                v0 += residual[(size_t)row0 * Nc + col];
                v1 += residual[(size_t)row0 * Nc + col + 1];
                v2 += residual[(size_t)(row0 + 8) * Nc + col];
                v3 += residual[(size_t)(row0 + 8) * Nc + col + 1];
            }
            if (round_out) {
                v0 = rnd_tf32(v0); v1 = rnd_tf32(v1);
                v2 = rnd_tf32(v2); v3 = rnd_tf32(v3);
            }
            *(float2*)(out + (size_t)row0 * Nc + col)       = make_float2(v0, v1);
            *(float2*)(out + (size_t)(row0 + 8) * Nc + col) = make_float2(v2, v3);
        }
    }
}

// ---------------------------------------------------------------------------
// RoPE applied in place to q or k laid out as [B*N, C] with col = h*64 + d
// ---------------------------------------------------------------------------
__global__ void __launch_bounds__(256) rope_kernel(
    float* __restrict__ t, const float* __restrict__ cosb,
    const float* __restrict__ sinb)
{
    int idx = blockIdx.x * 256 + threadIdx.x;
    const int d = idx & 31; idx >>= 5;
    const int h = idx & (Hh - 1); idx >>= 4;
    const int n = idx & (Nn_ - 1); idx >>= 11;
    const int b = idx;
    const size_t base = ((size_t)(b * Nn_ + n)) * Cdim + h * Dd;
    const float x1 = t[base + d];
    const float x2 = t[base + d + 32];
    const float c1 = cosb[n * Dd + d],      s1 = sinb[n * Dd + d];
    const float c2 = cosb[n * Dd + d + 32], s2 = sinb[n * Dd + d + 32];
    t[base + d]      = x1 * c1 - x2 * s1;
    t[base + d + 32] = x2 * c2 + x1 * s2;
}

// ---------------------------------------------------------------------------
// Flash attention, tf32 mma. Producers RNA-round into smem; fragments are raw.
// Register-staged prefetch of next K/V tile overlaps gmem with compute.
// ---------------------------------------------------------------------------
#define QSS 68
#define VSS 72
#define F_QS 0
#define F_KS (128 * QSS)
#define F_VS (F_KS + 64 * QSS)
#define F_PS (F_VS + 64 * VSS)
#define FLASH_SMEM ((F_PS + 128 * QSS) * 4)

__global__ void __launch_bounds__(256) flash_kernel(
    const float* __restrict__ q, const float* __restrict__ k,
    const float* __restrict__ v, float* __restrict__ out)
{
    extern __shared__ float sm[];
    float* Qs = sm + F_QS;
    float* Ks = sm + F_KS;
    float* Vs = sm + F_VS;
    float* Ps = sm + F_PS;

    const int tid  = threadIdx.x;
    const int wid  = tid >> 5;
    const int lane = tid & 31;
    const int lr   = lane >> 2;
    const int lc   = lane & 3;
    const int rm   = wid * 16;

    const int bh = blockIdx.y;
    const int b = bh >> 4;
    const int h = bh & 15;
    const int q0 = blockIdx.x * 128;
    const float qscale = 0.125f * 1.4426950408889634f;  // D^-1/2 * log2(e)

    // load Q tile (scaled + rounded)
    const float* qb = q + ((size_t)(b * Nn_ + q0)) * Cdim + h * Dd;
    #pragma unroll
    for (int i = 0; i < 8; i++) {
        const int idx = tid + i * 256;
        const int r = idx >> 4;
        const int c = (idx & 15) << 2;
        float4 t4 = *(const float4*)(qb + (size_t)r * Cdim + c);
        t4.x = rnd_tf32(t4.x * qscale); t4.y = rnd_tf32(t4.y * qscale);
        t4.z = rnd_tf32(t4.z * qscale); t4.w = rnd_tf32(t4.w * qscale);
        *(float4*)&Qs[r * QSS + c] = t4;
    }

    // per-thread staging addresses for K/V tiles
    int srow[4], scol[4];
    #pragma unroll
    for (int i = 0; i < 4; i++) {
        const int idx = tid + i * 256;
        srow[i] = idx >> 4;
        scol[i] = (idx & 15) << 2;
    }
    const float* kb0 = k + ((size_t)(b * Nn_)) * Cdim + h * Dd;
    const float* vb0 = v + ((size_t)(b * Nn_)) * Cdim + h * Dd;

    float4 kreg[4], vreg[4];
    #pragma unroll
    for (int i = 0; i < 4; i++) {
        kreg[i] = *(const float4*)(kb0 + (size_t)srow[i] * Cdim + scol[i]);
        vreg[i] = *(const float4*)(vb0 + (size_t)srow[i] * Cdim + scol[i]);
    }

    float m0 = -1e30f, m1 = -1e30f, l0 = 0.f, l1 = 0.f;
    float oacc[8][4];
    #pragma unroll
    for (int nt = 0; nt < 8; nt++)
        #pragma unroll
        for (int r = 0; r < 4; r++) oacc[nt][r] = 0.f;

    for (int kv0 = 0; kv0 < Nn_; kv0 += 64) {
        __syncthreads();   // previous tile fully consumed (and Qs ready, iter 0)
        #pragma unroll
        for (int i = 0; i < 4; i++) {
            float4 kt4 = kreg[i], vt4 = vreg[i];
            kt4.x = rnd_tf32(kt4.x); kt4.y = rnd_tf32(kt4.y);
            kt4.z = rnd_tf32(kt4.z); kt4.w = rnd_tf32(kt4.w);
            vt4.x = rnd_tf32(vt4.x); vt4.y = rnd_tf32(vt4.y);
            vt4.z = rnd_tf32(vt4.z); vt4.w = rnd_tf32(vt4.w);
            *(float4*)&Ks[srow[i] * QSS + scol[i]] = kt4;
            *(float4*)&Vs[srow[i] * VSS + scol[i]] = vt4;
        }
        __syncthreads();

        // prefetch next tile into registers (overlaps with compute below)
        if (kv0 + 64 < Nn_) {
            const float* kb = kb0 + (size_t)(kv0 + 64) * Cdim;
            const float* vb = vb0 + (size_t)(kv0 + 64) * Cdim;
            #pragma unroll
            for (int i = 0; i < 4; i++) {
                kreg[i] = *(const float4*)(kb + (size_t)srow[i] * Cdim + scol[i]);
                vreg[i] = *(const float4*)(vb + (size_t)srow[i] * Cdim + scol[i]);
            }
        }

        // S = Qs @ Ks^T
        float sacc[8][4];
        #pragma unroll
        for (int nt = 0; nt < 8; nt++)
            #pragma unroll
            for (int r = 0; r < 4; r++) sacc[nt][r] = 0.f;
        #pragma unroll
        for (int ks = 0; ks < 8; ks++) {
            const int kk = ks * 8;
            uint32_t af[4];
            af[0] = __float_as_uint(Qs[(rm + lr) * QSS + kk + lc]);
            af[1] = __float_as_uint(Qs[(rm + lr + 8) * QSS + kk + lc]);
            af[2] = __float_as_uint(Qs[(rm + lr) * QSS + kk + lc + 4]);
            af[3] = __float_as_uint(Qs[(rm + lr + 8) * QSS + kk + lc + 4]);
            #pragma unroll
            for (int nt = 0; nt < 8; nt++) {
                uint32_t bf[2];
                bf[0] = __float_as_uint(Ks[(nt * 8 + lr) * QSS + kk + lc]);
                bf[1] = __float_as_uint(Ks[(nt * 8 + lr) * QSS + kk + lc + 4]);
                MMA_TF32(sacc[nt], af, bf);
            }
        }

        // online softmax
        float mx0 = -1e30f, mx1 = -1e30f;
        #pragma unroll
        for (int nt = 0; nt < 8; nt++) {
            mx0 = fmaxf(mx0, fmaxf(sacc[nt][0], sacc[nt][1]));
            mx1 = fmaxf(mx1, fmaxf(sacc[nt][2], sacc[nt][3]));
        }
        #pragma unroll
        for (int o = 1; o < 4; o <<= 1) {
            mx0 = fmaxf(mx0, __shfl_xor_sync(0xffffffffu, mx0, o, 4));
            mx1 = fmaxf(mx1, __shfl_xor_sync(0xffffffffu, mx1, o, 4));
        }
        const float mn0 = fmaxf(m0, mx0);
        const float mn1 = fmaxf(m1, mx1);
        const float al0 = exp2f(m0 - mn0);
        const float al1 = exp2f(m1 - mn1);
        float rs0 = 0.f, rs1 = 0.f;
        #pragma unroll
        for (int nt = 0; nt < 8; nt++) {
            const float p0 = rnd_tf32(exp2f(sacc[nt][0] - mn0));
            const float p1 = rnd_tf32(exp2f(sacc[nt][1] - mn0));
            const float p2 = rnd_tf32(exp2f(sacc[nt][2] - mn1));
            const float p3 = rnd_tf32(exp2f(sacc[nt][3] - mn1));
            rs0 += p0 + p1; rs1 += p2 + p3;
            *(float2*)&Ps[(rm + lr) * QSS + nt * 8 + 2 * lc]     = make_float2(p0, p1);
            *(float2*)&Ps[(rm + lr + 8) * QSS + nt * 8 + 2 * lc] = make_float2(p2, p3);
        }
        #pragma unroll
        for (int o = 1; o < 4; o <<= 1) {
            rs0 += __shfl_xor_sync(0xffffffffu, rs0, o, 4);
            rs1 += __shfl_xor_sync(0xffffffffu, rs1, o, 4);
        }
        l0 = l0 * al0 + rs0;  m0 = mn0;
        l1 = l1 * al1 + rs1;  m1 = mn1;
        #pragma unroll
        for (int nt = 0; nt < 8; nt++) {
            oacc[nt][0] *= al0; oacc[nt][1] *= al0;
            oacc[nt][2] *= al1; oacc[nt][3] *= al1;
        }
        __syncwarp();   // Ps rows are warp-private

        // O += P @ V
        #pragma unroll
        for (int ks = 0; ks < 8; ks++) {
            const int kk = ks * 8;
            uint32_t af[4];
            af[0] = __float_as_uint(Ps[(rm + lr) * QSS + kk + lc]);
            af[1] = __float_as_uint(Ps[(rm + lr + 8) * QSS + kk + lc]);
            af[2] = __float_as_uint(Ps[(rm + lr) * QSS + kk + lc + 4]);
            af[3] = __float_as_uint(Ps[(rm + lr + 8) * QSS + kk + lc + 4]);
            #pragma unroll
            for (int nt = 0; nt < 8; nt++) {
                uint32_t bf[2];
                bf[0] = __float_as_uint(Vs[(kk + lc) * VSS + nt * 8 + lr]);
                bf[1] = __float_as_uint(Vs[(kk + lc + 4) * VSS + nt * 8 + lr]);
                MMA_TF32(oacc[nt], af, bf);
            }
        }
    }

    // write O (rounded: it is the A operand of the Wo GEMM)
    const float il0 = 1.0f / l0;
    const float il1 = 1.0f / l1;
    float* ob = out + ((size_t)(b * Nn_ + q0 + rm)) * Cdim + h * Dd;
    #pragma unroll
    for (int nt = 0; nt < 8; nt++) {
        const int col = nt * 8 + 2 * lc;
        *(float2*)(ob + (size_t)lr * Cdim + col) =
            make_float2(rnd_tf32(oacc[nt][0] * il0), rnd_tf32(oacc[nt][1] * il0));
        *(float2*)(ob + (size_t)(lr + 8) * Cdim + col) =
            make_float2(rnd_tf32(oacc[nt][2] * il1), rnd_tf32(oacc[nt][3] * il1));
    }
}

// ---------------------------------------------------------------------------
extern "C" void kernel_launch(void* const* d_in, const int* in_sizes, int n_in,
                              void* d_out, int out_size)
{
    const float* x    = (const float*)d_in[0];
    const float* rcos = (const float*)d_in[1];
    const float* rsin = (const float*)d_in[2];
    const float* g1   = (const float*)d_in[3];
    const float* be1  = (const float*)d_in[4];
    const float* Wq   = (const float*)d_in[5];
    const float* bq   = (const float*)d_in[6];
    const float* Wk   = (const float*)d_in[7];
    const float* bk   = (const float*)d_in[8];
    const float* Wv   = (const float*)d_in[9];
    const float* bv   = (const float*)d_in[10];
    const float* Wo   = (const float*)d_in[11];
    const float* bo   = (const float*)d_in[12];
    const float* g2   = (const float*)d_in[13];
    const float* be2  = (const float*)d_in[14];
    const float* W1   = (const float*)d_in[15];
    const float* b1   = (const float*)d_in[16];
    const float* W2   = (const float*)d_in[17];
    const float* b2   = (const float*)d_in[18];
    float* out = (float*)d_out;

    float* base = nullptr;
    cudaGetSymbolAddress((void**)&base, g_scratch);
    float* p_h   = base + OFF_H;
    float* p_q   = base + OFF_Q;
    float* p_k   = base + OFF_K;
    float* p_v   = base + OFF_V;
    float* p_att = base + OFF_ATT;
    float* p_x2  = base + OFF_X2;
    float* p_mlp = base + OFF_MLP;
    float* p_wq  = base + OFF_WQ;
    float* p_wk  = base + OFF_WK;
    float* p_wv  = base + OFF_WV;
    float* p_wo  = base + OFF_WO;
    float* p_w1  = base + OFF_W1;
    float* p_w2  = base + OFF_W2;

    cudaFuncSetAttribute(flash_kernel,
                         cudaFuncAttributeMaxDynamicSharedMemorySize, FLASH_SMEM);
    cudaFuncSetAttribute(tgemm_kernel,
                         cudaFuncAttributeMaxDynamicSharedMemorySize, GEMM_SMEM);

    // 0. pre-round all weights to tf32 (RNA)
    const int nC4 = (Cdim * Cdim) / 4;       // 262144
    const int nF4 = (Cdim * Fdim) / 4;       // 1048576
    round_tf32_kernel<<<592, 256>>>((const float4*)Wq, (float4*)p_wq, nC4);
    round_tf32_kernel<<<592, 256>>>((const float4*)Wk, (float4*)p_wk, nC4);
    round_tf32_kernel<<<592, 256>>>((const float4*)Wv, (float4*)p_wv, nC4);
    round_tf32_kernel<<<592, 256>>>((const float4*)Wo, (float4*)p_wo, nC4);
    round_tf32_kernel<<<592, 256>>>((const float4*)W1, (float4*)p_w1, nF4);
    round_tf32_kernel<<<592, 256>>>((const float4*)W2, (float4*)p_w2, nF4);

    // 1. LN1 (rounds output)
    ln_kernel<<<Mrows, 256>>>(x, g1, be1, p_h);

    // 2. fused QKV projections
    GemmSet qkv;
    qkv.W[0] = p_wq; qkv.W[1] = p_wk; qkv.W[2] = p_wv;
    qkv.bias[0] = bq; qkv.bias[1] = bk; qkv.bias[2] = bv;
    qkv.out[0] = p_q; qkv.out[1] = p_k; qkv.out[2] = p_v;
    tgemm_kernel<<<dim3(Cdim / 128, Mrows / 128, 3), 256, GEMM_SMEM>>>(
        p_h, qkv, nullptr, Mrows, Cdim, Cdim, 0, 0);

    // 3. RoPE (flash rounds q/k/v at smem store)
    const int rblocks = (Bb * Nn_ * Hh * 32) / 256;
    rope_kernel<<<rblocks, 256>>>(p_q, rcos, rsin);
    rope_kernel<<<rblocks, 256>>>(p_k, rcos, rsin);

    // 4. attention (rounds p_att output)
    flash_kernel<<<dim3(Nn_ / 128, Bb * Hh), 256, FLASH_SMEM>>>(p_q, p_k, p_v, p_att);

    // 5. output projection + residual (fp32 residual stream, no rounding)
    GemmSet so;
    so.W[0] = p_wo; so.bias[0] = bo; so.out[0] = p_x2;
    so.W[1] = so.W[2] = nullptr; so.bias[1] = so.bias[2] = nullptr;
    so.out[1] = so.out[2] = nullptr;
    tgemm_kernel<<<dim3(Cdim / 128, Mrows / 128, 1), 256, GEMM_SMEM>>>(
        p_att, so, x, Mrows, Cdim, Cdim, 0, 0);

    // 6. LN2 (rounds output)
    ln_kernel<<<Mrows, 256>>>(p_x2, g2, be2, p_h);

    // 7. MLP up + GELU (rounds output: A operand of W2 GEMM)
    GemmSet s1;
    s1.W[0] = p_w1; s1.bias[0] = b1; s1.out[0] = p_mlp;
    s1.W[1] = s1.W[2] = nullptr; s1.bias[1] = s1.bias[2] = nullptr;
    s1.out[1] = s1.out[2] = nullptr;
    tgemm_kernel<<<dim3(Fdim / 128, Mrows / 128, 1), 256, GEMM_SMEM>>>(
        p_h, s1, nullptr, Mrows, Fdim, Cdim, 1, 1);

    // 8. MLP down + residual -> output (fp32)
    GemmSet s2;
    s2.W[0] = p_w2; s2.bias[0] = b2; s2.out[0] = out;
    s2.W[1] = s2.W[2] = nullptr; s2.bias[1] = s2.bias[2] = nullptr;
    s2.out[1] = s2.out[2] = nullptr;
    tgemm_kernel<<<dim3(Cdim / 128, Mrows / 128, 1), 256, GEMM_SMEM>>>(
        p_mlp, s2, p_x2, Mrows, Cdim, Fdim, 0, 0);
}

// round 7
// speedup vs baseline: 1.0706x; 1.0035x over previous
#include <cuda_runtime.h>
#include <cuda_bf16.h>
#include <stdint.h>
#include <math.h>

// ---------------------------------------------------------------------------
// DiT block. Round 7: 64x64 warp tiles (MMA:LDS = 1:1), 128 thr/CTA, 2 CTA/SM,
// 3-stage cp.async, producer-side RNA tf32 rounding, fused weight-round pass.
//   B=2, N=2048, C=1024, H=16, D=64, F=4096, M=B*N=4096
// ---------------------------------------------------------------------------

#define Mrows 4096
#define Cdim  1024
#define Fdim  4096
#define Bb    2
#define Nn_   2048
#define Hh    16
#define Dd    64

#define OFF_H   ((size_t)0)
#define OFF_Q   ((size_t)4194304)
#define OFF_K   ((size_t)8388608)
#define OFF_V   ((size_t)12582912)
#define OFF_ATT ((size_t)16777216)
#define OFF_X2  ((size_t)20971520)
#define OFF_MLP ((size_t)25165824)
#define OFF_WQ  ((size_t)41943040)
#define OFF_WK  ((size_t)42991616)
#define OFF_WV  ((size_t)44040192)
#define OFF_WO  ((size_t)45088768)
#define OFF_W1  ((size_t)46137344)
#define OFF_W2  ((size_t)50331648)
__device__ float g_scratch[54525952];

__device__ __forceinline__ uint32_t f2tf32(float x) {
    uint32_t t;
    asm("cvt.rna.tf32.f32 %0, %1;" : "=r"(t) : "f"(x));
    return t;
}
__device__ __forceinline__ float rnd_tf32(float x) {
    return __uint_as_float(f2tf32(x));
}

#define MMA_TF32(d, a, b)                                                     \
    asm volatile(                                                             \
        "mma.sync.aligned.m16n8k8.row.col.f32.tf32.tf32.f32 "                 \
        "{%0,%1,%2,%3}, {%4,%5,%6,%7}, {%8,%9}, {%0,%1,%2,%3};"               \
        : "+f"(d[0]), "+f"(d[1]), "+f"(d[2]), "+f"(d[3])                      \
        : "r"(a[0]), "r"(a[1]), "r"(a[2]), "r"(a[3]), "r"(b[0]), "r"(b[1]))

#define CP_ASYNC16(dst_u32, src_ptr)                                          \
    asm volatile("cp.async.cg.shared.global [%0], [%1], 16;"                  \
                 :: "r"(dst_u32), "l"(src_ptr))
#define CP_COMMIT()  asm volatile("cp.async.commit_group;")
#define CP_WAIT(n)   asm volatile("cp.async.wait_group %0;" :: "n"(n))

// ---------------------------------------------------------------------------
// Fused weight rounding: z selects one of 6 arrays, grid-stride per z.
// ---------------------------------------------------------------------------
struct RoundSet {
    const float4* in[6];
    float4*       out[6];
    int           n4[6];
};

__global__ void __launch_bounds__(256) round_all_kernel(RoundSet rs)
{
    const int z = blockIdx.z;
    const float4* __restrict__ in = rs.in[z];
    float4* __restrict__ out = rs.out[z];
    const int n4 = rs.n4[z];
    const int stride = gridDim.x * 256;
    for (int i = blockIdx.x * 256 + threadIdx.x; i < n4; i += stride) {
        float4 v = in[i];
        v.x = rnd_tf32(v.x); v.y = rnd_tf32(v.y);
        v.z = rnd_tf32(v.z); v.w = rnd_tf32(v.w);
        out[i] = v;
    }
}

// ---------------------------------------------------------------------------
// LayerNorm: one block (256 thr) per row of 1024; output RNA tf32.
// ---------------------------------------------------------------------------
__global__ void __launch_bounds__(256) ln_kernel(
    const float* __restrict__ x, const float* __restrict__ g,
    const float* __restrict__ b, float* __restrict__ out)
{
    __shared__ float red[16];
    const int row = blockIdx.x;
    const int t = threadIdx.x;
    const float4 xv = ((const float4*)(x + (size_t)row * Cdim))[t];
    float s  = xv.x + xv.y + xv.z + xv.w;
    float ss = xv.x*xv.x + xv.y*xv.y + xv.z*xv.z + xv.w*xv.w;
    #pragma unroll
    for (int o = 16; o > 0; o >>= 1) {
        s  += __shfl_xor_sync(0xffffffffu, s,  o);
        ss += __shfl_xor_sync(0xffffffffu, ss, o);
    }
    const int w = t >> 5;
    if ((t & 31) == 0) { red[w] = s; red[8 + w] = ss; }
    __syncthreads();
    float ts = 0.f, tss = 0.f;
    #pragma unroll
    for (int i = 0; i < 8; i++) { ts += red[i]; tss += red[8 + i]; }
    const float mean = ts * (1.0f / Cdim);
    const float var  = tss * (1.0f / Cdim) - mean * mean;
    const float inv  = rsqrtf(var + 1e-6f);
    const float4 gv = ((const float4*)g)[t];
    const float4 bv = ((const float4*)b)[t];
    float4 o;
    o.x = rnd_tf32((xv.x - mean) * inv * gv.x + bv.x);
    o.y = rnd_tf32((xv.y - mean) * inv * gv.y + bv.y);
    o.z = rnd_tf32((xv.z - mean) * inv * gv.z + bv.z);
    o.w = rnd_tf32((xv.w - mean) * inv * gv.w + bv.w);
    ((float4*)(out + (size_t)row * Cdim))[t] = o;
}

// ---------------------------------------------------------------------------
// tf32 GEMM, 3-stage cp.async, 128x128 tile, 128 threads = 4 warps (2x2),
// warp tile 64x64 -> per warp-ks: 32 LDS / 32 MMA.
// Operands already tf32-representable (raw-bit fragments).
// ---------------------------------------------------------------------------
#define GS 36
#define TBUF (128 * GS)
#define BOFF (3 * TBUF)
#define GEMM_SMEM (6 * TBUF * 4)

struct GemmSet {
    const float* W[3];
    const float* bias[3];
    float*       out[3];
};

__global__ void __launch_bounds__(128, 2) tgemm_kernel(
    const float* __restrict__ A, GemmSet gs, const float* __restrict__ residual,
    int M, int Nc, int K, int gelu, int round_out)
{
    extern __shared__ float smf[];
    const uint32_t sb = (uint32_t)__cvta_generic_to_shared(smf);

    const int z = blockIdx.z;
    const float* __restrict__ Wp   = gs.W[z];
    const float* __restrict__ bias = gs.bias[z];
    float* __restrict__ out        = gs.out[z];

    const int tid  = threadIdx.x;
    const int wid  = tid >> 5;
    const int lane = tid & 31;
    const int lr   = lane >> 2;
    const int lc   = lane & 3;
    const int warpM = (wid & 1) * 64;
    const int warpN = (wid >> 1) * 64;
    const int bm = blockIdx.y * 128, bn = blockIdx.x * 128;

    const int lrow = tid >> 3;          // 0..15
    const int lcol = (tid & 7) << 2;    // 0,4,...,28

    float acc[4][8][4];
    #pragma unroll
    for (int i = 0; i < 4; i++)
        #pragma unroll
        for (int j = 0; j < 8; j++)
            #pragma unroll
            for (int r = 0; r < 4; r++) acc[i][j][r] = 0.f;

    const int nk = K >> 5;

    #define LOAD_TILE(stg, k0)                                                \
    do {                                                                      \
        _Pragma("unroll")                                                     \
        for (int p = 0; p < 8; p++) {                                         \
            const int row = lrow + p * 16;                                    \
            const uint32_t da = sb + (uint32_t)((((stg) * TBUF) + row * GS + lcol) * 4); \
            const uint32_t db = da + (uint32_t)(BOFF * 4);                    \
            CP_ASYNC16(da, A + (size_t)(bm + row) * K + (k0) + lcol);         \
            CP_ASYNC16(db, Wp + (size_t)(bn + row) * K + (k0) + lcol);        \
        }                                                                     \
    } while (0)

    LOAD_TILE(0, 0);
    CP_COMMIT();
    if (nk > 1) { LOAD_TILE(1, 32); }
    CP_COMMIT();

    int stg = 0;
    for (int kt = 0; kt < nk; kt++) {
        if (kt + 1 < nk) { CP_WAIT(1); } else { CP_WAIT(0); }
        __syncthreads();

        if (kt + 2 < nk) {
            const int ns = (stg + 2 >= 3) ? stg - 1 : stg + 2;
            LOAD_TILE(ns, (kt + 2) << 5);
            CP_COMMIT();
        }

        const float* Ab  = smf + stg * TBUF;
        const float* Bbf = smf + BOFF + stg * TBUF;
        #pragma unroll
        for (int ks = 0; ks < 4; ks++) {
            const int kk = ks * 8;
            uint32_t af[4][4], bf[8][2];
            #pragma unroll
            for (int i = 0; i < 4; i++) {
                const int rb = warpM + i * 16;
                af[i][0] = __float_as_uint(Ab[(rb + lr) * GS + kk + lc]);
                af[i][1] = __float_as_uint(Ab[(rb + lr + 8) * GS + kk + lc]);
                af[i][2] = __float_as_uint(Ab[(rb + lr) * GS + kk + lc + 4]);
                af[i][3] = __float_as_uint(Ab[(rb + lr + 8) * GS + kk + lc + 4]);
            }
            #pragma unroll
            for (int j = 0; j < 8; j++) {
                const int cb = warpN + j * 8;
                bf[j][0] = __float_as_uint(Bbf[(cb + lr) * GS + kk + lc]);
                bf[j][1] = __float_as_uint(Bbf[(cb + lr) * GS + kk + lc + 4]);
            }
            #pragma unroll
            for (int i = 0; i < 4; i++)
                #pragma unroll
                for (int j = 0; j < 8; j++)
                    MMA_TF32(acc[i][j], af[i], bf[j]);
        }
        stg = (stg + 1 >= 3) ? 0 : stg + 1;
    }

    // epilogue
    #pragma unroll
    for (int i = 0; i < 4; i++) {
        const int row0 = bm + warpM + i * 16 + lr;
        #pragma unroll
        for (int j = 0; j < 8; j++) {
            const int col = bn + warpN + j * 8 + (lc << 1);
            const float b0 = __ldg(&bias[col]);
            const float b1 = __ldg(&bias[col + 1]);
            float v0 = acc[i][j][0] + b0;
            float v1 = acc[i][j][1] + b1;
            float v2 = acc[i][j][2] + b0;
            float v3 = acc[i][j][3] + b1;
            if (gelu) {
                v0 = 0.5f * v0 * (1.0f + erff(v0 * 0.70710678118654752f));
                v1 = 0.5f * v1 * (1.0f + erff(v1 * 0.70710678118654752f));
                v2 = 0.5f * v2 * (1.0f + erff(v2 * 0.70710678118654752f));
                v3 = 0.5f * v3 * (1.0f + erff(v3 * 0.70710678118654752f));
            }
            if (residual) {
                v0 += residual[(size_t)row0 * Nc + col];
                v1 += residual[(size_t)row0 * Nc + col + 1];
                v2 += residual[(size_t)(row0 + 8) * Nc + col];
                v3 += residual[(size_t)(row0 + 8) * Nc + col + 1];
            }
            if (round_out) {
                v0 = rnd_tf32(v0); v1 = rnd_tf32(v1);
                v2 = rnd_tf32(v2); v3 = rnd_tf32(v3);
            }
            *(float2*)(out + (size_t)row0 * Nc + col)       = make_float2(v0, v1);
            *(float2*)(out + (size_t)(row0 + 8) * Nc + col) = make_float2(v2, v3);
        }
    }
}

// ---------------------------------------------------------------------------
// RoPE applied in place to q or k laid out as [B*N, C] with col = h*64 + d
// ---------------------------------------------------------------------------
__global__ void __launch_bounds__(256) rope_kernel(
    float* __restrict__ t, const float* __restrict__ cosb,
    const float* __restrict__ sinb)
{
    int idx = blockIdx.x * 256 + threadIdx.x;
    const int d = idx & 31; idx >>= 5;
    const int h = idx & (Hh - 1); idx >>= 4;
    const int n = idx & (Nn_ - 1); idx >>= 11;
    const int b = idx;
    const size_t base = ((size_t)(b * Nn_ + n)) * Cdim + h * Dd;
    const float x1 = t[base + d];
    const float x2 = t[base + d + 32];
    const float c1 = cosb[n * Dd + d],      s1 = sinb[n * Dd + d];
    const float c2 = cosb[n * Dd + d + 32], s2 = sinb[n * Dd + d + 32];
    t[base + d]      = x1 * c1 - x2 * s1;
    t[base + d + 32] = x2 * c2 + x1 * s2;
}

// ---------------------------------------------------------------------------
// Flash attention, tf32 mma, producer-rounded smem, reg-staged K/V prefetch.
// ---------------------------------------------------------------------------
#define QSS 68
#define VSS 72
#define F_QS 0
#define F_KS (128 * QSS)
#define F_VS (F_KS + 64 * QSS)
#define F_PS (F_VS + 64 * VSS)
#define FLASH_SMEM ((F_PS + 128 * QSS) * 4)

__global__ void __launch_bounds__(256) flash_kernel(
    const float* __restrict__ q, const float* __restrict__ k,
    const float* __restrict__ v, float* __restrict__ out)
{
    extern __shared__ float sm[];
    float* Qs = sm + F_QS;
    float* Ks = sm + F_KS;
    float* Vs = sm + F_VS;
    float* Ps = sm + F_PS;

    const int tid  = threadIdx.x;
    const int wid  = tid >> 5;
    const int lane = tid & 31;
    const int lr   = lane >> 2;
    const int lc   = lane & 3;
    const int rm   = wid * 16;

    const int bh = blockIdx.y;
    const int b = bh >> 4;
    const int h = bh & 15;
    const int q0 = blockIdx.x * 128;
    const float qscale = 0.125f * 1.4426950408889634f;

    const float* qb = q + ((size_t)(b * Nn_ + q0)) * Cdim + h * Dd;
    #pragma unroll
    for (int i = 0; i < 8; i++) {
        const int idx = tid + i * 256;
        const int r = idx >> 4;
        const int c = (idx & 15) << 2;
        float4 t4 = *(const float4*)(qb + (size_t)r * Cdim + c);
        t4.x = rnd_tf32(t4.x * qscale); t4.y = rnd_tf32(t4.y * qscale);
        t4.z = rnd_tf32(t4.z * qscale); t4.w = rnd_tf32(t4.w * qscale);
        *(float4*)&Qs[r * QSS + c] = t4;
    }

    int srow[4], scol[4];
    #pragma unroll
    for (int i = 0; i < 4; i++) {
        const int idx = tid + i * 256;
        srow[i] = idx >> 4;
        scol[i] = (idx & 15) << 2;
    }
    const float* kb0 = k + ((size_t)(b * Nn_)) * Cdim + h * Dd;
    const float* vb0 = v + ((size_t)(b * Nn_)) * Cdim + h * Dd;

    float4 kreg[4], vreg[4];
    #pragma unroll
    for (int i = 0; i < 4; i++) {
        kreg[i] = *(const float4*)(kb0 + (size_t)srow[i] * Cdim + scol[i]);
        vreg[i] = *(const float4*)(vb0 + (size_t)srow[i] * Cdim + scol[i]);
    }

    float m0 = -1e30f, m1 = -1e30f, l0 = 0.f, l1 = 0.f;
    float oacc[8][4];
    #pragma unroll
    for (int nt = 0; nt < 8; nt++)
        #pragma unroll
        for (int r = 0; r < 4; r++) oacc[nt][r] = 0.f;

    for (int kv0 = 0; kv0 < Nn_; kv0 += 64) {
        __syncthreads();
        #pragma unroll
        for (int i = 0; i < 4; i++) {
            float4 kt4 = kreg[i], vt4 = vreg[i];
            kt4.x = rnd_tf32(kt4.x); kt4.y = rnd_tf32(kt4.y);
            kt4.z = rnd_tf32(kt4.z); kt4.w = rnd_tf32(kt4.w);
            vt4.x = rnd_tf32(vt4.x); vt4.y = rnd_tf32(vt4.y);
            vt4.z = rnd_tf32(vt4.z); vt4.w = rnd_tf32(vt4.w);
            *(float4*)&Ks[srow[i] * QSS + scol[i]] = kt4;
            *(float4*)&Vs[srow[i] * VSS + scol[i]] = vt4;
        }
        __syncthreads();

        if (kv0 + 64 < Nn_) {
            const float* kb = kb0 + (size_t)(kv0 + 64) * Cdim;
            const float* vb = vb0 + (size_t)(kv0 + 64) * Cdim;
            #pragma unroll
            for (int i = 0; i < 4; i++) {
                kreg[i] = *(const float4*)(kb + (size_t)srow[i] * Cdim + scol[i]);
                vreg[i] = *(const float4*)(vb + (size_t)srow[i] * Cdim + scol[i]);
            }
        }

        float sacc[8][4];
        #pragma unroll
        for (int nt = 0; nt < 8; nt++)
            #pragma unroll
            for (int r = 0; r < 4; r++) sacc[nt][r] = 0.f;
        #pragma unroll
        for (int ks = 0; ks < 8; ks++) {
            const int kk = ks * 8;
            uint32_t af[4];
            af[0] = __float_as_uint(Qs[(rm + lr) * QSS + kk + lc]);
            af[1] = __float_as_uint(Qs[(rm + lr + 8) * QSS + kk + lc]);
            af[2] = __float_as_uint(Qs[(rm + lr) * QSS + kk + lc + 4]);
            af[3] = __float_as_uint(Qs[(rm + lr + 8) * QSS + kk + lc + 4]);
            #pragma unroll
            for (int nt = 0; nt < 8; nt++) {
                uint32_t bf[2];
                bf[0] = __float_as_uint(Ks[(nt * 8 + lr) * QSS + kk + lc]);
                bf[1] = __float_as_uint(Ks[(nt * 8 + lr) * QSS + kk + lc + 4]);
                MMA_TF32(sacc[nt], af, bf);
            }
        }

        float mx0 = -1e30f, mx1 = -1e30f;
        #pragma unroll
        for (int nt = 0; nt < 8; nt++) {
            mx0 = fmaxf(mx0, fmaxf(sacc[nt][0], sacc[nt][1]));
            mx1 = fmaxf(mx1, fmaxf(sacc[nt][2], sacc[nt][3]));
        }
        #pragma unroll
        for (int o = 1; o < 4; o <<= 1) {
            mx0 = fmaxf(mx0, __shfl_xor_sync(0xffffffffu, mx0, o, 4));
            mx1 = fmaxf(mx1, __shfl_xor_sync(0xffffffffu, mx1, o, 4));
        }
        const float mn0 = fmaxf(m0, mx0);
        const float mn1 = fmaxf(m1, mx1);
        const float al0 = exp2f(m0 - mn0);
        const float al1 = exp2f(m1 - mn1);
        float rs0 = 0.f, rs1 = 0.f;
        #pragma unroll
        for (int nt = 0; nt < 8; nt++) {
            const float p0 = rnd_tf32(exp2f(sacc[nt][0] - mn0));
            const float p1 = rnd_tf32(exp2f(sacc[nt][1] - mn0));
            const float p2 = rnd_tf32(exp2f(sacc[nt][2] - mn1));
            const float p3 = rnd_tf32(exp2f(sacc[nt][3] - mn1));
            rs0 += p0 + p1; rs1 += p2 + p3;
            *(float2*)&Ps[(rm + lr) * QSS + nt * 8 + 2 * lc]     = make_float2(p0, p1);
            *(float2*)&Ps[(rm + lr + 8) * QSS + nt * 8 + 2 * lc] = make_float2(p2, p3);
        }
        #pragma unroll
        for (int o = 1; o < 4; o <<= 1) {
            rs0 += __shfl_xor_sync(0xffffffffu, rs0, o, 4);
            rs1 += __shfl_xor_sync(0xffffffffu, rs1, o, 4);
        }
        l0 = l0 * al0 + rs0;  m0 = mn0;
        l1 = l1 * al1 + rs1;  m1 = mn1;
        #pragma unroll
        for (int nt = 0; nt < 8; nt++) {
            oacc[nt][0] *= al0; oacc[nt][1] *= al0;
            oacc[nt][2] *= al1; oacc[nt][3] *= al1;
        }
        __syncwarp();

        #pragma unroll
        for (int ks = 0; ks < 8; ks++) {
            const int kk = ks * 8;
            uint32_t af[4];
            af[0] = __float_as_uint(Ps[(rm + lr) * QSS + kk + lc]);
            af[1] = __float_as_uint(Ps[(rm + lr + 8) * QSS + kk + lc]);
            af[2] = __float_as_uint(Ps[(rm + lr) * QSS + kk + lc + 4]);
            af[3] = __float_as_uint(Ps[(rm + lr + 8) * QSS + kk + lc + 4]);
            #pragma unroll
            for (int nt = 0; nt < 8; nt++) {
                uint32_t bf[2];
                bf[0] = __float_as_uint(Vs[(kk + lc) * VSS + nt * 8 + lr]);
                bf[1] = __float_as_uint(Vs[(kk + lc + 4) * VSS + nt * 8 + lr]);
                MMA_TF32(oacc[nt], af, bf);
            }
        }
    }

    const float il0 = 1.0f / l0;
    const float il1 = 1.0f / l1;
    float* ob = out + ((size_t)(b * Nn_ + q0 + rm)) * Cdim + h * Dd;
    #pragma unroll
    for (int nt = 0; nt < 8; nt++) {
        const int col = nt * 8 + 2 * lc;
        *(float2*)(ob + (size_t)lr * Cdim + col) =
            make_float2(rnd_tf32(oacc[nt][0] * il0), rnd_tf32(oacc[nt][1] * il0));
        *(float2*)(ob + (size_t)(lr + 8) * Cdim + col) =
            make_float2(rnd_tf32(oacc[nt][2] * il1), rnd_tf32(oacc[nt][3] * il1));
    }
}

// ---------------------------------------------------------------------------
extern "C" void kernel_launch(void* const* d_in, const int* in_sizes, int n_in,
                              void* d_out, int out_size)
{
    const float* x    = (const float*)d_in[0];
    const float* rcos = (const float*)d_in[1];
    const float* rsin = (const float*)d_in[2];
    const float* g1   = (const float*)d_in[3];
    const float* be1  = (const float*)d_in[4];
    const float* Wq   = (const float*)d_in[5];
    const float* bq   = (const float*)d_in[6];
    const float* Wk   = (const float*)d_in[7];
    const float* bk   = (const float*)d_in[8];
    const float* Wv   = (const float*)d_in[9];
    const float* bv   = (const float*)d_in[10];
    const float* Wo   = (const float*)d_in[11];
    const float* bo   = (const float*)d_in[12];
    const float* g2   = (const float*)d_in[13];
    const float* be2  = (const float*)d_in[14];
    const float* W1   = (const float*)d_in[15];
    const float* b1   = (const float*)d_in[16];
    const float* W2   = (const float*)d_in[17];
    const float* b2   = (const float*)d_in[18];
    float* out = (float*)d_out;

    float* base = nullptr;
    cudaGetSymbolAddress((void**)&base, g_scratch);
    float* p_h   = base + OFF_H;
    float* p_q   = base + OFF_Q;
    float* p_k   = base + OFF_K;
    float* p_v   = base + OFF_V;
    float* p_att = base + OFF_ATT;
    float* p_x2  = base + OFF_X2;
    float* p_mlp = base + OFF_MLP;
    float* p_wq  = base + OFF_WQ;
    float* p_wk  = base + OFF_WK;
    float* p_wv  = base + OFF_WV;
    float* p_wo  = base + OFF_WO;
    float* p_w1  = base + OFF_W1;
    float* p_w2  = base + OFF_W2;

    cudaFuncSetAttribute(flash_kernel,
                         cudaFuncAttributeMaxDynamicSharedMemorySize, FLASH_SMEM);
    cudaFuncSetAttribute(tgemm_kernel,
                         cudaFuncAttributeMaxDynamicSharedMemorySize, GEMM_SMEM);

    // 0. fused weight rounding (6 arrays, one launch)
    const int nC4 = (Cdim * Cdim) / 4;
    const int nF4 = (Cdim * Fdim) / 4;
    RoundSet rs;
    rs.in[0] = (const float4*)Wq; rs.out[0] = (float4*)p_wq; rs.n4[0] = nC4;
    rs.in[1] = (const float4*)Wk; rs.out[1] = (float4*)p_wk; rs.n4[1] = nC4;
    rs.in[2] = (const float4*)Wv; rs.out[2] = (float4*)p_wv; rs.n4[2] = nC4;
    rs.in[3] = (const float4*)Wo; rs.out[3] = (float4*)p_wo; rs.n4[3] = nC4;
    rs.in[4] = (const float4*)W1; rs.out[4] = (float4*)p_w1; rs.n4[4] = nF4;
    rs.in[5] = (const float4*)W2; rs.out[5] = (float4*)p_w2; rs.n4[5] = nF4;
    round_all_kernel<<<dim3(512, 1, 6), 256>>>(rs);

    // 1. LN1
    ln_kernel<<<Mrows, 256>>>(x, g1, be1, p_h);

    // 2. fused QKV projections
    GemmSet qkv;
    qkv.W[0] = p_wq; qkv.W[1] = p_wk; qkv.W[2] = p_wv;
    qkv.bias[0] = bq; qkv.bias[1] = bk; qkv.bias[2] = bv;
    qkv.out[0] = p_q; qkv.out[1] = p_k; qkv.out[2] = p_v;
    tgemm_kernel<<<dim3(Cdim / 128, Mrows / 128, 3), 128, GEMM_SMEM>>>(
        p_h, qkv, nullptr, Mrows, Cdim, Cdim, 0, 0);

    // 3. RoPE
    const int rblocks = (Bb * Nn_ * Hh * 32) / 256;
    rope_kernel<<<rblocks, 256>>>(p_q, rcos, rsin);
    rope_kernel<<<rblocks, 256>>>(p_k, rcos, rsin);

    // 4. attention
    flash_kernel<<<dim3(Nn_ / 128, Bb * Hh), 256, FLASH_SMEM>>>(p_q, p_k, p_v, p_att);

    // 5. output projection + residual
    GemmSet so;
    so.W[0] = p_wo; so.bias[0] = bo; so.out[0] = p_x2;
    so.W[1] = so.W[2] = nullptr; so.bias[1] = so.bias[2] = nullptr;
    so.out[1] = so.out[2] = nullptr;
    tgemm_kernel<<<dim3(Cdim / 128, Mrows / 128, 1), 128, GEMM_SMEM>>>(
        p_att, so, x, Mrows, Cdim, Cdim, 0, 0);

    // 6. LN2
    ln_kernel<<<Mrows, 256>>>(p_x2, g2, be2, p_h);

    // 7. MLP up + GELU (round: A operand of W2 GEMM)
    GemmSet s1;
    s1.W[0] = p_w1; s1.bias[0] = b1; s1.out[0] = p_mlp;
    s1.W[1] = s1.W[2] = nullptr; s1.bias[1] = s1.bias[2] = nullptr;
    s1.out[1] = s1.out[2] = nullptr;
    tgemm_kernel<<<dim3(Fdim / 128, Mrows / 128, 1), 128, GEMM_SMEM>>>(
        p_h, s1, nullptr, Mrows, Fdim, Cdim, 1, 1);

    // 8. MLP down + residual -> output
    GemmSet s2;
    s2.W[0] = p_w2; s2.bias[0] = b2; s2.out[0] = out;
    s2.W[1] = s2.W[2] = nullptr; s2.bias[1] = s2.bias[2] = nullptr;
    s2.out[1] = s2.out[2] = nullptr;
    tgemm_kernel<<<dim3(Cdim / 128, Mrows / 128, 1), 128, GEMM_SMEM>>>(
        p_mlp, s2, p_x2, Mrows, Cdim, Fdim, 0, 0);
}

// round 10
// speedup vs baseline: 1.6455x; 1.5370x over previous
#include <cuda_runtime.h>
#include <cuda_fp16.h>
#include <stdint.h>
#include <math.h>

// ---------------------------------------------------------------------------
// DiT block. Round 10: all matmuls on fp16 mma.sync m16n8k16 (fp32 accum).
// fp16 u = 2^-11 == tf32 u, so accuracy ~ R7; 2x MACs/instruction.
//   B=2, N=2048, C=1024, H=16, D=64, F=4096, M=B*N=4096
// ---------------------------------------------------------------------------

#define Mrows 4096
#define Cdim  1024
#define Fdim  4096
#define Bb    2
#define Hh    16
#define Dd    64
#define Nn_   2048

// byte offsets into scratch
#define OFF_H   ((size_t)0)
#define OFF_Q   ((size_t)8388608)
#define OFF_K   ((size_t)16777216)
#define OFF_V   ((size_t)25165824)
#define OFF_ATT ((size_t)33554432)
#define OFF_MLP ((size_t)41943040)
#define OFF_X2  ((size_t)75497472)
#define OFF_WQ  ((size_t)92274688)
#define OFF_WK  ((size_t)94371840)
#define OFF_WV  ((size_t)96468992)
#define OFF_WO  ((size_t)98566144)
#define OFF_W1  ((size_t)100663296)
#define OFF_W2  ((size_t)109051904)
__device__ __align__(1024) unsigned char g_scratch[117440512];

__device__ __forceinline__ uint32_t h2u(__half2 h) {
    return *reinterpret_cast<uint32_t*>(&h);
}

#define MMA_F16(d, a, b)                                                      \
    asm volatile(                                                             \
        "mma.sync.aligned.m16n8k16.row.col.f32.f16.f16.f32 "                  \
        "{%0,%1,%2,%3}, {%4,%5,%6,%7}, {%8,%9}, {%0,%1,%2,%3};"               \
        : "+f"(d[0]), "+f"(d[1]), "+f"(d[2]), "+f"(d[3])                      \
        : "r"(a[0]), "r"(a[1]), "r"(a[2]), "r"(a[3]), "r"(b[0]), "r"(b[1]))

#define CP_ASYNC16(dst_u32, src_ptr)                                          \
    asm volatile("cp.async.cg.shared.global [%0], [%1], 16;"                  \
                 :: "r"(dst_u32), "l"(src_ptr))
#define CP_COMMIT()  asm volatile("cp.async.commit_group;")
#define CP_WAIT(n)   asm volatile("cp.async.wait_group %0;" :: "n"(n))

// ---------------------------------------------------------------------------
// Weight conversion fp32 -> fp16 (RN), 6 arrays in one launch.
// ---------------------------------------------------------------------------
struct ConvSet {
    const float4* in[6];
    __half2*      out[6];
    int           n4[6];
};

__global__ void __launch_bounds__(256) conv_half_kernel(ConvSet cs)
{
    const int z = blockIdx.z;
    const float4* __restrict__ in = cs.in[z];
    __half2* __restrict__ out = cs.out[z];
    const int n4 = cs.n4[z];
    const int stride = gridDim.x * 256;
    for (int i = blockIdx.x * 256 + threadIdx.x; i < n4; i += stride) {
        const float4 v = in[i];
        __half2 h01 = __floats2half2_rn(v.x, v.y);
        __half2 h23 = __floats2half2_rn(v.z, v.w);
        uint2 u; u.x = h2u(h01); u.y = h2u(h23);
        *(uint2*)&out[2 * i] = u;
    }
}

// ---------------------------------------------------------------------------
// LayerNorm: one block (256 thr) per row of 1024. fp32 in, fp16 out.
// ---------------------------------------------------------------------------
__global__ void __launch_bounds__(256) ln_kernel(
    const float* __restrict__ x, const float* __restrict__ g,
    const float* __restrict__ b, __half* __restrict__ out)
{
    __shared__ float red[16];
    const int row = blockIdx.x;
    const int t = threadIdx.x;
    const float4 xv = ((const float4*)(x + (size_t)row * Cdim))[t];
    float s  = xv.x + xv.y + xv.z + xv.w;
    float ss = xv.x*xv.x + xv.y*xv.y + xv.z*xv.z + xv.w*xv.w;
    #pragma unroll
    for (int o = 16; o > 0; o >>= 1) {
        s  += __shfl_xor_sync(0xffffffffu, s,  o);
        ss += __shfl_xor_sync(0xffffffffu, ss, o);
    }
    const int w = t >> 5;
    if ((t & 31) == 0) { red[w] = s; red[8 + w] = ss; }
    __syncthreads();
    float ts = 0.f, tss = 0.f;
    #pragma unroll
    for (int i = 0; i < 8; i++) { ts += red[i]; tss += red[8 + i]; }
    const float mean = ts * (1.0f / Cdim);
    const float var  = tss * (1.0f / Cdim) - mean * mean;
    const float inv  = rsqrtf(var + 1e-6f);
    const float4 gv = ((const float4*)g)[t];
    const float4 bv = ((const float4*)b)[t];
    __half2 h01 = __floats2half2_rn((xv.x - mean) * inv * gv.x + bv.x,
                                    (xv.y - mean) * inv * gv.y + bv.y);
    __half2 h23 = __floats2half2_rn((xv.z - mean) * inv * gv.z + bv.z,
                                    (xv.w - mean) * inv * gv.w + bv.w);
    uint2 u; u.x = h2u(h01); u.y = h2u(h23);
    *(uint2*)(out + (size_t)row * Cdim + 4 * t) = u;
}

// ---------------------------------------------------------------------------
// fp16 GEMM, 3-stage cp.async, 128x128 tile, BK=32, 256 thr (8 warps 2Mx4N),
// warp tile 64x32, mma m16n8k16 (2 k-steps per stage).
// out[z] = A[M,K](half) @ W[z][Nc,K](half)^T + bias (+GELU)(+fp32 resid)
// ---------------------------------------------------------------------------
#define GSH 40                       // smem row stride in halves
#define TBUFH (128 * GSH)            // halves per tile buffer
#define BOFFH (3 * TBUFH)
#define GEMM_SMEM (6 * TBUFH * 2)    // bytes

struct GemmSet {
    const __half* W[3];
    const float*  bias[3];
    void*         out[3];
};

__global__ void __launch_bounds__(256, 2) hgemm_kernel(
    const __half* __restrict__ A, GemmSet gs, const float* __restrict__ residual,
    int M, int Nc, int K, int gelu, int out_half)
{
    extern __shared__ __half smh[];
    const uint32_t sbase = (uint32_t)__cvta_generic_to_shared(smh);

    const int z = blockIdx.z;
    const __half* __restrict__ Wp  = gs.W[z];
    const float* __restrict__ bias = gs.bias[z];
    void* __restrict__ outp        = gs.out[z];

    const int tid  = threadIdx.x;
    const int wid  = tid >> 5;
    const int lane = tid & 31;
    const int lr   = lane >> 2;
    const int lc   = lane & 3;
    const int warpM = (wid & 1) * 64;
    const int warpN = (wid >> 1) * 32;
    const int bm = blockIdx.y * 128, bn = blockIdx.x * 128;

    float acc[4][4][4];
    #pragma unroll
    for (int i = 0; i < 4; i++)
        #pragma unroll
        for (int j = 0; j < 4; j++)
            #pragma unroll
            for (int r = 0; r < 4; r++) acc[i][j][r] = 0.f;

    const int nk = K >> 5;

    // A tile: 128 rows x 32 halves = 512 x 16B chunks; B same.
    #define LOAD_TILE(stg, k0)                                                \
    do {                                                                      \
        _Pragma("unroll")                                                     \
        for (int p = 0; p < 2; p++) {                                         \
            const int id = tid + p * 256;                                     \
            const int row = id >> 2;                                          \
            const int kc = id & 3;                                            \
            const uint32_t da = sbase + (uint32_t)(((stg) * TBUFH + row * GSH + kc * 8) * 2); \
            CP_ASYNC16(da, A + (size_t)(bm + row) * K + (k0) + kc * 8);       \
        }                                                                     \
        _Pragma("unroll")                                                     \
        for (int p = 0; p < 2; p++) {                                         \
            const int id = tid + p * 256;                                     \
            const int row = id >> 2;                                          \
            const int kc = id & 3;                                            \
            const uint32_t db = sbase + (uint32_t)((BOFFH + (stg) * TBUFH + row * GSH + kc * 8) * 2); \
            CP_ASYNC16(db, Wp + (size_t)(bn + row) * K + (k0) + kc * 8);      \
        }                                                                     \
    } while (0)

    LOAD_TILE(0, 0);
    CP_COMMIT();
    if (nk > 1) { LOAD_TILE(1, 32); }
    CP_COMMIT();

    int stg = 0;
    for (int kt = 0; kt < nk; kt++) {
        if (kt + 1 < nk) { CP_WAIT(1); } else { CP_WAIT(0); }
        __syncthreads();

        if (kt + 2 < nk) {
            const int ns = (stg + 2 >= 3) ? stg - 1 : stg + 2;
            LOAD_TILE(ns, (kt + 2) << 5);
            CP_COMMIT();
        }

        const __half* Asm = smh + stg * TBUFH;
        const __half* Bsm = smh + BOFFH + stg * TBUFH;
        #pragma unroll
        for (int ks = 0; ks < 2; ks++) {
            const int kk = ks * 16;
            uint32_t af[4][4], bf[4][2];
            #pragma unroll
            for (int i = 0; i < 4; i++) {
                const int rb = warpM + i * 16;
                af[i][0] = *(const uint32_t*)&Asm[(rb + lr) * GSH + kk + 2 * lc];
                af[i][1] = *(const uint32_t*)&Asm[(rb + lr + 8) * GSH + kk + 2 * lc];
                af[i][2] = *(const uint32_t*)&Asm[(rb + lr) * GSH + kk + 2 * lc + 8];
                af[i][3] = *(const uint32_t*)&Asm[(rb + lr + 8) * GSH + kk + 2 * lc + 8];
            }
            #pragma unroll
            for (int j = 0; j < 4; j++) {
                const int cb = warpN + j * 8;
                bf[j][0] = *(const uint32_t*)&Bsm[(cb + lr) * GSH + kk + 2 * lc];
                bf[j][1] = *(const uint32_t*)&Bsm[(cb + lr) * GSH + kk + 2 * lc + 8];
            }
            #pragma unroll
            for (int i = 0; i < 4; i++)
                #pragma unroll
                for (int j = 0; j < 4; j++)
                    MMA_F16(acc[i][j], af[i], bf[j]);
        }
        stg = (stg + 1 >= 3) ? 0 : stg + 1;
    }

    // epilogue (C layout: rows lr/lr+8, cols 2*lc, 2*lc+1)
    #pragma unroll
    for (int i = 0; i < 4; i++) {
        const int row0 = bm + warpM + i * 16 + lr;
        #pragma unroll
        for (int j = 0; j < 4; j++) {
            const int col = bn + warpN + j * 8 + (lc << 1);
            const float b0 = __ldg(&bias[col]);
            const float b1 = __ldg(&bias[col + 1]);
            float v0 = acc[i][j][0] + b0;
            float v1 = acc[i][j][1] + b1;
            float v2 = acc[i][j][2] + b0;
            float v3 = acc[i][j][3] + b1;
            if (gelu) {
                v0 = 0.5f * v0 * (1.0f + erff(v0 * 0.70710678118654752f));
                v1 = 0.5f * v1 * (1.0f + erff(v1 * 0.70710678118654752f));
                v2 = 0.5f * v2 * (1.0f + erff(v2 * 0.70710678118654752f));
                v3 = 0.5f * v3 * (1.0f + erff(v3 * 0.70710678118654752f));
            }
            if (residual) {
                v0 += residual[(size_t)row0 * Nc + col];
                v1 += residual[(size_t)row0 * Nc + col + 1];
                v2 += residual[(size_t)(row0 + 8) * Nc + col];
                v3 += residual[(size_t)(row0 + 8) * Nc + col + 1];
            }
            if (out_half) {
                __half* oh = (__half*)outp;
                *(uint32_t*)(oh + (size_t)row0 * Nc + col)       = h2u(__floats2half2_rn(v0, v1));
                *(uint32_t*)(oh + (size_t)(row0 + 8) * Nc + col) = h2u(__floats2half2_rn(v2, v3));
            } else {
                float* of = (float*)outp;
                *(float2*)(of + (size_t)row0 * Nc + col)       = make_float2(v0, v1);
                *(float2*)(of + (size_t)(row0 + 8) * Nc + col) = make_float2(v2, v3);
            }
        }
    }
}

// ---------------------------------------------------------------------------
// RoPE in place on half tensor [B*N, C], col = h*64 + d
// ---------------------------------------------------------------------------
__global__ void __launch_bounds__(256) rope_kernel(
    __half* __restrict__ t, const float* __restrict__ cosb,
    const float* __restrict__ sinb)
{
    int idx = blockIdx.x * 256 + threadIdx.x;
    const int d = idx & 31; idx >>= 5;
    const int h = idx & (Hh - 1); idx >>= 4;
    const int n = idx & (Nn_ - 1); idx >>= 11;
    const int b = idx;
    const size_t base = ((size_t)(b * Nn_ + n)) * Cdim + h * Dd;
    const float x1 = __half2float(t[base + d]);
    const float x2 = __half2float(t[base + d + 32]);
    const float c1 = cosb[n * Dd + d],      s1 = sinb[n * Dd + d];
    const float c2 = cosb[n * Dd + d + 32], s2 = sinb[n * Dd + d + 32];
    t[base + d]      = __float2half_rn(x1 * c1 - x2 * s1);
    t[base + d + 32] = __float2half_rn(x2 * c2 + x1 * s2);
}

// ---------------------------------------------------------------------------
// Flash attention, fp16 mma (fp32 accum). Q tile 128, KV tile 64, D=64.
// 8 warps, warp owns 16 query rows. V stored transposed [d][kv] so PV
// B-fragments are contiguous half2. P through per-warp smem.
// smem (halves): Qs[128][72], Ks[64][72], Vt[64][72], Ps[128][72]
// ---------------------------------------------------------------------------
#define QSH 72
#define F_QS 0
#define F_KS (128 * QSH)
#define F_VS (F_KS + 64 * QSH)
#define F_PS (F_VS + 64 * QSH)
#define FLASH_SMEM ((F_PS + 128 * QSH) * 2)

__global__ void __launch_bounds__(256) flash_kernel(
    const __half* __restrict__ q, const __half* __restrict__ k,
    const __half* __restrict__ v, __half* __restrict__ out)
{
    extern __shared__ __half smf[];
    __half* Qs = smf + F_QS;
    __half* Ks = smf + F_KS;
    __half* Vt = smf + F_VS;
    __half* Ps = smf + F_PS;

    const int tid  = threadIdx.x;
    const int wid  = tid >> 5;
    const int lane = tid & 31;
    const int lr   = lane >> 2;
    const int lc   = lane & 3;
    const int rm   = wid * 16;

    const int bh = blockIdx.y;
    const int b = bh >> 4;
    const int h = bh & 15;
    const int q0 = blockIdx.x * 128;
    const float qscale = 0.125f * 1.4426950408889634f;  // D^-1/2 * log2(e)

    // Q tile: 128 x 64 halves = 1024 x (8-half) chunks; scale while loading
    const __half* qb = q + ((size_t)(b * Nn_ + q0)) * Cdim + h * Dd;
    #pragma unroll
    for (int i = 0; i < 4; i++) {
        const int idx = tid + i * 256;
        const int r = idx >> 3;
        const int c = (idx & 7) * 8;
        uint4 u = *(const uint4*)(qb + (size_t)r * Cdim + c);
        __half2* hp = (__half2*)&u;
        #pragma unroll
        for (int j = 0; j < 4; j++) {
            float2 f = __half22float2(hp[j]);
            hp[j] = __floats2half2_rn(f.x * qscale, f.y * qscale);
        }
        *(uint4*)&Qs[r * QSH + c] = u;
    }

    // staging for K/V (64 x 64 halves = 512 chunks, 2 per thread)
    int srow[2], scol[2];
    #pragma unroll
    for (int i = 0; i < 2; i++) {
        const int idx = tid + i * 256;
        srow[i] = idx >> 3;
        scol[i] = (idx & 7) * 8;
    }
    const __half* kb0 = k + ((size_t)(b * Nn_)) * Cdim + h * Dd;
    const __half* vb0 = v + ((size_t)(b * Nn_)) * Cdim + h * Dd;

    uint4 kreg[2], vreg[2];
    #pragma unroll
    for (int i = 0; i < 2; i++) {
        kreg[i] = *(const uint4*)(kb0 + (size_t)srow[i] * Cdim + scol[i]);
        vreg[i] = *(const uint4*)(vb0 + (size_t)srow[i] * Cdim + scol[i]);
    }

    float m0 = -1e30f, m1 = -1e30f, l0 = 0.f, l1 = 0.f;
    float oacc[8][4];
    #pragma unroll
    for (int nt = 0; nt < 8; nt++)
        #pragma unroll
        for (int r = 0; r < 4; r++) oacc[nt][r] = 0.f;

    for (int kv0 = 0; kv0 < Nn_; kv0 += 64) {
        __syncthreads();
        #pragma unroll
        for (int i = 0; i < 2; i++) {
            *(uint4*)&Ks[srow[i] * QSH + scol[i]] = kreg[i];
            const __half* vh = (const __half*)&vreg[i];
            #pragma unroll
            for (int j = 0; j < 8; j++)
                Vt[(scol[i] + j) * QSH + srow[i]] = vh[j];   // transpose
        }
        __syncthreads();

        if (kv0 + 64 < Nn_) {
            const __half* kb = kb0 + (size_t)(kv0 + 64) * Cdim;
            const __half* vb = vb0 + (size_t)(kv0 + 64) * Cdim;
            #pragma unroll
            for (int i = 0; i < 2; i++) {
                kreg[i] = *(const uint4*)(kb + (size_t)srow[i] * Cdim + scol[i]);
                vreg[i] = *(const uint4*)(vb + (size_t)srow[i] * Cdim + scol[i]);
            }
        }

        // S = Qs @ Ks^T  (contraction over D=64: 4 k16 steps)
        float sacc[8][4];
        #pragma unroll
        for (int nt = 0; nt < 8; nt++)
            #pragma unroll
            for (int r = 0; r < 4; r++) sacc[nt][r] = 0.f;
        #pragma unroll
        for (int ks = 0; ks < 4; ks++) {
            const int kk = ks * 16;
            uint32_t af[4];
            af[0] = *(const uint32_t*)&Qs[(rm + lr) * QSH + kk + 2 * lc];
            af[1] = *(const uint32_t*)&Qs[(rm + lr + 8) * QSH + kk + 2 * lc];
            af[2] = *(const uint32_t*)&Qs[(rm + lr) * QSH + kk + 2 * lc + 8];
            af[3] = *(const uint32_t*)&Qs[(rm + lr + 8) * QSH + kk + 2 * lc + 8];
            #pragma unroll
            for (int nt = 0; nt < 8; nt++) {
                uint32_t bf[2];
                bf[0] = *(const uint32_t*)&Ks[(nt * 8 + lr) * QSH + kk + 2 * lc];
                bf[1] = *(const uint32_t*)&Ks[(nt * 8 + lr) * QSH + kk + 2 * lc + 8];
                MMA_F16(sacc[nt], af, bf);
            }
        }

        // online softmax (rows rm+lr, rm+lr+8; 4-lane groups share a row)
        float mx0 = -1e30f, mx1 = -1e30f;
        #pragma unroll
        for (int nt = 0; nt < 8; nt++) {
            mx0 = fmaxf(mx0, fmaxf(sacc[nt][0], sacc[nt][1]));
            mx1 = fmaxf(mx1, fmaxf(sacc[nt][2], sacc[nt][3]));
        }
        #pragma unroll
        for (int o = 1; o < 4; o <<= 1) {
            mx0 = fmaxf(mx0, __shfl_xor_sync(0xffffffffu, mx0, o, 4));
            mx1 = fmaxf(mx1, __shfl_xor_sync(0xffffffffu, mx1, o, 4));
        }
        const float mn0 = fmaxf(m0, mx0);
        const float mn1 = fmaxf(m1, mx1);
        const float al0 = exp2f(m0 - mn0);
        const float al1 = exp2f(m1 - mn1);
        float rs0 = 0.f, rs1 = 0.f;
        #pragma unroll
        for (int nt = 0; nt < 8; nt++) {
            __half2 p01 = __floats2half2_rn(exp2f(sacc[nt][0] - mn0),
                                            exp2f(sacc[nt][1] - mn0));
            __half2 p23 = __floats2half2_rn(exp2f(sacc[nt][2] - mn1),
                                            exp2f(sacc[nt][3] - mn1));
            const float2 f01 = __half22float2(p01);
            const float2 f23 = __half22float2(p23);
            rs0 += f01.x + f01.y;
            rs1 += f23.x + f23.y;
            *(uint32_t*)&Ps[(rm + lr) * QSH + nt * 8 + 2 * lc]     = h2u(p01);
            *(uint32_t*)&Ps[(rm + lr + 8) * QSH + nt * 8 + 2 * lc] = h2u(p23);
        }
        #pragma unroll
        for (int o = 1; o < 4; o <<= 1) {
            rs0 += __shfl_xor_sync(0xffffffffu, rs0, o, 4);
            rs1 += __shfl_xor_sync(0xffffffffu, rs1, o, 4);
        }
        l0 = l0 * al0 + rs0;  m0 = mn0;
        l1 = l1 * al1 + rs1;  m1 = mn1;
        #pragma unroll
        for (int nt = 0; nt < 8; nt++) {
            oacc[nt][0] *= al0; oacc[nt][1] *= al0;
            oacc[nt][2] *= al1; oacc[nt][3] *= al1;
        }
        __syncwarp();   // Ps rows are warp-private

        // O += P @ Vt  (contraction over kv=64: 4 k16 steps)
        #pragma unroll
        for (int ks = 0; ks < 4; ks++) {
            const int kk = ks * 16;
            uint32_t af[4];
            af[0] = *(const uint32_t*)&Ps[(rm + lr) * QSH + kk + 2 * lc];
            af[1] = *(const uint32_t*)&Ps[(rm + lr + 8) * QSH + kk + 2 * lc];
            af[2] = *(const uint32_t*)&Ps[(rm + lr) * QSH + kk + 2 * lc + 8];
            af[3] = *(const uint32_t*)&Ps[(rm + lr + 8) * QSH + kk + 2 * lc + 8];
            #pragma unroll
            for (int nt = 0; nt < 8; nt++) {
                uint32_t bf[2];
                bf[0] = *(const uint32_t*)&Vt[(nt * 8 + lr) * QSH + kk + 2 * lc];
                bf[1] = *(const uint32_t*)&Vt[(nt * 8 + lr) * QSH + kk + 2 * lc + 8];
                MMA_F16(oacc[nt], af, bf);
            }
        }
    }

    // write O (half: A operand of Wo GEMM)
    const float il0 = 1.0f / l0;
    const float il1 = 1.0f / l1;
    __half* ob = out + ((size_t)(b * Nn_ + q0 + rm)) * Cdim + h * Dd;
    #pragma unroll
    for (int nt = 0; nt < 8; nt++) {
        const int col = nt * 8 + 2 * lc;
        *(uint32_t*)(ob + (size_t)lr * Cdim + col) =
            h2u(__floats2half2_rn(oacc[nt][0] * il0, oacc[nt][1] * il0));
        *(uint32_t*)(ob + (size_t)(lr + 8) * Cdim + col) =
            h2u(__floats2half2_rn(oacc[nt][2] * il1, oacc[nt][3] * il1));
    }
}

// ---------------------------------------------------------------------------
extern "C" void kernel_launch(void* const* d_in, const int* in_sizes, int n_in,
                              void* d_out, int out_size)
{
    const float* x    = (const float*)d_in[0];
    const float* rcos = (const float*)d_in[1];
    const float* rsin = (const float*)d_in[2];
    const float* g1   = (const float*)d_in[3];
    const float* be1  = (const float*)d_in[4];
    const float* Wq   = (const float*)d_in[5];
    const float* bq   = (const float*)d_in[6];
    const float* Wk   = (const float*)d_in[7];
    const float* bk   = (const float*)d_in[8];
    const float* Wv   = (const float*)d_in[9];
    const float* bv   = (const float*)d_in[10];
    const float* Wo   = (const float*)d_in[11];
    const float* bo   = (const float*)d_in[12];
    const float* g2   = (const float*)d_in[13];
    const float* be2  = (const float*)d_in[14];
    const float* W1   = (const float*)d_in[15];
    const float* b1   = (const float*)d_in[16];
    const float* W2   = (const float*)d_in[17];
    const float* b2   = (const float*)d_in[18];
    float* out = (float*)d_out;

    unsigned char* base = nullptr;
    cudaGetSymbolAddress((void**)&base, g_scratch);
    __half* p_h   = (__half*)(base + OFF_H);
    __half* p_q   = (__half*)(base + OFF_Q);
    __half* p_k   = (__half*)(base + OFF_K);
    __half* p_v   = (__half*)(base + OFF_V);
    __half* p_att = (__half*)(base + OFF_ATT);
    __half* p_mlp = (__half*)(base + OFF_MLP);
    float*  p_x2  = (float*)(base + OFF_X2);
    __half* p_wq  = (__half*)(base + OFF_WQ);
    __half* p_wk  = (__half*)(base + OFF_WK);
    __half* p_wv  = (__half*)(base + OFF_WV);
    __half* p_wo  = (__half*)(base + OFF_WO);
    __half* p_w1  = (__half*)(base + OFF_W1);
    __half* p_w2  = (__half*)(base + OFF_W2);

    cudaFuncSetAttribute(flash_kernel,
                         cudaFuncAttributeMaxDynamicSharedMemorySize, FLASH_SMEM);
    cudaFuncSetAttribute(hgemm_kernel,
                         cudaFuncAttributeMaxDynamicSharedMemorySize, GEMM_SMEM);

    // 0. weights -> fp16 (one launch)
    const int nC4 = (Cdim * Cdim) / 4;
    const int nF4 = (Cdim * Fdim) / 4;
    ConvSet cs;
    cs.in[0] = (const float4*)Wq; cs.out[0] = (__half2*)p_wq; cs.n4[0] = nC4;
    cs.in[1] = (const float4*)Wk; cs.out[1] = (__half2*)p_wk; cs.n4[1] = nC4;
    cs.in[2] = (const float4*)Wv; cs.out[2] = (__half2*)p_wv; cs.n4[2] = nC4;
    cs.in[3] = (const float4*)Wo; cs.out[3] = (__half2*)p_wo; cs.n4[3] = nC4;
    cs.in[4] = (const float4*)W1; cs.out[4] = (__half2*)p_w1; cs.n4[4] = nF4;
    cs.in[5] = (const float4*)W2; cs.out[5] = (__half2*)p_w2; cs.n4[5] = nF4;
    conv_half_kernel<<<dim3(512, 1, 6), 256>>>(cs);

    // 1. LN1 -> half
    ln_kernel<<<Mrows, 256>>>(x, g1, be1, p_h);

    // 2. fused QKV projections -> half
    GemmSet qkv;
    qkv.W[0] = p_wq; qkv.W[1] = p_wk; qkv.W[2] = p_wv;
    qkv.bias[0] = bq; qkv.bias[1] = bk; qkv.bias[2] = bv;
    qkv.out[0] = p_q; qkv.out[1] = p_k; qkv.out[2] = p_v;
    hgemm_kernel<<<dim3(Cdim / 128, Mrows / 128, 3), 256, GEMM_SMEM>>>(
        p_h, qkv, nullptr, Mrows, Cdim, Cdim, 0, 1);

    // 3. RoPE (in place on half q/k)
    const int rblocks = (Bb * Nn_ * Hh * 32) / 256;
    rope_kernel<<<rblocks, 256>>>(p_q, rcos, rsin);
    rope_kernel<<<rblocks, 256>>>(p_k, rcos, rsin);

    // 4. attention -> half
    flash_kernel<<<dim3(Nn_ / 128, Bb * Hh), 256, FLASH_SMEM>>>(p_q, p_k, p_v, p_att);

    // 5. output projection + fp32 residual -> fp32 x2
    GemmSet so;
    so.W[0] = p_wo; so.bias[0] = bo; so.out[0] = p_x2;
    so.W[1] = so.W[2] = nullptr; so.bias[1] = so.bias[2] = nullptr;
    so.out[1] = so.out[2] = nullptr;
    hgemm_kernel<<<dim3(Cdim / 128, Mrows / 128, 1), 256, GEMM_SMEM>>>(
        p_att, so, x, Mrows, Cdim, Cdim, 0, 0);

    // 6. LN2 -> half
    ln_kernel<<<Mrows, 256>>>(p_x2, g2, be2, p_h);

    // 7. MLP up + GELU -> half
    GemmSet s1;
    s1.W[0] = p_w1; s1.bias[0] = b1; s1.out[0] = p_mlp;
    s1.W[1] = s1.W[2] = nullptr; s1.bias[1] = s1.bias[2] = nullptr;
    s1.out[1] = s1.out[2] = nullptr;
    hgemm_kernel<<<dim3(Fdim / 128, Mrows / 128, 1), 256, GEMM_SMEM>>>(
        p_h, s1, nullptr, Mrows, Fdim, Cdim, 1, 1);

    // 8. MLP down + fp32 residual -> fp32 output
    GemmSet s2;
    s2.W[0] = p_w2; s2.bias[0] = b2; s2.out[0] = out;
    s2.W[1] = s2.W[2] = nullptr; s2.bias[1] = s2.bias[2] = nullptr;
    s2.out[1] = s2.out[2] = nullptr;
    hgemm_kernel<<<dim3(Cdim / 128, Mrows / 128, 1), 256, GEMM_SMEM>>>(
        p_mlp, s2, p_x2, Mrows, Cdim, Fdim, 0, 0);
}

// round 11
// speedup vs baseline: 1.6965x; 1.0310x over previous
#include <cuda_runtime.h>
#include <cuda_fp16.h>
#include <stdint.h>
#include <math.h>

// ---------------------------------------------------------------------------
// DiT block. Round 11: fp16 mma everywhere; flash keeps P (and Q frags) in
// registers — no Ps smem round-trip; vectorized fused RoPE launch.
//   B=2, N=2048, C=1024, H=16, D=64, F=4096, M=B*N=4096
// ---------------------------------------------------------------------------

#define Mrows 4096
#define Cdim  1024
#define Fdim  4096
#define Bb    2
#define Hh    16
#define Dd    64
#define Nn_   2048

// byte offsets into scratch
#define OFF_H   ((size_t)0)
#define OFF_Q   ((size_t)8388608)
#define OFF_K   ((size_t)16777216)
#define OFF_V   ((size_t)25165824)
#define OFF_ATT ((size_t)33554432)
#define OFF_MLP ((size_t)41943040)
#define OFF_X2  ((size_t)75497472)
#define OFF_WQ  ((size_t)92274688)
#define OFF_WK  ((size_t)94371840)
#define OFF_WV  ((size_t)96468992)
#define OFF_WO  ((size_t)98566144)
#define OFF_W1  ((size_t)100663296)
#define OFF_W2  ((size_t)109051904)
__device__ __align__(1024) unsigned char g_scratch[117440512];

__device__ __forceinline__ uint32_t h2u(__half2 h) {
    return *reinterpret_cast<uint32_t*>(&h);
}

#define MMA_F16(d, a, b)                                                      \
    asm volatile(                                                             \
        "mma.sync.aligned.m16n8k16.row.col.f32.f16.f16.f32 "                  \
        "{%0,%1,%2,%3}, {%4,%5,%6,%7}, {%8,%9}, {%0,%1,%2,%3};"               \
        : "+f"(d[0]), "+f"(d[1]), "+f"(d[2]), "+f"(d[3])                      \
        : "r"(a[0]), "r"(a[1]), "r"(a[2]), "r"(a[3]), "r"(b[0]), "r"(b[1]))

#define CP_ASYNC16(dst_u32, src_ptr)                                          \
    asm volatile("cp.async.cg.shared.global [%0], [%1], 16;"                  \
                 :: "r"(dst_u32), "l"(src_ptr))
#define CP_COMMIT()  asm volatile("cp.async.commit_group;")
#define CP_WAIT(n)   asm volatile("cp.async.wait_group %0;" :: "n"(n))

// ---------------------------------------------------------------------------
// Weight conversion fp32 -> fp16 (RN), 6 arrays in one launch.
// ---------------------------------------------------------------------------
struct ConvSet {
    const float4* in[6];
    __half2*      out[6];
    int           n4[6];
};

__global__ void __launch_bounds__(256) conv_half_kernel(ConvSet cs)
{
    const int z = blockIdx.z;
    const float4* __restrict__ in = cs.in[z];
    __half2* __restrict__ out = cs.out[z];
    const int n4 = cs.n4[z];
    const int stride = gridDim.x * 256;
    for (int i = blockIdx.x * 256 + threadIdx.x; i < n4; i += stride) {
        const float4 v = in[i];
        __half2 h01 = __floats2half2_rn(v.x, v.y);
        __half2 h23 = __floats2half2_rn(v.z, v.w);
        uint2 u; u.x = h2u(h01); u.y = h2u(h23);
        *(uint2*)&out[2 * i] = u;
    }
}

// ---------------------------------------------------------------------------
// LayerNorm: one block (256 thr) per row of 1024. fp32 in, fp16 out.
// ---------------------------------------------------------------------------
__global__ void __launch_bounds__(256) ln_kernel(
    const float* __restrict__ x, const float* __restrict__ g,
    const float* __restrict__ b, __half* __restrict__ out)
{
    __shared__ float red[16];
    const int row = blockIdx.x;
    const int t = threadIdx.x;
    const float4 xv = ((const float4*)(x + (size_t)row * Cdim))[t];
    float s  = xv.x + xv.y + xv.z + xv.w;
    float ss = xv.x*xv.x + xv.y*xv.y + xv.z*xv.z + xv.w*xv.w;
    #pragma unroll
    for (int o = 16; o > 0; o >>= 1) {
        s  += __shfl_xor_sync(0xffffffffu, s,  o);
        ss += __shfl_xor_sync(0xffffffffu, ss, o);
    }
    const int w = t >> 5;
    if ((t & 31) == 0) { red[w] = s; red[8 + w] = ss; }
    __syncthreads();
    float ts = 0.f, tss = 0.f;
    #pragma unroll
    for (int i = 0; i < 8; i++) { ts += red[i]; tss += red[8 + i]; }
    const float mean = ts * (1.0f / Cdim);
    const float var  = tss * (1.0f / Cdim) - mean * mean;
    const float inv  = rsqrtf(var + 1e-6f);
    const float4 gv = ((const float4*)g)[t];
    const float4 bv = ((const float4*)b)[t];
    __half2 h01 = __floats2half2_rn((xv.x - mean) * inv * gv.x + bv.x,
                                    (xv.y - mean) * inv * gv.y + bv.y);
    __half2 h23 = __floats2half2_rn((xv.z - mean) * inv * gv.z + bv.z,
                                    (xv.w - mean) * inv * gv.w + bv.w);
    uint2 u; u.x = h2u(h01); u.y = h2u(h23);
    *(uint2*)(out + (size_t)row * Cdim + 4 * t) = u;
}

// ---------------------------------------------------------------------------
// fp16 GEMM, 3-stage cp.async, 128x128 tile, BK=32, 256 thr (8 warps 2Mx4N),
// warp tile 64x32, mma m16n8k16 (2 k-steps per stage). Unchanged from R10.
// ---------------------------------------------------------------------------
#define GSH 40
#define TBUFH (128 * GSH)
#define BOFFH (3 * TBUFH)
#define GEMM_SMEM (6 * TBUFH * 2)

struct GemmSet {
    const __half* W[3];
    const float*  bias[3];
    void*         out[3];
};

__global__ void __launch_bounds__(256, 2) hgemm_kernel(
    const __half* __restrict__ A, GemmSet gs, const float* __restrict__ residual,
    int M, int Nc, int K, int gelu, int out_half)
{
    extern __shared__ __half smh[];
    const uint32_t sbase = (uint32_t)__cvta_generic_to_shared(smh);

    const int z = blockIdx.z;
    const __half* __restrict__ Wp  = gs.W[z];
    const float* __restrict__ bias = gs.bias[z];
    void* __restrict__ outp        = gs.out[z];

    const int tid  = threadIdx.x;
    const int wid  = tid >> 5;
    const int lane = tid & 31;
    const int lr   = lane >> 2;
    const int lc   = lane & 3;
    const int warpM = (wid & 1) * 64;
    const int warpN = (wid >> 1) * 32;
    const int bm = blockIdx.y * 128, bn = blockIdx.x * 128;

    float acc[4][4][4];
    #pragma unroll
    for (int i = 0; i < 4; i++)
        #pragma unroll
        for (int j = 0; j < 4; j++)
            #pragma unroll
            for (int r = 0; r < 4; r++) acc[i][j][r] = 0.f;

    const int nk = K >> 5;

    #define LOAD_TILE(stg, k0)                                                \
    do {                                                                      \
        _Pragma("unroll")                                                     \
        for (int p = 0; p < 2; p++) {                                         \
            const int id = tid + p * 256;                                     \
            const int row = id >> 2;                                          \
            const int kc = id & 3;                                            \
            const uint32_t da = sbase + (uint32_t)(((stg) * TBUFH + row * GSH + kc * 8) * 2); \
            CP_ASYNC16(da, A + (size_t)(bm + row) * K + (k0) + kc * 8);       \
        }                                                                     \
        _Pragma("unroll")                                                     \
        for (int p = 0; p < 2; p++) {                                         \
            const int id = tid + p * 256;                                     \
            const int row = id >> 2;                                          \
            const int kc = id & 3;                                            \
            const uint32_t db = sbase + (uint32_t)((BOFFH + (stg) * TBUFH + row * GSH + kc * 8) * 2); \
            CP_ASYNC16(db, Wp + (size_t)(bn + row) * K + (k0) + kc * 8);      \
        }                                                                     \
    } while (0)

    LOAD_TILE(0, 0);
    CP_COMMIT();
    if (nk > 1) { LOAD_TILE(1, 32); }
    CP_COMMIT();

    int stg = 0;
    for (int kt = 0; kt < nk; kt++) {
        if (kt + 1 < nk) { CP_WAIT(1); } else { CP_WAIT(0); }
        __syncthreads();

        if (kt + 2 < nk) {
            const int ns = (stg + 2 >= 3) ? stg - 1 : stg + 2;
            LOAD_TILE(ns, (kt + 2) << 5);
            CP_COMMIT();
        }

        const __half* Asm = smh + stg * TBUFH;
        const __half* Bsm = smh + BOFFH + stg * TBUFH;
        #pragma unroll
        for (int ks = 0; ks < 2; ks++) {
            const int kk = ks * 16;
            uint32_t af[4][4], bf[4][2];
            #pragma unroll
            for (int i = 0; i < 4; i++) {
                const int rb = warpM + i * 16;
                af[i][0] = *(const uint32_t*)&Asm[(rb + lr) * GSH + kk + 2 * lc];
                af[i][1] = *(const uint32_t*)&Asm[(rb + lr + 8) * GSH + kk + 2 * lc];
                af[i][2] = *(const uint32_t*)&Asm[(rb + lr) * GSH + kk + 2 * lc + 8];
                af[i][3] = *(const uint32_t*)&Asm[(rb + lr + 8) * GSH + kk + 2 * lc + 8];
            }
            #pragma unroll
            for (int j = 0; j < 4; j++) {
                const int cb = warpN + j * 8;
                bf[j][0] = *(const uint32_t*)&Bsm[(cb + lr) * GSH + kk + 2 * lc];
                bf[j][1] = *(const uint32_t*)&Bsm[(cb + lr) * GSH + kk + 2 * lc + 8];
            }
            #pragma unroll
            for (int i = 0; i < 4; i++)
                #pragma unroll
                for (int j = 0; j < 4; j++)
                    MMA_F16(acc[i][j], af[i], bf[j]);
        }
        stg = (stg + 1 >= 3) ? 0 : stg + 1;
    }

    #pragma unroll
    for (int i = 0; i < 4; i++) {
        const int row0 = bm + warpM + i * 16 + lr;
        #pragma unroll
        for (int j = 0; j < 4; j++) {
            const int col = bn + warpN + j * 8 + (lc << 1);
            const float b0 = __ldg(&bias[col]);
            const float b1 = __ldg(&bias[col + 1]);
            float v0 = acc[i][j][0] + b0;
            float v1 = acc[i][j][1] + b1;
            float v2 = acc[i][j][2] + b0;
            float v3 = acc[i][j][3] + b1;
            if (gelu) {
                v0 = 0.5f * v0 * (1.0f + erff(v0 * 0.70710678118654752f));
                v1 = 0.5f * v1 * (1.0f + erff(v1 * 0.70710678118654752f));
                v2 = 0.5f * v2 * (1.0f + erff(v2 * 0.70710678118654752f));
                v3 = 0.5f * v3 * (1.0f + erff(v3 * 0.70710678118654752f));
            }
            if (residual) {
                v0 += residual[(size_t)row0 * Nc + col];
                v1 += residual[(size_t)row0 * Nc + col + 1];
                v2 += residual[(size_t)(row0 + 8) * Nc + col];
                v3 += residual[(size_t)(row0 + 8) * Nc + col + 1];
            }
            if (out_half) {
                __half* oh = (__half*)outp;
                *(uint32_t*)(oh + (size_t)row0 * Nc + col)       = h2u(__floats2half2_rn(v0, v1));
                *(uint32_t*)(oh + (size_t)(row0 + 8) * Nc + col) = h2u(__floats2half2_rn(v2, v3));
            } else {
                float* of = (float*)outp;
                *(float2*)(of + (size_t)row0 * Nc + col)       = make_float2(v0, v1);
                *(float2*)(of + (size_t)(row0 + 8) * Nc + col) = make_float2(v2, v3);
            }
        }
    }
}

// ---------------------------------------------------------------------------
// Vectorized RoPE: thread handles the (d, d+32) pair x 8 lanes; grid.z picks
// q or k. uint4 half loads/stores, float4 cos/sin.
// ---------------------------------------------------------------------------
__global__ void __launch_bounds__(256) rope2_kernel(
    __half* __restrict__ qp, __half* __restrict__ kp,
    const float* __restrict__ cosb, const float* __restrict__ sinb)
{
    __half* t = blockIdx.z ? kp : qp;
    int idx = blockIdx.x * 256 + threadIdx.x;   // over B*N*H*4
    const int ci = idx & 3; idx >>= 2;          // chunk 0..3 -> c = 8*ci (d<32)
    const int h = idx & (Hh - 1); idx >>= 4;
    const int n = idx & (Nn_ - 1); idx >>= 11;
    const int b = idx;
    const int c = ci * 8;
    const size_t base = ((size_t)(b * Nn_ + n)) * Cdim + h * Dd;

    uint4 lo = *(uint4*)(t + base + c);
    uint4 hi = *(uint4*)(t + base + c + 32);
    const __half* xl = (const __half*)&lo;
    const __half* xh = (const __half*)&hi;

    const float* cb = cosb + n * Dd;
    const float* sb = sinb + n * Dd;
    float cl[8], sl[8], ch[8], sh[8];
    *(float4*)&cl[0] = *(const float4*)(cb + c);
    *(float4*)&cl[4] = *(const float4*)(cb + c + 4);
    *(float4*)&ch[0] = *(const float4*)(cb + c + 32);
    *(float4*)&ch[4] = *(const float4*)(cb + c + 36);
    *(float4*)&sl[0] = *(const float4*)(sb + c);
    *(float4*)&sl[4] = *(const float4*)(sb + c + 4);
    *(float4*)&sh[0] = *(const float4*)(sb + c + 32);
    *(float4*)&sh[4] = *(const float4*)(sb + c + 36);

    uint4 olo, ohi;
    __half* ol = (__half*)&olo;
    __half* oh = (__half*)&ohi;
    #pragma unroll
    for (int j = 0; j < 8; j++) {
        const float x1 = __half2float(xl[j]);
        const float x2 = __half2float(xh[j]);
        ol[j] = __float2half_rn(x1 * cl[j] - x2 * sl[j]);
        oh[j] = __float2half_rn(x2 * ch[j] + x1 * sh[j]);
    }
    *(uint4*)(t + base + c)      = olo;
    *(uint4*)(t + base + c + 32) = ohi;
}

// ---------------------------------------------------------------------------
// Flash attention, fp16 mma (fp32 accum). Q tile 128, KV tile 64, D=64.
// Q fragments hoisted; P kept in registers (C-fragment == A-fragment layout);
// V transposed in smem for the PV B operand.
// smem (halves): Qs[128][72], Ks[64][72], Vt[64][72]
// ---------------------------------------------------------------------------
#define QSH 72
#define F_QS 0
#define F_KS (128 * QSH)
#define F_VS (F_KS + 64 * QSH)
#define FLASH_SMEM ((F_VS + 64 * QSH) * 2)

__global__ void __launch_bounds__(256) flash_kernel(
    const __half* __restrict__ q, const __half* __restrict__ k,
    const __half* __restrict__ v, __half* __restrict__ out)
{
    extern __shared__ __half smf[];
    __half* Qs = smf + F_QS;
    __half* Ks = smf + F_KS;
    __half* Vt = smf + F_VS;

    const int tid  = threadIdx.x;
    const int wid  = tid >> 5;
    const int lane = tid & 31;
    const int lr   = lane >> 2;
    const int lc   = lane & 3;
    const int rm   = wid * 16;

    const int bh = blockIdx.y;
    const int b = bh >> 4;
    const int h = bh & 15;
    const int q0 = blockIdx.x * 128;
    const float qscale = 0.125f * 1.4426950408889634f;  // D^-1/2 * log2(e)

    // Q tile: scale while loading
    const __half* qb = q + ((size_t)(b * Nn_ + q0)) * Cdim + h * Dd;
    #pragma unroll
    for (int i = 0; i < 4; i++) {
        const int idx = tid + i * 256;
        const int r = idx >> 3;
        const int c = (idx & 7) * 8;
        uint4 u = *(const uint4*)(qb + (size_t)r * Cdim + c);
        __half2* hp = (__half2*)&u;
        #pragma unroll
        for (int j = 0; j < 4; j++) {
            float2 f = __half22float2(hp[j]);
            hp[j] = __floats2half2_rn(f.x * qscale, f.y * qscale);
        }
        *(uint4*)&Qs[r * QSH + c] = u;
    }
    __syncthreads();

    // hoist Q fragments (Qs never read again)
    uint32_t qf[4][4];
    #pragma unroll
    for (int ks = 0; ks < 4; ks++) {
        const int kk = ks * 16;
        qf[ks][0] = *(const uint32_t*)&Qs[(rm + lr) * QSH + kk + 2 * lc];
        qf[ks][1] = *(const uint32_t*)&Qs[(rm + lr + 8) * QSH + kk + 2 * lc];
        qf[ks][2] = *(const uint32_t*)&Qs[(rm + lr) * QSH + kk + 2 * lc + 8];
        qf[ks][3] = *(const uint32_t*)&Qs[(rm + lr + 8) * QSH + kk + 2 * lc + 8];
    }

    // staging for K/V (64 x 64 halves = 512 chunks, 2 per thread)
    int srow[2], scol[2];
    #pragma unroll
    for (int i = 0; i < 2; i++) {
        const int idx = tid + i * 256;
        srow[i] = idx >> 3;
        scol[i] = (idx & 7) * 8;
    }
    const __half* kb0 = k + ((size_t)(b * Nn_)) * Cdim + h * Dd;
    const __half* vb0 = v + ((size_t)(b * Nn_)) * Cdim + h * Dd;

    uint4 kreg[2], vreg[2];
    #pragma unroll
    for (int i = 0; i < 2; i++) {
        kreg[i] = *(const uint4*)(kb0 + (size_t)srow[i] * Cdim + scol[i]);
        vreg[i] = *(const uint4*)(vb0 + (size_t)srow[i] * Cdim + scol[i]);
    }

    float m0 = -1e30f, m1 = -1e30f, l0 = 0.f, l1 = 0.f;
    float oacc[8][4];
    #pragma unroll
    for (int nt = 0; nt < 8; nt++)
        #pragma unroll
        for (int r = 0; r < 4; r++) oacc[nt][r] = 0.f;

    for (int kv0 = 0; kv0 < Nn_; kv0 += 64) {
        __syncthreads();
        #pragma unroll
        for (int i = 0; i < 2; i++) {
            *(uint4*)&Ks[srow[i] * QSH + scol[i]] = kreg[i];
            const __half* vh = (const __half*)&vreg[i];
            #pragma unroll
            for (int j = 0; j < 8; j++)
                Vt[(scol[i] + j) * QSH + srow[i]] = vh[j];   // transpose
        }
        __syncthreads();

        if (kv0 + 64 < Nn_) {
            const __half* kb = kb0 + (size_t)(kv0 + 64) * Cdim;
            const __half* vb = vb0 + (size_t)(kv0 + 64) * Cdim;
            #pragma unroll
            for (int i = 0; i < 2; i++) {
                kreg[i] = *(const uint4*)(kb + (size_t)srow[i] * Cdim + scol[i]);
                vreg[i] = *(const uint4*)(vb + (size_t)srow[i] * Cdim + scol[i]);
            }
        }

        // S = Qs @ Ks^T  (4 k16 steps over D=64)
        float sacc[8][4];
        #pragma unroll
        for (int nt = 0; nt < 8; nt++)
            #pragma unroll
            for (int r = 0; r < 4; r++) sacc[nt][r] = 0.f;
        #pragma unroll
        for (int ks = 0; ks < 4; ks++) {
            const int kk = ks * 16;
            #pragma unroll
            for (int nt = 0; nt < 8; nt++) {
                uint32_t bf[2];
                bf[0] = *(const uint32_t*)&Ks[(nt * 8 + lr) * QSH + kk + 2 * lc];
                bf[1] = *(const uint32_t*)&Ks[(nt * 8 + lr) * QSH + kk + 2 * lc + 8];
                MMA_F16(sacc[nt], qf[ks], bf);
            }
        }

        // online softmax; produce P directly as half2 A-fragments pf[4][4]
        float mx0 = -1e30f, mx1 = -1e30f;
        #pragma unroll
        for (int nt = 0; nt < 8; nt++) {
            mx0 = fmaxf(mx0, fmaxf(sacc[nt][0], sacc[nt][1]));
            mx1 = fmaxf(mx1, fmaxf(sacc[nt][2], sacc[nt][3]));
        }
        #pragma unroll
        for (int o = 1; o < 4; o <<= 1) {
            mx0 = fmaxf(mx0, __shfl_xor_sync(0xffffffffu, mx0, o, 4));
            mx1 = fmaxf(mx1, __shfl_xor_sync(0xffffffffu, mx1, o, 4));
        }
        const float mn0 = fmaxf(m0, mx0);
        const float mn1 = fmaxf(m1, mx1);
        const float al0 = exp2f(m0 - mn0);
        const float al1 = exp2f(m1 - mn1);
        float rs0 = 0.f, rs1 = 0.f;
        uint32_t pf[4][4];
        #pragma unroll
        for (int ks = 0; ks < 4; ks++) {
            // nt = 2*ks (k low 8) and 2*ks+1 (k high 8)
            const int ntA = 2 * ks, ntB = 2 * ks + 1;
            __half2 a0 = __floats2half2_rn(exp2f(sacc[ntA][0] - mn0),
                                           exp2f(sacc[ntA][1] - mn0));
            __half2 a1 = __floats2half2_rn(exp2f(sacc[ntA][2] - mn1),
                                           exp2f(sacc[ntA][3] - mn1));
            __half2 a2 = __floats2half2_rn(exp2f(sacc[ntB][0] - mn0),
                                           exp2f(sacc[ntB][1] - mn0));
            __half2 a3 = __floats2half2_rn(exp2f(sacc[ntB][2] - mn1),
                                           exp2f(sacc[ntB][3] - mn1));
            pf[ks][0] = h2u(a0); pf[ks][1] = h2u(a1);
            pf[ks][2] = h2u(a2); pf[ks][3] = h2u(a3);
            const float2 f0 = __half22float2(a0);
            const float2 f1 = __half22float2(a1);
            const float2 f2 = __half22float2(a2);
            const float2 f3 = __half22float2(a3);
            rs0 += f0.x + f0.y + f2.x + f2.y;
            rs1 += f1.x + f1.y + f3.x + f3.y;
        }
        #pragma unroll
        for (int o = 1; o < 4; o <<= 1) {
            rs0 += __shfl_xor_sync(0xffffffffu, rs0, o, 4);
            rs1 += __shfl_xor_sync(0xffffffffu, rs1, o, 4);
        }
        l0 = l0 * al0 + rs0;  m0 = mn0;
        l1 = l1 * al1 + rs1;  m1 = mn1;
        #pragma unroll
        for (int nt = 0; nt < 8; nt++) {
            oacc[nt][0] *= al0; oacc[nt][1] *= al0;
            oacc[nt][2] *= al1; oacc[nt][3] *= al1;
        }

        // O += P @ Vt (4 k16 steps over kv=64)
        #pragma unroll
        for (int ks = 0; ks < 4; ks++) {
            const int kk = ks * 16;
            #pragma unroll
            for (int nt = 0; nt < 8; nt++) {
                uint32_t bf[2];
                bf[0] = *(const uint32_t*)&Vt[(nt * 8 + lr) * QSH + kk + 2 * lc];
                bf[1] = *(const uint32_t*)&Vt[(nt * 8 + lr) * QSH + kk + 2 * lc + 8];
                MMA_F16(oacc[nt], pf[ks], bf);
            }
        }
    }

    // write O (half: A operand of Wo GEMM)
    const float il0 = 1.0f / l0;
    const float il1 = 1.0f / l1;
    __half* ob = out + ((size_t)(b * Nn_ + q0 + rm)) * Cdim + h * Dd;
    #pragma unroll
    for (int nt = 0; nt < 8; nt++) {
        const int col = nt * 8 + 2 * lc;
        *(uint32_t*)(ob + (size_t)lr * Cdim + col) =
            h2u(__floats2half2_rn(oacc[nt][0] * il0, oacc[nt][1] * il0));
        *(uint32_t*)(ob + (size_t)(lr + 8) * Cdim + col) =
            h2u(__floats2half2_rn(oacc[nt][2] * il1, oacc[nt][3] * il1));
    }
}

// ---------------------------------------------------------------------------
extern "C" void kernel_launch(void* const* d_in, const int* in_sizes, int n_in,
                              void* d_out, int out_size)
{
    const float* x    = (const float*)d_in[0];
    const float* rcos = (const float*)d_in[1];
    const float* rsin = (const float*)d_in[2];
    const float* g1   = (const float*)d_in[3];
    const float* be1  = (const float*)d_in[4];
    const float* Wq   = (const float*)d_in[5];
    const float* bq   = (const float*)d_in[6];
    const float* Wk   = (const float*)d_in[7];
    const float* bk   = (const float*)d_in[8];
    const float* Wv   = (const float*)d_in[9];
    const float* bv   = (const float*)d_in[10];
    const float* Wo   = (const float*)d_in[11];
    const float* bo   = (const float*)d_in[12];
    const float* g2   = (const float*)d_in[13];
    const float* be2  = (const float*)d_in[14];
    const float* W1   = (const float*)d_in[15];
    const float* b1   = (const float*)d_in[16];
    const float* W2   = (const float*)d_in[17];
    const float* b2   = (const float*)d_in[18];
    float* out = (float*)d_out;

    unsigned char* base = nullptr;
    cudaGetSymbolAddress((void**)&base, g_scratch);
    __half* p_h   = (__half*)(base + OFF_H);
    __half* p_q   = (__half*)(base + OFF_Q);
    __half* p_k   = (__half*)(base + OFF_K);
    __half* p_v   = (__half*)(base + OFF_V);
    __half* p_att = (__half*)(base + OFF_ATT);
    __half* p_mlp = (__half*)(base + OFF_MLP);
    float*  p_x2  = (float*)(base + OFF_X2);
    __half* p_wq  = (__half*)(base + OFF_WQ);
    __half* p_wk  = (__half*)(base + OFF_WK);
    __half* p_wv  = (__half*)(base + OFF_WV);
    __half* p_wo  = (__half*)(base + OFF_WO);
    __half* p_w1  = (__half*)(base + OFF_W1);
    __half* p_w2  = (__half*)(base + OFF_W2);

    cudaFuncSetAttribute(flash_kernel,
                         cudaFuncAttributeMaxDynamicSharedMemorySize, FLASH_SMEM);
    cudaFuncSetAttribute(hgemm_kernel,
                         cudaFuncAttributeMaxDynamicSharedMemorySize, GEMM_SMEM);

    // 0. weights -> fp16 (one launch)
    const int nC4 = (Cdim * Cdim) / 4;
    const int nF4 = (Cdim * Fdim) / 4;
    ConvSet cs;
    cs.in[0] = (const float4*)Wq; cs.out[0] = (__half2*)p_wq; cs.n4[0] = nC4;
    cs.in[1] = (const float4*)Wk; cs.out[1] = (__half2*)p_wk; cs.n4[1] = nC4;
    cs.in[2] = (const float4*)Wv; cs.out[2] = (__half2*)p_wv; cs.n4[2] = nC4;
    cs.in[3] = (const float4*)Wo; cs.out[3] = (__half2*)p_wo; cs.n4[3] = nC4;
    cs.in[4] = (const float4*)W1; cs.out[4] = (__half2*)p_w1; cs.n4[4] = nF4;
    cs.in[5] = (const float4*)W2; cs.out[5] = (__half2*)p_w2; cs.n4[5] = nF4;
    conv_half_kernel<<<dim3(512, 1, 6), 256>>>(cs);

    // 1. LN1 -> half
    ln_kernel<<<Mrows, 256>>>(x, g1, be1, p_h);

    // 2. fused QKV projections -> half
    GemmSet qkv;
    qkv.W[0] = p_wq; qkv.W[1] = p_wk; qkv.W[2] = p_wv;
    qkv.bias[0] = bq; qkv.bias[1] = bk; qkv.bias[2] = bv;
    qkv.out[0] = p_q; qkv.out[1] = p_k; qkv.out[2] = p_v;
    hgemm_kernel<<<dim3(Cdim / 128, Mrows / 128, 3), 256, GEMM_SMEM>>>(
        p_h, qkv, nullptr, Mrows, Cdim, Cdim, 0, 1);

    // 3. RoPE on q and k, one vectorized launch
    rope2_kernel<<<dim3((Bb * Nn_ * Hh * 4) / 256, 1, 2), 256>>>(p_q, p_k, rcos, rsin);

    // 4. attention -> half
    flash_kernel<<<dim3(Nn_ / 128, Bb * Hh), 256, FLASH_SMEM>>>(p_q, p_k, p_v, p_att);

    // 5. output projection + fp32 residual -> fp32 x2
    GemmSet so;
    so.W[0] = p_wo; so.bias[0] = bo; so.out[0] = p_x2;
    so.W[1] = so.W[2] = nullptr; so.bias[1] = so.bias[2] = nullptr;
    so.out[1] = so.out[2] = nullptr;
    hgemm_kernel<<<dim3(Cdim / 128, Mrows / 128, 1), 256, GEMM_SMEM>>>(
        p_att, so, x, Mrows, Cdim, Cdim, 0, 0);

    // 6. LN2 -> half
    ln_kernel<<<Mrows, 256>>>(p_x2, g2, be2, p_h);

    // 7. MLP up + GELU -> half
    GemmSet s1;
    s1.W[0] = p_w1; s1.bias[0] = b1; s1.out[0] = p_mlp;
    s1.W[1] = s1.W[2] = nullptr; s1.bias[1] = s1.bias[2] = nullptr;
    s1.out[1] = s1.out[2] = nullptr;
    hgemm_kernel<<<dim3(Fdim / 128, Mrows / 128, 1), 256, GEMM_SMEM>>>(
        p_h, s1, nullptr, Mrows, Fdim, Cdim, 1, 1);

    // 8. MLP down + fp32 residual -> fp32 output
    GemmSet s2;
    s2.W[0] = p_w2; s2.bias[0] = b2; s2.out[0] = out;
    s2.W[1] = s2.W[2] = nullptr; s2.bias[1] = s2.bias[2] = nullptr;
    s2.out[1] = s2.out[2] = nullptr;
    hgemm_kernel<<<dim3(Cdim / 128, Mrows / 128, 1), 256, GEMM_SMEM>>>(
        p_mlp, s2, p_x2, Mrows, Cdim, Fdim, 0, 0);
}

// round 12
// speedup vs baseline: 1.7252x; 1.0169x over previous
#include <cuda_runtime.h>
#include <cuda_fp16.h>
#include <stdint.h>
#include <math.h>

// ---------------------------------------------------------------------------
// DiT block. Round 12: hgemm warp tile 64x64 (128 B/MMA fragment traffic,
// smem-BW balanced), 4 warps / 128 threads per CTA, 2 CTA/SM.
// Flash/LN/RoPE/conv unchanged from R11.
//   B=2, N=2048, C=1024, H=16, D=64, F=4096, M=B*N=4096
// ---------------------------------------------------------------------------

#define Mrows 4096
#define Cdim  1024
#define Fdim  4096
#define Bb    2
#define Hh    16
#define Dd    64
#define Nn_   2048

// byte offsets into scratch
#define OFF_H   ((size_t)0)
#define OFF_Q   ((size_t)8388608)
#define OFF_K   ((size_t)16777216)
#define OFF_V   ((size_t)25165824)
#define OFF_ATT ((size_t)33554432)
#define OFF_MLP ((size_t)41943040)
#define OFF_X2  ((size_t)75497472)
#define OFF_WQ  ((size_t)92274688)
#define OFF_WK  ((size_t)94371840)
#define OFF_WV  ((size_t)96468992)
#define OFF_WO  ((size_t)98566144)
#define OFF_W1  ((size_t)100663296)
#define OFF_W2  ((size_t)109051904)
__device__ __align__(1024) unsigned char g_scratch[117440512];

__device__ __forceinline__ uint32_t h2u(__half2 h) {
    return *reinterpret_cast<uint32_t*>(&h);
}

#define MMA_F16(d, a, b)                                                      \
    asm volatile(                                                             \
        "mma.sync.aligned.m16n8k16.row.col.f32.f16.f16.f32 "                  \
        "{%0,%1,%2,%3}, {%4,%5,%6,%7}, {%8,%9}, {%0,%1,%2,%3};"               \
        : "+f"(d[0]), "+f"(d[1]), "+f"(d[2]), "+f"(d[3])                      \
        : "r"(a[0]), "r"(a[1]), "r"(a[2]), "r"(a[3]), "r"(b[0]), "r"(b[1]))

#define CP_ASYNC16(dst_u32, src_ptr)                                          \
    asm volatile("cp.async.cg.shared.global [%0], [%1], 16;"                  \
                 :: "r"(dst_u32), "l"(src_ptr))
#define CP_COMMIT()  asm volatile("cp.async.commit_group;")
#define CP_WAIT(n)   asm volatile("cp.async.wait_group %0;" :: "n"(n))

// ---------------------------------------------------------------------------
// Weight conversion fp32 -> fp16 (RN), 6 arrays in one launch.
// ---------------------------------------------------------------------------
struct ConvSet {
    const float4* in[6];
    __half2*      out[6];
    int           n4[6];
};

__global__ void __launch_bounds__(256) conv_half_kernel(ConvSet cs)
{
    const int z = blockIdx.z;
    const float4* __restrict__ in = cs.in[z];
    __half2* __restrict__ out = cs.out[z];
    const int n4 = cs.n4[z];
    const int stride = gridDim.x * 256;
    for (int i = blockIdx.x * 256 + threadIdx.x; i < n4; i += stride) {
        const float4 v = in[i];
        __half2 h01 = __floats2half2_rn(v.x, v.y);
        __half2 h23 = __floats2half2_rn(v.z, v.w);
        uint2 u; u.x = h2u(h01); u.y = h2u(h23);
        *(uint2*)&out[2 * i] = u;
    }
}

// ---------------------------------------------------------------------------
// LayerNorm: one block (256 thr) per row of 1024. fp32 in, fp16 out.
// ---------------------------------------------------------------------------
__global__ void __launch_bounds__(256) ln_kernel(
    const float* __restrict__ x, const float* __restrict__ g,
    const float* __restrict__ b, __half* __restrict__ out)
{
    __shared__ float red[16];
    const int row = blockIdx.x;
    const int t = threadIdx.x;
    const float4 xv = ((const float4*)(x + (size_t)row * Cdim))[t];
    float s  = xv.x + xv.y + xv.z + xv.w;
    float ss = xv.x*xv.x + xv.y*xv.y + xv.z*xv.z + xv.w*xv.w;
    #pragma unroll
    for (int o = 16; o > 0; o >>= 1) {
        s  += __shfl_xor_sync(0xffffffffu, s,  o);
        ss += __shfl_xor_sync(0xffffffffu, ss, o);
    }
    const int w = t >> 5;
    if ((t & 31) == 0) { red[w] = s; red[8 + w] = ss; }
    __syncthreads();
    float ts = 0.f, tss = 0.f;
    #pragma unroll
    for (int i = 0; i < 8; i++) { ts += red[i]; tss += red[8 + i]; }
    const float mean = ts * (1.0f / Cdim);
    const float var  = tss * (1.0f / Cdim) - mean * mean;
    const float inv  = rsqrtf(var + 1e-6f);
    const float4 gv = ((const float4*)g)[t];
    const float4 bv = ((const float4*)b)[t];
    __half2 h01 = __floats2half2_rn((xv.x - mean) * inv * gv.x + bv.x,
                                    (xv.y - mean) * inv * gv.y + bv.y);
    __half2 h23 = __floats2half2_rn((xv.z - mean) * inv * gv.z + bv.z,
                                    (xv.w - mean) * inv * gv.w + bv.w);
    uint2 u; u.x = h2u(h01); u.y = h2u(h23);
    *(uint2*)(out + (size_t)row * Cdim + 4 * t) = u;
}

// ---------------------------------------------------------------------------
// fp16 GEMM, 3-stage cp.async, 128x128 CTA tile, BK=32.
// 128 threads = 4 warps (2M x 2N), warp tile 64x64.
// Fragment traffic: 128 B/MMA (A frag reused over 8 n-tiles, B over 4 m-tiles).
// ---------------------------------------------------------------------------
#define GSH 40
#define TBUFH (128 * GSH)
#define BOFFH (3 * TBUFH)
#define GEMM_SMEM (6 * TBUFH * 2)

struct GemmSet {
    const __half* W[3];
    const float*  bias[3];
    void*         out[3];
};

__global__ void __launch_bounds__(128, 2) hgemm_kernel(
    const __half* __restrict__ A, GemmSet gs, const float* __restrict__ residual,
    int M, int Nc, int K, int gelu, int out_half)
{
    extern __shared__ __half smh[];
    const uint32_t sbase = (uint32_t)__cvta_generic_to_shared(smh);

    const int z = blockIdx.z;
    const __half* __restrict__ Wp  = gs.W[z];
    const float* __restrict__ bias = gs.bias[z];
    void* __restrict__ outp        = gs.out[z];

    const int tid  = threadIdx.x;
    const int wid  = tid >> 5;
    const int lane = tid & 31;
    const int lr   = lane >> 2;
    const int lc   = lane & 3;
    const int warpM = (wid & 1) * 64;
    const int warpN = (wid >> 1) * 64;
    const int bm = blockIdx.y * 128, bn = blockIdx.x * 128;

    float acc[4][8][4];
    #pragma unroll
    for (int i = 0; i < 4; i++)
        #pragma unroll
        for (int j = 0; j < 8; j++)
            #pragma unroll
            for (int r = 0; r < 4; r++) acc[i][j][r] = 0.f;

    const int nk = K >> 5;

    // A tile: 128 rows x 32 halves = 512 chunks of 16B; B same. 128 threads
    // -> 4 chunks each per tile.
    #define LOAD_TILE(stg, k0)                                                \
    do {                                                                      \
        _Pragma("unroll")                                                     \
        for (int p = 0; p < 4; p++) {                                         \
            const int id = tid + p * 128;                                     \
            const int row = id >> 2;                                          \
            const int kc = id & 3;                                            \
            const uint32_t da = sbase + (uint32_t)(((stg) * TBUFH + row * GSH + kc * 8) * 2); \
            CP_ASYNC16(da, A + (size_t)(bm + row) * K + (k0) + kc * 8);       \
        }                                                                     \
        _Pragma("unroll")                                                     \
        for (int p = 0; p < 4; p++) {                                         \
            const int id = tid + p * 128;                                     \
            const int row = id >> 2;                                          \
            const int kc = id & 3;                                            \
            const uint32_t db = sbase + (uint32_t)((BOFFH + (stg) * TBUFH + row * GSH + kc * 8) * 2); \
            CP_ASYNC16(db, Wp + (size_t)(bn + row) * K + (k0) + kc * 8);      \
        }                                                                     \
    } while (0)

    LOAD_TILE(0, 0);
    CP_COMMIT();
    if (nk > 1) { LOAD_TILE(1, 32); }
    CP_COMMIT();

    int stg = 0;
    for (int kt = 0; kt < nk; kt++) {
        if (kt + 1 < nk) { CP_WAIT(1); } else { CP_WAIT(0); }
        __syncthreads();

        if (kt + 2 < nk) {
            const int ns = (stg + 2 >= 3) ? stg - 1 : stg + 2;
            LOAD_TILE(ns, (kt + 2) << 5);
            CP_COMMIT();
        }

        const __half* Asm = smh + stg * TBUFH;
        const __half* Bsm = smh + BOFFH + stg * TBUFH;
        #pragma unroll
        for (int ks = 0; ks < 2; ks++) {
            const int kk = ks * 16;
            uint32_t af[4][4], bf[8][2];
            #pragma unroll
            for (int i = 0; i < 4; i++) {
                const int rb = warpM + i * 16;
                af[i][0] = *(const uint32_t*)&Asm[(rb + lr) * GSH + kk + 2 * lc];
                af[i][1] = *(const uint32_t*)&Asm[(rb + lr + 8) * GSH + kk + 2 * lc];
                af[i][2] = *(const uint32_t*)&Asm[(rb + lr) * GSH + kk + 2 * lc + 8];
                af[i][3] = *(const uint32_t*)&Asm[(rb + lr + 8) * GSH + kk + 2 * lc + 8];
            }
            #pragma unroll
            for (int j = 0; j < 8; j++) {
                const int cb = warpN + j * 8;
                bf[j][0] = *(const uint32_t*)&Bsm[(cb + lr) * GSH + kk + 2 * lc];
                bf[j][1] = *(const uint32_t*)&Bsm[(cb + lr) * GSH + kk + 2 * lc + 8];
            }
            #pragma unroll
            for (int i = 0; i < 4; i++)
                #pragma unroll
                for (int j = 0; j < 8; j++)
                    MMA_F16(acc[i][j], af[i], bf[j]);
        }
        stg = (stg + 1 >= 3) ? 0 : stg + 1;
    }

    #pragma unroll
    for (int i = 0; i < 4; i++) {
        const int row0 = bm + warpM + i * 16 + lr;
        #pragma unroll
        for (int j = 0; j < 8; j++) {
            const int col = bn + warpN + j * 8 + (lc << 1);
            const float b0 = __ldg(&bias[col]);
            const float b1 = __ldg(&bias[col + 1]);
            float v0 = acc[i][j][0] + b0;
            float v1 = acc[i][j][1] + b1;
            float v2 = acc[i][j][2] + b0;
            float v3 = acc[i][j][3] + b1;
            if (gelu) {
                v0 = 0.5f * v0 * (1.0f + erff(v0 * 0.70710678118654752f));
                v1 = 0.5f * v1 * (1.0f + erff(v1 * 0.70710678118654752f));
                v2 = 0.5f * v2 * (1.0f + erff(v2 * 0.70710678118654752f));
                v3 = 0.5f * v3 * (1.0f + erff(v3 * 0.70710678118654752f));
            }
            if (residual) {
                v0 += residual[(size_t)row0 * Nc + col];
                v1 += residual[(size_t)row0 * Nc + col + 1];
                v2 += residual[(size_t)(row0 + 8) * Nc + col];
                v3 += residual[(size_t)(row0 + 8) * Nc + col + 1];
            }
            if (out_half) {
                __half* oh = (__half*)outp;
                *(uint32_t*)(oh + (size_t)row0 * Nc + col)       = h2u(__floats2half2_rn(v0, v1));
                *(uint32_t*)(oh + (size_t)(row0 + 8) * Nc + col) = h2u(__floats2half2_rn(v2, v3));
            } else {
                float* of = (float*)outp;
                *(float2*)(of + (size_t)row0 * Nc + col)       = make_float2(v0, v1);
                *(float2*)(of + (size_t)(row0 + 8) * Nc + col) = make_float2(v2, v3);
            }
        }
    }
}

// ---------------------------------------------------------------------------
// Vectorized RoPE (unchanged from R11)
// ---------------------------------------------------------------------------
__global__ void __launch_bounds__(256) rope2_kernel(
    __half* __restrict__ qp, __half* __restrict__ kp,
    const float* __restrict__ cosb, const float* __restrict__ sinb)
{
    __half* t = blockIdx.z ? kp : qp;
    int idx = blockIdx.x * 256 + threadIdx.x;
    const int ci = idx & 3; idx >>= 2;
    const int h = idx & (Hh - 1); idx >>= 4;
    const int n = idx & (Nn_ - 1); idx >>= 11;
    const int b = idx;
    const int c = ci * 8;
    const size_t base = ((size_t)(b * Nn_ + n)) * Cdim + h * Dd;

    uint4 lo = *(uint4*)(t + base + c);
    uint4 hi = *(uint4*)(t + base + c + 32);
    const __half* xl = (const __half*)&lo;
    const __half* xh = (const __half*)&hi;

    const float* cb = cosb + n * Dd;
    const float* sb = sinb + n * Dd;
    float cl[8], sl[8], ch[8], sh[8];
    *(float4*)&cl[0] = *(const float4*)(cb + c);
    *(float4*)&cl[4] = *(const float4*)(cb + c + 4);
    *(float4*)&ch[0] = *(const float4*)(cb + c + 32);
    *(float4*)&ch[4] = *(const float4*)(cb + c + 36);
    *(float4*)&sl[0] = *(const float4*)(sb + c);
    *(float4*)&sl[4] = *(const float4*)(sb + c + 4);
    *(float4*)&sh[0] = *(const float4*)(sb + c + 32);
    *(float4*)&sh[4] = *(const float4*)(sb + c + 36);

    uint4 olo, ohi;
    __half* ol = (__half*)&olo;
    __half* oh = (__half*)&ohi;
    #pragma unroll
    for (int j = 0; j < 8; j++) {
        const float x1 = __half2float(xl[j]);
        const float x2 = __half2float(xh[j]);
        ol[j] = __float2half_rn(x1 * cl[j] - x2 * sl[j]);
        oh[j] = __float2half_rn(x2 * ch[j] + x1 * sh[j]);
    }
    *(uint4*)(t + base + c)      = olo;
    *(uint4*)(t + base + c + 32) = ohi;
}

// ---------------------------------------------------------------------------
// Flash attention (unchanged from R11): fp16 mma, P in registers.
// ---------------------------------------------------------------------------
#define QSH 72
#define F_QS 0
#define F_KS (128 * QSH)
#define F_VS (F_KS + 64 * QSH)
#define FLASH_SMEM ((F_VS + 64 * QSH) * 2)

__global__ void __launch_bounds__(256) flash_kernel(
    const __half* __restrict__ q, const __half* __restrict__ k,
    const __half* __restrict__ v, __half* __restrict__ out)
{
    extern __shared__ __half smf[];
    __half* Qs = smf + F_QS;
    __half* Ks = smf + F_KS;
    __half* Vt = smf + F_VS;

    const int tid  = threadIdx.x;
    const int wid  = tid >> 5;
    const int lane = tid & 31;
    const int lr   = lane >> 2;
    const int lc   = lane & 3;
    const int rm   = wid * 16;

    const int bh = blockIdx.y;
    const int b = bh >> 4;
    const int h = bh & 15;
    const int q0 = blockIdx.x * 128;
    const float qscale = 0.125f * 1.4426950408889634f;

    const __half* qb = q + ((size_t)(b * Nn_ + q0)) * Cdim + h * Dd;
    #pragma unroll
    for (int i = 0; i < 4; i++) {
        const int idx = tid + i * 256;
        const int r = idx >> 3;
        const int c = (idx & 7) * 8;
        uint4 u = *(const uint4*)(qb + (size_t)r * Cdim + c);
        __half2* hp = (__half2*)&u;
        #pragma unroll
        for (int j = 0; j < 4; j++) {
            float2 f = __half22float2(hp[j]);
            hp[j] = __floats2half2_rn(f.x * qscale, f.y * qscale);
        }
        *(uint4*)&Qs[r * QSH + c] = u;
    }
    __syncthreads();

    uint32_t qf[4][4];
    #pragma unroll
    for (int ks = 0; ks < 4; ks++) {
        const int kk = ks * 16;
        qf[ks][0] = *(const uint32_t*)&Qs[(rm + lr) * QSH + kk + 2 * lc];
        qf[ks][1] = *(const uint32_t*)&Qs[(rm + lr + 8) * QSH + kk + 2 * lc];
        qf[ks][2] = *(const uint32_t*)&Qs[(rm + lr) * QSH + kk + 2 * lc + 8];
        qf[ks][3] = *(const uint32_t*)&Qs[(rm + lr + 8) * QSH + kk + 2 * lc + 8];
    }

    int srow[2], scol[2];
    #pragma unroll
    for (int i = 0; i < 2; i++) {
        const int idx = tid + i * 256;
        srow[i] = idx >> 3;
        scol[i] = (idx & 7) * 8;
    }
    const __half* kb0 = k + ((size_t)(b * Nn_)) * Cdim + h * Dd;
    const __half* vb0 = v + ((size_t)(b * Nn_)) * Cdim + h * Dd;

    uint4 kreg[2], vreg[2];
    #pragma unroll
    for (int i = 0; i < 2; i++) {
        kreg[i] = *(const uint4*)(kb0 + (size_t)srow[i] * Cdim + scol[i]);
        vreg[i] = *(const uint4*)(vb0 + (size_t)srow[i] * Cdim + scol[i]);
    }

    float m0 = -1e30f, m1 = -1e30f, l0 = 0.f, l1 = 0.f;
    float oacc[8][4];
    #pragma unroll
    for (int nt = 0; nt < 8; nt++)
        #pragma unroll
        for (int r = 0; r < 4; r++) oacc[nt][r] = 0.f;

    for (int kv0 = 0; kv0 < Nn_; kv0 += 64) {
        __syncthreads();
        #pragma unroll
        for (int i = 0; i < 2; i++) {
            *(uint4*)&Ks[srow[i] * QSH + scol[i]] = kreg[i];
            const __half* vh = (const __half*)&vreg[i];
            #pragma unroll
            for (int j = 0; j < 8; j++)
                Vt[(scol[i] + j) * QSH + srow[i]] = vh[j];
        }
        __syncthreads();

        if (kv0 + 64 < Nn_) {
            const __half* kb = kb0 + (size_t)(kv0 + 64) * Cdim;
            const __half* vb = vb0 + (size_t)(kv0 + 64) * Cdim;
            #pragma unroll
            for (int i = 0; i < 2; i++) {
                kreg[i] = *(const uint4*)(kb + (size_t)srow[i] * Cdim + scol[i]);
                vreg[i] = *(const uint4*)(vb + (size_t)srow[i] * Cdim + scol[i]);
            }
        }

        float sacc[8][4];
        #pragma unroll
        for (int nt = 0; nt < 8; nt++)
            #pragma unroll
            for (int r = 0; r < 4; r++) sacc[nt][r] = 0.f;
        #pragma unroll
        for (int ks = 0; ks < 4; ks++) {
            const int kk = ks * 16;
            #pragma unroll
            for (int nt = 0; nt < 8; nt++) {
                uint32_t bf[2];
                bf[0] = *(const uint32_t*)&Ks[(nt * 8 + lr) * QSH + kk + 2 * lc];
                bf[1] = *(const uint32_t*)&Ks[(nt * 8 + lr) * QSH + kk + 2 * lc + 8];
                MMA_F16(sacc[nt], qf[ks], bf);
            }
        }

        float mx0 = -1e30f, mx1 = -1e30f;
        #pragma unroll
        for (int nt = 0; nt < 8; nt++) {
            mx0 = fmaxf(mx0, fmaxf(sacc[nt][0], sacc[nt][1]));
            mx1 = fmaxf(mx1, fmaxf(sacc[nt][2], sacc[nt][3]));
        }
        #pragma unroll
        for (int o = 1; o < 4; o <<= 1) {
            mx0 = fmaxf(mx0, __shfl_xor_sync(0xffffffffu, mx0, o, 4));
            mx1 = fmaxf(mx1, __shfl_xor_sync(0xffffffffu, mx1, o, 4));
        }
        const float mn0 = fmaxf(m0, mx0);
        const float mn1 = fmaxf(m1, mx1);
        const float al0 = exp2f(m0 - mn0);
        const float al1 = exp2f(m1 - mn1);
        float rs0 = 0.f, rs1 = 0.f;
        uint32_t pf[4][4];
        #pragma unroll
        for (int ks = 0; ks < 4; ks++) {
            const int ntA = 2 * ks, ntB = 2 * ks + 1;
            __half2 a0 = __floats2half2_rn(exp2f(sacc[ntA][0] - mn0),
                                           exp2f(sacc[ntA][1] - mn0));
            __half2 a1 = __floats2half2_rn(exp2f(sacc[ntA][2] - mn1),
                                           exp2f(sacc[ntA][3] - mn1));
            __half2 a2 = __floats2half2_rn(exp2f(sacc[ntB][0] - mn0),
                                           exp2f(sacc[ntB][1] - mn0));
            __half2 a3 = __floats2half2_rn(exp2f(sacc[ntB][2] - mn1),
                                           exp2f(sacc[ntB][3] - mn1));
            pf[ks][0] = h2u(a0); pf[ks][1] = h2u(a1);
            pf[ks][2] = h2u(a2); pf[ks][3] = h2u(a3);
            const float2 f0 = __half22float2(a0);
            const float2 f1 = __half22float2(a1);
            const float2 f2 = __half22float2(a2);
            const float2 f3 = __half22float2(a3);
            rs0 += f0.x + f0.y + f2.x + f2.y;
            rs1 += f1.x + f1.y + f3.x + f3.y;
        }
        #pragma unroll
        for (int o = 1; o < 4; o <<= 1) {
            rs0 += __shfl_xor_sync(0xffffffffu, rs0, o, 4);
            rs1 += __shfl_xor_sync(0xffffffffu, rs1, o, 4);
        }
        l0 = l0 * al0 + rs0;  m0 = mn0;
        l1 = l1 * al1 + rs1;  m1 = mn1;
        #pragma unroll
        for (int nt = 0; nt < 8; nt++) {
            oacc[nt][0] *= al0; oacc[nt][1] *= al0;
            oacc[nt][2] *= al1; oacc[nt][3] *= al1;
        }

        #pragma unroll
        for (int ks = 0; ks < 4; ks++) {
            const int kk = ks * 16;
            #pragma unroll
            for (int nt = 0; nt < 8; nt++) {
                uint32_t bf[2];
                bf[0] = *(const uint32_t*)&Vt[(nt * 8 + lr) * QSH + kk + 2 * lc];
                bf[1] = *(const uint32_t*)&Vt[(nt * 8 + lr) * QSH + kk + 2 * lc + 8];
                MMA_F16(oacc[nt], pf[ks], bf);
            }
        }
    }

    const float il0 = 1.0f / l0;
    const float il1 = 1.0f / l1;
    __half* ob = out + ((size_t)(b * Nn_ + q0 + rm)) * Cdim + h * Dd;
    #pragma unroll
    for (int nt = 0; nt < 8; nt++) {
        const int col = nt * 8 + 2 * lc;
        *(uint32_t*)(ob + (size_t)lr * Cdim + col) =
            h2u(__floats2half2_rn(oacc[nt][0] * il0, oacc[nt][1] * il0));
        *(uint32_t*)(ob + (size_t)(lr + 8) * Cdim + col) =
            h2u(__floats2half2_rn(oacc[nt][2] * il1, oacc[nt][3] * il1));
    }
}

// ---------------------------------------------------------------------------
extern "C" void kernel_launch(void* const* d_in, const int* in_sizes, int n_in,
                              void* d_out, int out_size)
{
    const float* x    = (const float*)d_in[0];
    const float* rcos = (const float*)d_in[1];
    const float* rsin = (const float*)d_in[2];
    const float* g1   = (const float*)d_in[3];
    const float* be1  = (const float*)d_in[4];
    const float* Wq   = (const float*)d_in[5];
    const float* bq   = (const float*)d_in[6];
    const float* Wk   = (const float*)d_in[7];
    const float* bk   = (const float*)d_in[8];
    const float* Wv   = (const float*)d_in[9];
    const float* bv   = (const float*)d_in[10];
    const float* Wo   = (const float*)d_in[11];
    const float* bo   = (const float*)d_in[12];
    const float* g2   = (const float*)d_in[13];
    const float* be2  = (const float*)d_in[14];
    const float* W1   = (const float*)d_in[15];
    const float* b1   = (const float*)d_in[16];
    const float* W2   = (const float*)d_in[17];
    const float* b2   = (const float*)d_in[18];
    float* out = (float*)d_out;

    unsigned char* base = nullptr;
    cudaGetSymbolAddress((void**)&base, g_scratch);
    __half* p_h   = (__half*)(base + OFF_H);
    __half* p_q   = (__half*)(base + OFF_Q);
    __half* p_k   = (__half*)(base + OFF_K);
    __half* p_v   = (__half*)(base + OFF_V);
    __half* p_att = (__half*)(base + OFF_ATT);
    __half* p_mlp = (__half*)(base + OFF_MLP);
    float*  p_x2  = (float*)(base + OFF_X2);
    __half* p_wq  = (__half*)(base + OFF_WQ);
    __half* p_wk  = (__half*)(base + OFF_WK);
    __half* p_wv  = (__half*)(base + OFF_WV);
    __half* p_wo  = (__half*)(base + OFF_WO);
    __half* p_w1  = (__half*)(base + OFF_W1);
    __half* p_w2  = (__half*)(base + OFF_W2);

    cudaFuncSetAttribute(flash_kernel,
                         cudaFuncAttributeMaxDynamicSharedMemorySize, FLASH_SMEM);
    cudaFuncSetAttribute(hgemm_kernel,
                         cudaFuncAttributeMaxDynamicSharedMemorySize, GEMM_SMEM);

    // 0. weights -> fp16 (one launch)
    const int nC4 = (Cdim * Cdim) / 4;
    const int nF4 = (Cdim * Fdim) / 4;
    ConvSet cs;
    cs.in[0] = (const float4*)Wq; cs.out[0] = (__half2*)p_wq; cs.n4[0] = nC4;
    cs.in[1] = (const float4*)Wk; cs.out[1] = (__half2*)p_wk; cs.n4[1] = nC4;
    cs.in[2] = (const float4*)Wv; cs.out[2] = (__half2*)p_wv; cs.n4[2] = nC4;
    cs.in[3] = (const float4*)Wo; cs.out[3] = (__half2*)p_wo; cs.n4[3] = nC4;
    cs.in[4] = (const float4*)W1; cs.out[4] = (__half2*)p_w1; cs.n4[4] = nF4;
    cs.in[5] = (const float4*)W2; cs.out[5] = (__half2*)p_w2; cs.n4[5] = nF4;
    conv_half_kernel<<<dim3(512, 1, 6), 256>>>(cs);

    // 1. LN1 -> half
    ln_kernel<<<Mrows, 256>>>(x, g1, be1, p_h);

    // 2. fused QKV projections -> half
    GemmSet qkv;
    qkv.W[0] = p_wq; qkv.W[1] = p_wk; qkv.W[2] = p_wv;
    qkv.bias[0] = bq; qkv.bias[1] = bk; qkv.bias[2] = bv;
    qkv.out[0] = p_q; qkv.out[1] = p_k; qkv.out[2] = p_v;
    hgemm_kernel<<<dim3(Cdim / 128, Mrows / 128, 3), 128, GEMM_SMEM>>>(
        p_h, qkv, nullptr, Mrows, Cdim, Cdim, 0, 1);

    // 3. RoPE on q and k, one vectorized launch
    rope2_kernel<<<dim3((Bb * Nn_ * Hh * 4) / 256, 1, 2), 256>>>(p_q, p_k, rcos, rsin);

    // 4. attention -> half
    flash_kernel<<<dim3(Nn_ / 128, Bb * Hh), 256, FLASH_SMEM>>>(p_q, p_k, p_v, p_att);

    // 5. output projection + fp32 residual -> fp32 x2
    GemmSet so;
    so.W[0] = p_wo; so.bias[0] = bo; so.out[0] = p_x2;
    so.W[1] = so.W[2] = nullptr; so.bias[1] = so.bias[2] = nullptr;
    so.out[1] = so.out[2] = nullptr;
    hgemm_kernel<<<dim3(Cdim / 128, Mrows / 128, 1), 128, GEMM_SMEM>>>(
        p_att, so, x, Mrows, Cdim, Cdim, 0, 0);

    // 6. LN2 -> half
    ln_kernel<<<Mrows, 256>>>(p_x2, g2, be2, p_h);

    // 7. MLP up + GELU -> half
    GemmSet s1;
    s1.W[0] = p_w1; s1.bias[0] = b1; s1.out[0] = p_mlp;
    s1.W[1] = s1.W[2] = nullptr; s1.bias[1] = s1.bias[2] = nullptr;
    s1.out[1] = s1.out[2] = nullptr;
    hgemm_kernel<<<dim3(Fdim / 128, Mrows / 128, 1), 128, GEMM_SMEM>>>(
        p_h, s1, nullptr, Mrows, Fdim, Cdim, 1, 1);

    // 8. MLP down + fp32 residual -> fp32 output
    GemmSet s2;
    s2.W[0] = p_w2; s2.bias[0] = b2; s2.out[0] = out;
    s2.W[1] = s2.W[2] = nullptr; s2.bias[1] = s2.bias[2] = nullptr;
    s2.out[1] = s2.out[2] = nullptr;
    hgemm_kernel<<<dim3(Cdim / 128, Mrows / 128, 1), 128, GEMM_SMEM>>>(
        p_mlp, s2, p_x2, Mrows, Cdim, Fdim, 0, 0);
}

// round 13
// speedup vs baseline: 1.7548x; 1.0172x over previous
#include <cuda_runtime.h>
#include <cuda_fp16.h>
#include <stdint.h>
#include <math.h>

// ---------------------------------------------------------------------------
// DiT block. Round 13: flash softmax via ex2.approx.f16x2 (half the MUFU ops);
// balanced flat weight-conversion kernel. hgemm/LN/RoPE unchanged from R12.
//   B=2, N=2048, C=1024, H=16, D=64, F=4096, M=B*N=4096
// ---------------------------------------------------------------------------

#define Mrows 4096
#define Cdim  1024
#define Fdim  4096
#define Bb    2
#define Hh    16
#define Dd    64
#define Nn_   2048

// byte offsets into scratch
#define OFF_H   ((size_t)0)
#define OFF_Q   ((size_t)8388608)
#define OFF_K   ((size_t)16777216)
#define OFF_V   ((size_t)25165824)
#define OFF_ATT ((size_t)33554432)
#define OFF_MLP ((size_t)41943040)
#define OFF_X2  ((size_t)75497472)
#define OFF_WQ  ((size_t)92274688)
#define OFF_WK  ((size_t)94371840)
#define OFF_WV  ((size_t)96468992)
#define OFF_WO  ((size_t)98566144)
#define OFF_W1  ((size_t)100663296)
#define OFF_W2  ((size_t)109051904)
__device__ __align__(1024) unsigned char g_scratch[117440512];

__device__ __forceinline__ uint32_t h2u(__half2 h) {
    return *reinterpret_cast<uint32_t*>(&h);
}

#define MMA_F16(d, a, b)                                                      \
    asm volatile(                                                             \
        "mma.sync.aligned.m16n8k16.row.col.f32.f16.f16.f32 "                  \
        "{%0,%1,%2,%3}, {%4,%5,%6,%7}, {%8,%9}, {%0,%1,%2,%3};"               \
        : "+f"(d[0]), "+f"(d[1]), "+f"(d[2]), "+f"(d[3])                      \
        : "r"(a[0]), "r"(a[1]), "r"(a[2]), "r"(a[3]), "r"(b[0]), "r"(b[1]))

#define CP_ASYNC16(dst_u32, src_ptr)                                          \
    asm volatile("cp.async.cg.shared.global [%0], [%1], 16;"                  \
                 :: "r"(dst_u32), "l"(src_ptr))
#define CP_COMMIT()  asm volatile("cp.async.commit_group;")
#define CP_WAIT(n)   asm volatile("cp.async.wait_group %0;" :: "n"(n))

#define EX2_F16X2(out_u32, in_u32)                                            \
    asm("ex2.approx.f16x2 %0, %1;" : "=r"(out_u32) : "r"(in_u32))

// ---------------------------------------------------------------------------
// Weight conversion fp32 -> fp16 (RN). Flat balanced grid-stride over all 6
// arrays (total index space; per-thread array lookup via cumulative starts).
// ---------------------------------------------------------------------------
struct ConvSet {
    const float4* in[6];
    __half2*      out[6];
    int           start[7];   // cumulative float4 offsets, start[6] = total
};

__global__ void __launch_bounds__(256) conv_half_kernel(ConvSet cs)
{
    const int total = cs.start[6];
    const int stride = gridDim.x * 256;
    for (int i = blockIdx.x * 256 + threadIdx.x; i < total; i += stride) {
        int z = 0;
        #pragma unroll
        for (int j = 1; j < 6; j++) z = (i >= cs.start[j]) ? j : z;
        const int li = i - cs.start[z];
        const float4 v = cs.in[z][li];
        __half2 h01 = __floats2half2_rn(v.x, v.y);
        __half2 h23 = __floats2half2_rn(v.z, v.w);
        uint2 u; u.x = h2u(h01); u.y = h2u(h23);
        *(uint2*)&cs.out[z][2 * li] = u;
    }
}

// ---------------------------------------------------------------------------
// LayerNorm: one block (256 thr) per row of 1024. fp32 in, fp16 out.
// ---------------------------------------------------------------------------
__global__ void __launch_bounds__(256) ln_kernel(
    const float* __restrict__ x, const float* __restrict__ g,
    const float* __restrict__ b, __half* __restrict__ out)
{
    __shared__ float red[16];
    const int row = blockIdx.x;
    const int t = threadIdx.x;
    const float4 xv = ((const float4*)(x + (size_t)row * Cdim))[t];
    float s  = xv.x + xv.y + xv.z + xv.w;
    float ss = xv.x*xv.x + xv.y*xv.y + xv.z*xv.z + xv.w*xv.w;
    #pragma unroll
    for (int o = 16; o > 0; o >>= 1) {
        s  += __shfl_xor_sync(0xffffffffu, s,  o);
        ss += __shfl_xor_sync(0xffffffffu, ss, o);
    }
    const int w = t >> 5;
    if ((t & 31) == 0) { red[w] = s; red[8 + w] = ss; }
    __syncthreads();
    float ts = 0.f, tss = 0.f;
    #pragma unroll
    for (int i = 0; i < 8; i++) { ts += red[i]; tss += red[8 + i]; }
    const float mean = ts * (1.0f / Cdim);
    const float var  = tss * (1.0f / Cdim) - mean * mean;
    const float inv  = rsqrtf(var + 1e-6f);
    const float4 gv = ((const float4*)g)[t];
    const float4 bv = ((const float4*)b)[t];
    __half2 h01 = __floats2half2_rn((xv.x - mean) * inv * gv.x + bv.x,
                                    (xv.y - mean) * inv * gv.y + bv.y);
    __half2 h23 = __floats2half2_rn((xv.z - mean) * inv * gv.z + bv.z,
                                    (xv.w - mean) * inv * gv.w + bv.w);
    uint2 u; u.x = h2u(h01); u.y = h2u(h23);
    *(uint2*)(out + (size_t)row * Cdim + 4 * t) = u;
}

// ---------------------------------------------------------------------------
// fp16 GEMM (unchanged from R12): 3-stage cp.async, 128x128 CTA tile, BK=32,
// 128 threads = 4 warps (2M x 2N), warp tile 64x64.
// ---------------------------------------------------------------------------
#define GSH 40
#define TBUFH (128 * GSH)
#define BOFFH (3 * TBUFH)
#define GEMM_SMEM (6 * TBUFH * 2)

struct GemmSet {
    const __half* W[3];
    const float*  bias[3];
    void*         out[3];
};

__global__ void __launch_bounds__(128, 2) hgemm_kernel(
    const __half* __restrict__ A, GemmSet gs, const float* __restrict__ residual,
    int M, int Nc, int K, int gelu, int out_half)
{
    extern __shared__ __half smh[];
    const uint32_t sbase = (uint32_t)__cvta_generic_to_shared(smh);

    const int z = blockIdx.z;
    const __half* __restrict__ Wp  = gs.W[z];
    const float* __restrict__ bias = gs.bias[z];
    void* __restrict__ outp        = gs.out[z];

    const int tid  = threadIdx.x;
    const int wid  = tid >> 5;
    const int lane = tid & 31;
    const int lr   = lane >> 2;
    const int lc   = lane & 3;
    const int warpM = (wid & 1) * 64;
    const int warpN = (wid >> 1) * 64;
    const int bm = blockIdx.y * 128, bn = blockIdx.x * 128;

    float acc[4][8][4];
    #pragma unroll
    for (int i = 0; i < 4; i++)
        #pragma unroll
        for (int j = 0; j < 8; j++)
            #pragma unroll
            for (int r = 0; r < 4; r++) acc[i][j][r] = 0.f;

    const int nk = K >> 5;

    #define LOAD_TILE(stg, k0)                                                \
    do {                                                                      \
        _Pragma("unroll")                                                     \
        for (int p = 0; p < 4; p++) {                                         \
            const int id = tid + p * 128;                                     \
            const int row = id >> 2;                                          \
            const int kc = id & 3;                                            \
            const uint32_t da = sbase + (uint32_t)(((stg) * TBUFH + row * GSH + kc * 8) * 2); \
            CP_ASYNC16(da, A + (size_t)(bm + row) * K + (k0) + kc * 8);       \
        }                                                                     \
        _Pragma("unroll")                                                     \
        for (int p = 0; p < 4; p++) {                                         \
            const int id = tid + p * 128;                                     \
            const int row = id >> 2;                                          \
            const int kc = id & 3;                                            \
            const uint32_t db = sbase + (uint32_t)((BOFFH + (stg) * TBUFH + row * GSH + kc * 8) * 2); \
            CP_ASYNC16(db, Wp + (size_t)(bn + row) * K + (k0) + kc * 8);      \
        }                                                                     \
    } while (0)

    LOAD_TILE(0, 0);
    CP_COMMIT();
    if (nk > 1) { LOAD_TILE(1, 32); }
    CP_COMMIT();

    int stg = 0;
    for (int kt = 0; kt < nk; kt++) {
        if (kt + 1 < nk) { CP_WAIT(1); } else { CP_WAIT(0); }
        __syncthreads();

        if (kt + 2 < nk) {
            const int ns = (stg + 2 >= 3) ? stg - 1 : stg + 2;
            LOAD_TILE(ns, (kt + 2) << 5);
            CP_COMMIT();
        }

        const __half* Asm = smh + stg * TBUFH;
        const __half* Bsm = smh + BOFFH + stg * TBUFH;
        #pragma unroll
        for (int ks = 0; ks < 2; ks++) {
            const int kk = ks * 16;
            uint32_t af[4][4], bf[8][2];
            #pragma unroll
            for (int i = 0; i < 4; i++) {
                const int rb = warpM + i * 16;
                af[i][0] = *(const uint32_t*)&Asm[(rb + lr) * GSH + kk + 2 * lc];
                af[i][1] = *(const uint32_t*)&Asm[(rb + lr + 8) * GSH + kk + 2 * lc];
                af[i][2] = *(const uint32_t*)&Asm[(rb + lr) * GSH + kk + 2 * lc + 8];
                af[i][3] = *(const uint32_t*)&Asm[(rb + lr + 8) * GSH + kk + 2 * lc + 8];
            }
            #pragma unroll
            for (int j = 0; j < 8; j++) {
                const int cb = warpN + j * 8;
                bf[j][0] = *(const uint32_t*)&Bsm[(cb + lr) * GSH + kk + 2 * lc];
                bf[j][1] = *(const uint32_t*)&Bsm[(cb + lr) * GSH + kk + 2 * lc + 8];
            }
            #pragma unroll
            for (int i = 0; i < 4; i++)
                #pragma unroll
                for (int j = 0; j < 8; j++)
                    MMA_F16(acc[i][j], af[i], bf[j]);
        }
        stg = (stg + 1 >= 3) ? 0 : stg + 1;
    }

    #pragma unroll
    for (int i = 0; i < 4; i++) {
        const int row0 = bm + warpM + i * 16 + lr;
        #pragma unroll
        for (int j = 0; j < 8; j++) {
            const int col = bn + warpN + j * 8 + (lc << 1);
            const float b0 = __ldg(&bias[col]);
            const float b1 = __ldg(&bias[col + 1]);
            float v0 = acc[i][j][0] + b0;
            float v1 = acc[i][j][1] + b1;
            float v2 = acc[i][j][2] + b0;
            float v3 = acc[i][j][3] + b1;
            if (gelu) {
                v0 = 0.5f * v0 * (1.0f + erff(v0 * 0.70710678118654752f));
                v1 = 0.5f * v1 * (1.0f + erff(v1 * 0.70710678118654752f));
                v2 = 0.5f * v2 * (1.0f + erff(v2 * 0.70710678118654752f));
                v3 = 0.5f * v3 * (1.0f + erff(v3 * 0.70710678118654752f));
            }
            if (residual) {
                v0 += residual[(size_t)row0 * Nc + col];
                v1 += residual[(size_t)row0 * Nc + col + 1];
                v2 += residual[(size_t)(row0 + 8) * Nc + col];
                v3 += residual[(size_t)(row0 + 8) * Nc + col + 1];
            }
            if (out_half) {
                __half* oh = (__half*)outp;
                *(uint32_t*)(oh + (size_t)row0 * Nc + col)       = h2u(__floats2half2_rn(v0, v1));
                *(uint32_t*)(oh + (size_t)(row0 + 8) * Nc + col) = h2u(__floats2half2_rn(v2, v3));
            } else {
                float* of = (float*)outp;
                *(float2*)(of + (size_t)row0 * Nc + col)       = make_float2(v0, v1);
                *(float2*)(of + (size_t)(row0 + 8) * Nc + col) = make_float2(v2, v3);
            }
        }
    }
}

// ---------------------------------------------------------------------------
// Vectorized RoPE (unchanged from R12)
// ---------------------------------------------------------------------------
__global__ void __launch_bounds__(256) rope2_kernel(
    __half* __restrict__ qp, __half* __restrict__ kp,
    const float* __restrict__ cosb, const float* __restrict__ sinb)
{
    __half* t = blockIdx.z ? kp : qp;
    int idx = blockIdx.x * 256 + threadIdx.x;
    const int ci = idx & 3; idx >>= 2;
    const int h = idx & (Hh - 1); idx >>= 4;
    const int n = idx & (Nn_ - 1); idx >>= 11;
    const int b = idx;
    const int c = ci * 8;
    const size_t base = ((size_t)(b * Nn_ + n)) * Cdim + h * Dd;

    uint4 lo = *(uint4*)(t + base + c);
    uint4 hi = *(uint4*)(t + base + c + 32);
    const __half* xl = (const __half*)&lo;
    const __half* xh = (const __half*)&hi;

    const float* cb = cosb + n * Dd;
    const float* sb = sinb + n * Dd;
    float cl[8], sl[8], ch[8], sh[8];
    *(float4*)&cl[0] = *(const float4*)(cb + c);
    *(float4*)&cl[4] = *(const float4*)(cb + c + 4);
    *(float4*)&ch[0] = *(const float4*)(cb + c + 32);
    *(float4*)&ch[4] = *(const float4*)(cb + c + 36);
    *(float4*)&sl[0] = *(const float4*)(sb + c);
    *(float4*)&sl[4] = *(const float4*)(sb + c + 4);
    *(float4*)&sh[0] = *(const float4*)(sb + c + 32);
    *(float4*)&sh[4] = *(const float4*)(sb + c + 36);

    uint4 olo, ohi;
    __half* ol = (__half*)&olo;
    __half* oh = (__half*)&ohi;
    #pragma unroll
    for (int j = 0; j < 8; j++) {
        const float x1 = __half2float(xl[j]);
        const float x2 = __half2float(xh[j]);
        ol[j] = __float2half_rn(x1 * cl[j] - x2 * sl[j]);
        oh[j] = __float2half_rn(x2 * ch[j] + x1 * sh[j]);
    }
    *(uint4*)(t + base + c)      = olo;
    *(uint4*)(t + base + c + 32) = ohi;
}

// ---------------------------------------------------------------------------
// Flash attention, fp16 mma; softmax via ex2.approx.f16x2; P in registers.
// ---------------------------------------------------------------------------
#define QSH 72
#define F_QS 0
#define F_KS (128 * QSH)
#define F_VS (F_KS + 64 * QSH)
#define FLASH_SMEM ((F_VS + 64 * QSH) * 2)

__global__ void __launch_bounds__(256) flash_kernel(
    const __half* __restrict__ q, const __half* __restrict__ k,
    const __half* __restrict__ v, __half* __restrict__ out)
{
    extern __shared__ __half smf[];
    __half* Qs = smf + F_QS;
    __half* Ks = smf + F_KS;
    __half* Vt = smf + F_VS;

    const int tid  = threadIdx.x;
    const int wid  = tid >> 5;
    const int lane = tid & 31;
    const int lr   = lane >> 2;
    const int lc   = lane & 3;
    const int rm   = wid * 16;

    const int bh = blockIdx.y;
    const int b = bh >> 4;
    const int h = bh & 15;
    const int q0 = blockIdx.x * 128;
    const float qscale = 0.125f * 1.4426950408889634f;

    const __half* qb = q + ((size_t)(b * Nn_ + q0)) * Cdim + h * Dd;
    #pragma unroll
    for (int i = 0; i < 4; i++) {
        const int idx = tid + i * 256;
        const int r = idx >> 3;
        const int c = (idx & 7) * 8;
        uint4 u = *(const uint4*)(qb + (size_t)r * Cdim + c);
        __half2* hp = (__half2*)&u;
        #pragma unroll
        for (int j = 0; j < 4; j++) {
            float2 f = __half22float2(hp[j]);
            hp[j] = __floats2half2_rn(f.x * qscale, f.y * qscale);
        }
        *(uint4*)&Qs[r * QSH + c] = u;
    }
    __syncthreads();

    uint32_t qf[4][4];
    #pragma unroll
    for (int ks = 0; ks < 4; ks++) {
        const int kk = ks * 16;
        qf[ks][0] = *(const uint32_t*)&Qs[(rm + lr) * QSH + kk + 2 * lc];
        qf[ks][1] = *(const uint32_t*)&Qs[(rm + lr + 8) * QSH + kk + 2 * lc];
        qf[ks][2] = *(const uint32_t*)&Qs[(rm + lr) * QSH + kk + 2 * lc + 8];
        qf[ks][3] = *(const uint32_t*)&Qs[(rm + lr + 8) * QSH + kk + 2 * lc + 8];
    }

    int srow[2], scol[2];
    #pragma unroll
    for (int i = 0; i < 2; i++) {
        const int idx = tid + i * 256;
        srow[i] = idx >> 3;
        scol[i] = (idx & 7) * 8;
    }
    const __half* kb0 = k + ((size_t)(b * Nn_)) * Cdim + h * Dd;
    const __half* vb0 = v + ((size_t)(b * Nn_)) * Cdim + h * Dd;

    uint4 kreg[2], vreg[2];
    #pragma unroll
    for (int i = 0; i < 2; i++) {
        kreg[i] = *(const uint4*)(kb0 + (size_t)srow[i] * Cdim + scol[i]);
        vreg[i] = *(const uint4*)(vb0 + (size_t)srow[i] * Cdim + scol[i]);
    }

    float m0 = -1e30f, m1 = -1e30f, l0 = 0.f, l1 = 0.f;
    float oacc[8][4];
    #pragma unroll
    for (int nt = 0; nt < 8; nt++)
        #pragma unroll
        for (int r = 0; r < 4; r++) oacc[nt][r] = 0.f;

    for (int kv0 = 0; kv0 < Nn_; kv0 += 64) {
        __syncthreads();
        #pragma unroll
        for (int i = 0; i < 2; i++) {
            *(uint4*)&Ks[srow[i] * QSH + scol[i]] = kreg[i];
            const __half* vh = (const __half*)&vreg[i];
            #pragma unroll
            for (int j = 0; j < 8; j++)
                Vt[(scol[i] + j) * QSH + srow[i]] = vh[j];
        }
        __syncthreads();

        if (kv0 + 64 < Nn_) {
            const __half* kb = kb0 + (size_t)(kv0 + 64) * Cdim;
            const __half* vb = vb0 + (size_t)(kv0 + 64) * Cdim;
            #pragma unroll
            for (int i = 0; i < 2; i++) {
                kreg[i] = *(const uint4*)(kb + (size_t)srow[i] * Cdim + scol[i]);
                vreg[i] = *(const uint4*)(vb + (size_t)srow[i] * Cdim + scol[i]);
            }
        }

        float sacc[8][4];
        #pragma unroll
        for (int nt = 0; nt < 8; nt++)
            #pragma unroll
            for (int r = 0; r < 4; r++) sacc[nt][r] = 0.f;
        #pragma unroll
        for (int ks = 0; ks < 4; ks++) {
            const int kk = ks * 16;
            #pragma unroll
            for (int nt = 0; nt < 8; nt++) {
                uint32_t bf[2];
                bf[0] = *(const uint32_t*)&Ks[(nt * 8 + lr) * QSH + kk + 2 * lc];
                bf[1] = *(const uint32_t*)&Ks[(nt * 8 + lr) * QSH + kk + 2 * lc + 8];
                MMA_F16(sacc[nt], qf[ks], bf);
            }
        }

        // online softmax; P produced by ex2.approx.f16x2 directly as half2
        float mx0 = -1e30f, mx1 = -1e30f;
        #pragma unroll
        for (int nt = 0; nt < 8; nt++) {
            mx0 = fmaxf(mx0, fmaxf(sacc[nt][0], sacc[nt][1]));
            mx1 = fmaxf(mx1, fmaxf(sacc[nt][2], sacc[nt][3]));
        }
        #pragma unroll
        for (int o = 1; o < 4; o <<= 1) {
            mx0 = fmaxf(mx0, __shfl_xor_sync(0xffffffffu, mx0, o, 4));
            mx1 = fmaxf(mx1, __shfl_xor_sync(0xffffffffu, mx1, o, 4));
        }
        const float mn0 = fmaxf(m0, mx0);
        const float mn1 = fmaxf(m1, mx1);
        const float al0 = exp2f(m0 - mn0);
        const float al1 = exp2f(m1 - mn1);
        float rs0 = 0.f, rs1 = 0.f;
        uint32_t pf[4][4];
        #pragma unroll
        for (int ks = 0; ks < 4; ks++) {
            const int ntA = 2 * ks, ntB = 2 * ks + 1;
            __half2 d0 = __floats2half2_rn(sacc[ntA][0] - mn0, sacc[ntA][1] - mn0);
            __half2 d1 = __floats2half2_rn(sacc[ntA][2] - mn1, sacc[ntA][3] - mn1);
            __half2 d2 = __floats2half2_rn(sacc[ntB][0] - mn0, sacc[ntB][1] - mn0);
            __half2 d3 = __floats2half2_rn(sacc[ntB][2] - mn1, sacc[ntB][3] - mn1);
            EX2_F16X2(pf[ks][0], h2u(d0));
            EX2_F16X2(pf[ks][1], h2u(d1));
            EX2_F16X2(pf[ks][2], h2u(d2));
            EX2_F16X2(pf[ks][3], h2u(d3));
            const float2 f0 = __half22float2(*(__half2*)&pf[ks][0]);
            const float2 f1 = __half22float2(*(__half2*)&pf[ks][1]);
            const float2 f2 = __half22float2(*(__half2*)&pf[ks][2]);
            const float2 f3 = __half22float2(*(__half2*)&pf[ks][3]);
            rs0 += f0.x + f0.y + f2.x + f2.y;
            rs1 += f1.x + f1.y + f3.x + f3.y;
        }
        #pragma unroll
        for (int o = 1; o < 4; o <<= 1) {
            rs0 += __shfl_xor_sync(0xffffffffu, rs0, o, 4);
            rs1 += __shfl_xor_sync(0xffffffffu, rs1, o, 4);
        }
        l0 = l0 * al0 + rs0;  m0 = mn0;
        l1 = l1 * al1 + rs1;  m1 = mn1;
        #pragma unroll
        for (int nt = 0; nt < 8; nt++) {
            oacc[nt][0] *= al0; oacc[nt][1] *= al0;
            oacc[nt][2] *= al1; oacc[nt][3] *= al1;
        }

        #pragma unroll
        for (int ks = 0; ks < 4; ks++) {
            const int kk = ks * 16;
            #pragma unroll
            for (int nt = 0; nt < 8; nt++) {
                uint32_t bf[2];
                bf[0] = *(const uint32_t*)&Vt[(nt * 8 + lr) * QSH + kk + 2 * lc];
                bf[1] = *(const uint32_t*)&Vt[(nt * 8 + lr) * QSH + kk + 2 * lc + 8];
                MMA_F16(oacc[nt], pf[ks], bf);
            }
        }
    }

    const float il0 = 1.0f / l0;
    const float il1 = 1.0f / l1;
    __half* ob = out + ((size_t)(b * Nn_ + q0 + rm)) * Cdim + h * Dd;
    #pragma unroll
    for (int nt = 0; nt < 8; nt++) {
        const int col = nt * 8 + 2 * lc;
        *(uint32_t*)(ob + (size_t)lr * Cdim + col) =
            h2u(__floats2half2_rn(oacc[nt][0] * il0, oacc[nt][1] * il0));
        *(uint32_t*)(ob + (size_t)(lr + 8) * Cdim + col) =
            h2u(__floats2half2_rn(oacc[nt][2] * il1, oacc[nt][3] * il1));
    }
}

// ---------------------------------------------------------------------------
extern "C" void kernel_launch(void* const* d_in, const int* in_sizes, int n_in,
                              void* d_out, int out_size)
{
    const float* x    = (const float*)d_in[0];
    const float* rcos = (const float*)d_in[1];
    const float* rsin = (const float*)d_in[2];
    const float* g1   = (const float*)d_in[3];
    const float* be1  = (const float*)d_in[4];
    const float* Wq   = (const float*)d_in[5];
    const float* bq   = (const float*)d_in[6];
    const float* Wk   = (const float*)d_in[7];
    const float* bk   = (const float*)d_in[8];
    const float* Wv   = (const float*)d_in[9];
    const float* bv   = (const float*)d_in[10];
    const float* Wo   = (const float*)d_in[11];
    const float* bo   = (const float*)d_in[12];
    const float* g2   = (const float*)d_in[13];
    const float* be2  = (const float*)d_in[14];
    const float* W1   = (const float*)d_in[15];
    const float* b1   = (const float*)d_in[16];
    const float* W2   = (const float*)d_in[17];
    const float* b2   = (const float*)d_in[18];
    float* out = (float*)d_out;

    unsigned char* base = nullptr;
    cudaGetSymbolAddress((void**)&base, g_scratch);
    __half* p_h   = (__half*)(base + OFF_H);
    __half* p_q   = (__half*)(base + OFF_Q);
    __half* p_k   = (__half*)(base + OFF_K);
    __half* p_v   = (__half*)(base + OFF_V);
    __half* p_att = (__half*)(base + OFF_ATT);
    __half* p_mlp = (__half*)(base + OFF_MLP);
    float*  p_x2  = (float*)(base + OFF_X2);
    __half* p_wq  = (__half*)(base + OFF_WQ);
    __half* p_wk  = (__half*)(base + OFF_WK);
    __half* p_wv  = (__half*)(base + OFF_WV);
    __half* p_wo  = (__half*)(base + OFF_WO);
    __half* p_w1  = (__half*)(base + OFF_W1);
    __half* p_w2  = (__half*)(base + OFF_W2);

    cudaFuncSetAttribute(flash_kernel,
                         cudaFuncAttributeMaxDynamicSharedMemorySize, FLASH_SMEM);
    cudaFuncSetAttribute(hgemm_kernel,
                         cudaFuncAttributeMaxDynamicSharedMemorySize, GEMM_SMEM);

    // 0. weights -> fp16 (balanced flat launch)
    const int nC4 = (Cdim * Cdim) / 4;      // 262144
    const int nF4 = (Cdim * Fdim) / 4;      // 1048576
    ConvSet cs;
    cs.in[0] = (const float4*)Wq; cs.out[0] = (__half2*)p_wq;
    cs.in[1] = (const float4*)Wk; cs.out[1] = (__half2*)p_wk;
    cs.in[2] = (const float4*)Wv; cs.out[2] = (__half2*)p_wv;
    cs.in[3] = (const float4*)Wo; cs.out[3] = (__half2*)p_wo;
    cs.in[4] = (const float4*)W1; cs.out[4] = (__half2*)p_w1;
    cs.in[5] = (const float4*)W2; cs.out[5] = (__half2*)p_w2;
    cs.start[0] = 0;
    cs.start[1] = nC4;
    cs.start[2] = 2 * nC4;
    cs.start[3] = 3 * nC4;
    cs.start[4] = 4 * nC4;
    cs.start[5] = 4 * nC4 + nF4;
    cs.start[6] = 4 * nC4 + 2 * nF4;        // 3145728 total float4s
    conv_half_kernel<<<3072, 256>>>(cs);

    // 1. LN1 -> half
    ln_kernel<<<Mrows, 256>>>(x, g1, be1, p_h);

    // 2. fused QKV projections -> half
    GemmSet qkv;
    qkv.W[0] = p_wq; qkv.W[1] = p_wk; qkv.W[2] = p_wv;
    qkv.bias[0] = bq; qkv.bias[1] = bk; qkv.bias[2] = bv;
    qkv.out[0] = p_q; qkv.out[1] = p_k; qkv.out[2] = p_v;
    hgemm_kernel<<<dim3(Cdim / 128, Mrows / 128, 3), 128, GEMM_SMEM>>>(
        p_h, qkv, nullptr, Mrows, Cdim, Cdim, 0, 1);

    // 3. RoPE on q and k, one vectorized launch
    rope2_kernel<<<dim3((Bb * Nn_ * Hh * 4) / 256, 1, 2), 256>>>(p_q, p_k, rcos, rsin);

    // 4. attention -> half
    flash_kernel<<<dim3(Nn_ / 128, Bb * Hh), 256, FLASH_SMEM>>>(p_q, p_k, p_v, p_att);

    // 5. output projection + fp32 residual -> fp32 x2
    GemmSet so;
    so.W[0] = p_wo; so.bias[0] = bo; so.out[0] = p_x2;
    so.W[1] = so.W[2] = nullptr; so.bias[1] = so.bias[2] = nullptr;
    so.out[1] = so.out[2] = nullptr;
    hgemm_kernel<<<dim3(Cdim / 128, Mrows / 128, 1), 128, GEMM_SMEM>>>(
        p_att, so, x, Mrows, Cdim, Cdim, 0, 0);

    // 6. LN2 -> half
    ln_kernel<<<Mrows, 256>>>(p_x2, g2, be2, p_h);

    // 7. MLP up + GELU -> half
    GemmSet s1;
    s1.W[0] = p_w1; s1.bias[0] = b1; s1.out[0] = p_mlp;
    s1.W[1] = s1.W[2] = nullptr; s1.bias[1] = s1.bias[2] = nullptr;
    s1.out[1] = s1.out[2] = nullptr;
    hgemm_kernel<<<dim3(Fdim / 128, Mrows / 128, 1), 128, GEMM_SMEM>>>(
        p_h, s1, nullptr, Mrows, Fdim, Cdim, 1, 1);

    // 8. MLP down + fp32 residual -> fp32 output
    GemmSet s2;
    s2.W[0] = p_w2; s2.bias[0] = b2; s2.out[0] = out;
    s2.W[1] = s2.W[2] = nullptr; s2.bias[1] = s2.bias[2] = nullptr;
    s2.out[1] = s2.out[2] = nullptr;
    hgemm_kernel<<<dim3(Cdim / 128, Mrows / 128, 1), 128, GEMM_SMEM>>>(
        p_mlp, s2, p_x2, Mrows, Cdim, Fdim, 0, 0);
}

// round 14
// speedup vs baseline: 1.9959x; 1.1374x over previous
#include <cuda_runtime.h>
#include <cuda_fp16.h>
#include <stdint.h>
#include <math.h>

// ---------------------------------------------------------------------------
// DiT block. Round 14: hgemm fragment loads via ldmatrix.m8n8.x4
// (64 LDS -> 16 LDSM per warp-iteration). Rest unchanged from R13.
//   B=2, N=2048, C=1024, H=16, D=64, F=4096, M=B*N=4096
// ---------------------------------------------------------------------------

#define Mrows 4096
#define Cdim  1024
#define Fdim  4096
#define Bb    2
#define Hh    16
#define Dd    64
#define Nn_   2048

// byte offsets into scratch
#define OFF_H   ((size_t)0)
#define OFF_Q   ((size_t)8388608)
#define OFF_K   ((size_t)16777216)
#define OFF_V   ((size_t)25165824)
#define OFF_ATT ((size_t)33554432)
#define OFF_MLP ((size_t)41943040)
#define OFF_X2  ((size_t)75497472)
#define OFF_WQ  ((size_t)92274688)
#define OFF_WK  ((size_t)94371840)
#define OFF_WV  ((size_t)96468992)
#define OFF_WO  ((size_t)98566144)
#define OFF_W1  ((size_t)100663296)
#define OFF_W2  ((size_t)109051904)
__device__ __align__(1024) unsigned char g_scratch[117440512];

__device__ __forceinline__ uint32_t h2u(__half2 h) {
    return *reinterpret_cast<uint32_t*>(&h);
}

#define MMA_F16(d, a, b)                                                      \
    asm volatile(                                                             \
        "mma.sync.aligned.m16n8k16.row.col.f32.f16.f16.f32 "                  \
        "{%0,%1,%2,%3}, {%4,%5,%6,%7}, {%8,%9}, {%0,%1,%2,%3};"               \
        : "+f"(d[0]), "+f"(d[1]), "+f"(d[2]), "+f"(d[3])                      \
        : "r"(a[0]), "r"(a[1]), "r"(a[2]), "r"(a[3]), "r"(b[0]), "r"(b[1]))

#define CP_ASYNC16(dst_u32, src_ptr)                                          \
    asm volatile("cp.async.cg.shared.global [%0], [%1], 16;"                  \
                 :: "r"(dst_u32), "l"(src_ptr))
#define CP_COMMIT()  asm volatile("cp.async.commit_group;")
#define CP_WAIT(n)   asm volatile("cp.async.wait_group %0;" :: "n"(n))

#define EX2_F16X2(out_u32, in_u32)                                            \
    asm("ex2.approx.f16x2 %0, %1;" : "=r"(out_u32) : "r"(in_u32))

#define LDSM_X4(r0, r1, r2, r3, addr)                                         \
    asm volatile("ldmatrix.sync.aligned.m8n8.x4.shared.b16 "                  \
                 "{%0,%1,%2,%3}, [%4];"                                       \
                 : "=r"(r0), "=r"(r1), "=r"(r2), "=r"(r3) : "r"(addr))

// ---------------------------------------------------------------------------
// Weight conversion fp32 -> fp16 (RN), flat balanced grid-stride.
// ---------------------------------------------------------------------------
struct ConvSet {
    const float4* in[6];
    __half2*      out[6];
    int           start[7];
};

__global__ void __launch_bounds__(256) conv_half_kernel(ConvSet cs)
{
    const int total = cs.start[6];
    const int stride = gridDim.x * 256;
    for (int i = blockIdx.x * 256 + threadIdx.x; i < total; i += stride) {
        int z = 0;
        #pragma unroll
        for (int j = 1; j < 6; j++) z = (i >= cs.start[j]) ? j : z;
        const int li = i - cs.start[z];
        const float4 v = cs.in[z][li];
        __half2 h01 = __floats2half2_rn(v.x, v.y);
        __half2 h23 = __floats2half2_rn(v.z, v.w);
        uint2 u; u.x = h2u(h01); u.y = h2u(h23);
        *(uint2*)&cs.out[z][2 * li] = u;
    }
}

// ---------------------------------------------------------------------------
// LayerNorm: one block (256 thr) per row of 1024. fp32 in, fp16 out.
// ---------------------------------------------------------------------------
__global__ void __launch_bounds__(256) ln_kernel(
    const float* __restrict__ x, const float* __restrict__ g,
    const float* __restrict__ b, __half* __restrict__ out)
{
    __shared__ float red[16];
    const int row = blockIdx.x;
    const int t = threadIdx.x;
    const float4 xv = ((const float4*)(x + (size_t)row * Cdim))[t];
    float s  = xv.x + xv.y + xv.z + xv.w;
    float ss = xv.x*xv.x + xv.y*xv.y + xv.z*xv.z + xv.w*xv.w;
    #pragma unroll
    for (int o = 16; o > 0; o >>= 1) {
        s  += __shfl_xor_sync(0xffffffffu, s,  o);
        ss += __shfl_xor_sync(0xffffffffu, ss, o);
    }
    const int w = t >> 5;
    if ((t & 31) == 0) { red[w] = s; red[8 + w] = ss; }
    __syncthreads();
    float ts = 0.f, tss = 0.f;
    #pragma unroll
    for (int i = 0; i < 8; i++) { ts += red[i]; tss += red[8 + i]; }
    const float mean = ts * (1.0f / Cdim);
    const float var  = tss * (1.0f / Cdim) - mean * mean;
    const float inv  = rsqrtf(var + 1e-6f);
    const float4 gv = ((const float4*)g)[t];
    const float4 bv = ((const float4*)b)[t];
    __half2 h01 = __floats2half2_rn((xv.x - mean) * inv * gv.x + bv.x,
                                    (xv.y - mean) * inv * gv.y + bv.y);
    __half2 h23 = __floats2half2_rn((xv.z - mean) * inv * gv.z + bv.z,
                                    (xv.w - mean) * inv * gv.w + bv.w);
    uint2 u; u.x = h2u(h01); u.y = h2u(h23);
    *(uint2*)(out + (size_t)row * Cdim + 4 * t) = u;
}

// ---------------------------------------------------------------------------
// fp16 GEMM: 3-stage cp.async, 128x128 CTA tile, BK=32, 4 warps (2Mx2N),
// warp tile 64x64, fragments via ldmatrix.x4.
// ---------------------------------------------------------------------------
#define GSH 40
#define TBUFH (128 * GSH)
#define BOFFH (3 * TBUFH)
#define GEMM_SMEM (6 * TBUFH * 2)

struct GemmSet {
    const __half* W[3];
    const float*  bias[3];
    void*         out[3];
};

__global__ void __launch_bounds__(128, 2) hgemm_kernel(
    const __half* __restrict__ A, GemmSet gs, const float* __restrict__ residual,
    int M, int Nc, int K, int gelu, int out_half)
{
    extern __shared__ __half smh[];
    const uint32_t sbase = (uint32_t)__cvta_generic_to_shared(smh);

    const int z = blockIdx.z;
    const __half* __restrict__ Wp  = gs.W[z];
    const float* __restrict__ bias = gs.bias[z];
    void* __restrict__ outp        = gs.out[z];

    const int tid  = threadIdx.x;
    const int wid  = tid >> 5;
    const int lane = tid & 31;
    const int lr   = lane >> 2;
    const int lc   = lane & 3;
    const int warpM = (wid & 1) * 64;
    const int warpN = (wid >> 1) * 64;
    const int bm = blockIdx.y * 128, bn = blockIdx.x * 128;

    // ldmatrix lane-row/col mappings
    const int a_row  = warpM + (lane & 15);          // within A tile
    const int a_col8 = (lane >> 4) * 8;              // 0 or 8
    const int b_row  = (lane & 7) + ((lane >> 4) & 1) * 8;  // within 16-row jp block
    const int b_col8 = ((lane >> 3) & 1) * 8;        // 0 or 8

    float acc[4][8][4];
    #pragma unroll
    for (int i = 0; i < 4; i++)
        #pragma unroll
        for (int j = 0; j < 8; j++)
            #pragma unroll
            for (int r = 0; r < 4; r++) acc[i][j][r] = 0.f;

    const int nk = K >> 5;

    #define LOAD_TILE(stg, k0)                                                \
    do {                                                                      \
        _Pragma("unroll")                                                     \
        for (int p = 0; p < 4; p++) {                                         \
            const int id = tid + p * 128;                                     \
            const int row = id >> 2;                                          \
            const int kc = id & 3;                                            \
            const uint32_t da = sbase + (uint32_t)(((stg) * TBUFH + row * GSH + kc * 8) * 2); \
            CP_ASYNC16(da, A + (size_t)(bm + row) * K + (k0) + kc * 8);       \
        }                                                                     \
        _Pragma("unroll")                                                     \
        for (int p = 0; p < 4; p++) {                                         \
            const int id = tid + p * 128;                                     \
            const int row = id >> 2;                                          \
            const int kc = id & 3;                                            \
            const uint32_t db = sbase + (uint32_t)((BOFFH + (stg) * TBUFH + row * GSH + kc * 8) * 2); \
            CP_ASYNC16(db, Wp + (size_t)(bn + row) * K + (k0) + kc * 8);      \
        }                                                                     \
    } while (0)

    LOAD_TILE(0, 0);
    CP_COMMIT();
    if (nk > 1) { LOAD_TILE(1, 32); }
    CP_COMMIT();

    int stg = 0;
    for (int kt = 0; kt < nk; kt++) {
        if (kt + 1 < nk) { CP_WAIT(1); } else { CP_WAIT(0); }
        __syncthreads();

        if (kt + 2 < nk) {
            const int ns = (stg + 2 >= 3) ? stg - 1 : stg + 2;
            LOAD_TILE(ns, (kt + 2) << 5);
            CP_COMMIT();
        }

        const uint32_t aTile = sbase + (uint32_t)((stg * TBUFH) * 2);
        const uint32_t bTile = sbase + (uint32_t)((BOFFH + stg * TBUFH) * 2);
        #pragma unroll
        for (int ks = 0; ks < 2; ks++) {
            const int kk = ks * 16;
            uint32_t af[4][4], bf[8][2];
            #pragma unroll
            for (int i = 0; i < 4; i++) {
                const uint32_t addr = aTile +
                    (uint32_t)(((a_row + i * 16) * GSH + kk + a_col8) * 2);
                LDSM_X4(af[i][0], af[i][1], af[i][2], af[i][3], addr);
            }
            #pragma unroll
            for (int jp = 0; jp < 4; jp++) {
                const int cb = warpN + jp * 16;
                const uint32_t addr = bTile +
                    (uint32_t)(((cb + b_row) * GSH + kk + b_col8) * 2);
                LDSM_X4(bf[2 * jp][0], bf[2 * jp][1],
                        bf[2 * jp + 1][0], bf[2 * jp + 1][1], addr);
            }
            #pragma unroll
            for (int i = 0; i < 4; i++)
                #pragma unroll
                for (int j = 0; j < 8; j++)
                    MMA_F16(acc[i][j], af[i], bf[j]);
        }
        stg = (stg + 1 >= 3) ? 0 : stg + 1;
    }

    #pragma unroll
    for (int i = 0; i < 4; i++) {
        const int row0 = bm + warpM + i * 16 + lr;
        #pragma unroll
        for (int j = 0; j < 8; j++) {
            const int col = bn + warpN + j * 8 + (lc << 1);
            const float b0 = __ldg(&bias[col]);
            const float b1 = __ldg(&bias[col + 1]);
            float v0 = acc[i][j][0] + b0;
            float v1 = acc[i][j][1] + b1;
            float v2 = acc[i][j][2] + b0;
            float v3 = acc[i][j][3] + b1;
            if (gelu) {
                v0 = 0.5f * v0 * (1.0f + erff(v0 * 0.70710678118654752f));
                v1 = 0.5f * v1 * (1.0f + erff(v1 * 0.70710678118654752f));
                v2 = 0.5f * v2 * (1.0f + erff(v2 * 0.70710678118654752f));
                v3 = 0.5f * v3 * (1.0f + erff(v3 * 0.70710678118654752f));
            }
            if (residual) {
                v0 += residual[(size_t)row0 * Nc + col];
                v1 += residual[(size_t)row0 * Nc + col + 1];
                v2 += residual[(size_t)(row0 + 8) * Nc + col];
                v3 += residual[(size_t)(row0 + 8) * Nc + col + 1];
            }
            if (out_half) {
                __half* oh = (__half*)outp;
                *(uint32_t*)(oh + (size_t)row0 * Nc + col)       = h2u(__floats2half2_rn(v0, v1));
                *(uint32_t*)(oh + (size_t)(row0 + 8) * Nc + col) = h2u(__floats2half2_rn(v2, v3));
            } else {
                float* of = (float*)outp;
                *(float2*)(of + (size_t)row0 * Nc + col)       = make_float2(v0, v1);
                *(float2*)(of + (size_t)(row0 + 8) * Nc + col) = make_float2(v2, v3);
            }
        }
    }
}

// ---------------------------------------------------------------------------
// Vectorized RoPE (unchanged)
// ---------------------------------------------------------------------------
__global__ void __launch_bounds__(256) rope2_kernel(
    __half* __restrict__ qp, __half* __restrict__ kp,
    const float* __restrict__ cosb, const float* __restrict__ sinb)
{
    __half* t = blockIdx.z ? kp : qp;
    int idx = blockIdx.x * 256 + threadIdx.x;
    const int ci = idx & 3; idx >>= 2;
    const int h = idx & (Hh - 1); idx >>= 4;
    const int n = idx & (Nn_ - 1); idx >>= 11;
    const int b = idx;
    const int c = ci * 8;
    const size_t base = ((size_t)(b * Nn_ + n)) * Cdim + h * Dd;

    uint4 lo = *(uint4*)(t + base + c);
    uint4 hi = *(uint4*)(t + base + c + 32);
    const __half* xl = (const __half*)&lo;
    const __half* xh = (const __half*)&hi;

    const float* cb = cosb + n * Dd;
    const float* sb = sinb + n * Dd;
    float cl[8], sl[8], ch[8], sh[8];
    *(float4*)&cl[0] = *(const float4*)(cb + c);
    *(float4*)&cl[4] = *(const float4*)(cb + c + 4);
    *(float4*)&ch[0] = *(const float4*)(cb + c + 32);
    *(float4*)&ch[4] = *(const float4*)(cb + c + 36);
    *(float4*)&sl[0] = *(const float4*)(sb + c);
    *(float4*)&sl[4] = *(const float4*)(sb + c + 4);
    *(float4*)&sh[0] = *(const float4*)(sb + c + 32);
    *(float4*)&sh[4] = *(const float4*)(sb + c + 36);

    uint4 olo, ohi;
    __half* ol = (__half*)&olo;
    __half* oh = (__half*)&ohi;
    #pragma unroll
    for (int j = 0; j < 8; j++) {
        const float x1 = __half2float(xl[j]);
        const float x2 = __half2float(xh[j]);
        ol[j] = __float2half_rn(x1 * cl[j] - x2 * sl[j]);
        oh[j] = __float2half_rn(x2 * ch[j] + x1 * sh[j]);
    }
    *(uint4*)(t + base + c)      = olo;
    *(uint4*)(t + base + c + 32) = ohi;
}

// ---------------------------------------------------------------------------
// Flash attention (unchanged from R13): fp16 mma, ex2.f16x2, P in registers.
// ---------------------------------------------------------------------------
#define QSH 72
#define F_QS 0
#define F_KS (128 * QSH)
#define F_VS (F_KS + 64 * QSH)
#define FLASH_SMEM ((F_VS + 64 * QSH) * 2)

__global__ void __launch_bounds__(256) flash_kernel(
    const __half* __restrict__ q, const __half* __restrict__ k,
    const __half* __restrict__ v, __half* __restrict__ out)
{
    extern __shared__ __half smf[];
    __half* Qs = smf + F_QS;
    __half* Ks = smf + F_KS;
    __half* Vt = smf + F_VS;

    const int tid  = threadIdx.x;
    const int wid  = tid >> 5;
    const int lane = tid & 31;
    const int lr   = lane >> 2;
    const int lc   = lane & 3;
    const int rm   = wid * 16;

    const int bh = blockIdx.y;
    const int b = bh >> 4;
    const int h = bh & 15;
    const int q0 = blockIdx.x * 128;
    const float qscale = 0.125f * 1.4426950408889634f;

    const __half* qb = q + ((size_t)(b * Nn_ + q0)) * Cdim + h * Dd;
    #pragma unroll
    for (int i = 0; i < 4; i++) {
        const int idx = tid + i * 256;
        const int r = idx >> 3;
        const int c = (idx & 7) * 8;
        uint4 u = *(const uint4*)(qb + (size_t)r * Cdim + c);
        __half2* hp = (__half2*)&u;
        #pragma unroll
        for (int j = 0; j < 4; j++) {
            float2 f = __half22float2(hp[j]);
            hp[j] = __floats2half2_rn(f.x * qscale, f.y * qscale);
        }
        *(uint4*)&Qs[r * QSH + c] = u;
    }
    __syncthreads();

    uint32_t qf[4][4];
    #pragma unroll
    for (int ks = 0; ks < 4; ks++) {
        const int kk = ks * 16;
        qf[ks][0] = *(const uint32_t*)&Qs[(rm + lr) * QSH + kk + 2 * lc];
        qf[ks][1] = *(const uint32_t*)&Qs[(rm + lr + 8) * QSH + kk + 2 * lc];
        qf[ks][2] = *(const uint32_t*)&Qs[(rm + lr) * QSH + kk + 2 * lc + 8];
        qf[ks][3] = *(const uint32_t*)&Qs[(rm + lr + 8) * QSH + kk + 2 * lc + 8];
    }

    int srow[2], scol[2];
    #pragma unroll
    for (int i = 0; i < 2; i++) {
        const int idx = tid + i * 256;
        srow[i] = idx >> 3;
        scol[i] = (idx & 7) * 8;
    }
    const __half* kb0 = k + ((size_t)(b * Nn_)) * Cdim + h * Dd;
    const __half* vb0 = v + ((size_t)(b * Nn_)) * Cdim + h * Dd;

    uint4 kreg[2], vreg[2];
    #pragma unroll
    for (int i = 0; i < 2; i++) {
        kreg[i] = *(const uint4*)(kb0 + (size_t)srow[i] * Cdim + scol[i]);
        vreg[i] = *(const uint4*)(vb0 + (size_t)srow[i] * Cdim + scol[i]);
    }

    float m0 = -1e30f, m1 = -1e30f, l0 = 0.f, l1 = 0.f;
    float oacc[8][4];
    #pragma unroll
    for (int nt = 0; nt < 8; nt++)
        #pragma unroll
        for (int r = 0; r < 4; r++) oacc[nt][r] = 0.f;

    for (int kv0 = 0; kv0 < Nn_; kv0 += 64) {
        __syncthreads();
        #pragma unroll
        for (int i = 0; i < 2; i++) {
            *(uint4*)&Ks[srow[i] * QSH + scol[i]] = kreg[i];
            const __half* vh = (const __half*)&vreg[i];
            #pragma unroll
            for (int j = 0; j < 8; j++)
                Vt[(scol[i] + j) * QSH + srow[i]] = vh[j];
        }
        __syncthreads();

        if (kv0 + 64 < Nn_) {
            const __half* kb = kb0 + (size_t)(kv0 + 64) * Cdim;
            const __half* vb = vb0 + (size_t)(kv0 + 64) * Cdim;
            #pragma unroll
            for (int i = 0; i < 2; i++) {
                kreg[i] = *(const uint4*)(kb + (size_t)srow[i] * Cdim + scol[i]);
                vreg[i] = *(const uint4*)(vb + (size_t)srow[i] * Cdim + scol[i]);
            }
        }

        float sacc[8][4];
        #pragma unroll
        for (int nt = 0; nt < 8; nt++)
            #pragma unroll
            for (int r = 0; r < 4; r++) sacc[nt][r] = 0.f;
        #pragma unroll
        for (int ks = 0; ks < 4; ks++) {
            const int kk = ks * 16;
            #pragma unroll
            for (int nt = 0; nt < 8; nt++) {
                uint32_t bf[2];
                bf[0] = *(const uint32_t*)&Ks[(nt * 8 + lr) * QSH + kk + 2 * lc];
                bf[1] = *(const uint32_t*)&Ks[(nt * 8 + lr) * QSH + kk + 2 * lc + 8];
                MMA_F16(sacc[nt], qf[ks], bf);
            }
        }

        float mx0 = -1e30f, mx1 = -1e30f;
        #pragma unroll
        for (int nt = 0; nt < 8; nt++) {
            mx0 = fmaxf(mx0, fmaxf(sacc[nt][0], sacc[nt][1]));
            mx1 = fmaxf(mx1, fmaxf(sacc[nt][2], sacc[nt][3]));
        }
        #pragma unroll
        for (int o = 1; o < 4; o <<= 1) {
            mx0 = fmaxf(mx0, __shfl_xor_sync(0xffffffffu, mx0, o, 4));
            mx1 = fmaxf(mx1, __shfl_xor_sync(0xffffffffu, mx1, o, 4));
        }
        const float mn0 = fmaxf(m0, mx0);
        const float mn1 = fmaxf(m1, mx1);
        const float al0 = exp2f(m0 - mn0);
        const float al1 = exp2f(m1 - mn1);
        float rs0 = 0.f, rs1 = 0.f;
        uint32_t pf[4][4];
        #pragma unroll
        for (int ks = 0; ks < 4; ks++) {
            const int ntA = 2 * ks, ntB = 2 * ks + 1;
            __half2 d0 = __floats2half2_rn(sacc[ntA][0] - mn0, sacc[ntA][1] - mn0);
            __half2 d1 = __floats2half2_rn(sacc[ntA][2] - mn1, sacc[ntA][3] - mn1);
            __half2 d2 = __floats2half2_rn(sacc[ntB][0] - mn0, sacc[ntB][1] - mn0);
            __half2 d3 = __floats2half2_rn(sacc[ntB][2] - mn1, sacc[ntB][3] - mn1);
            EX2_F16X2(pf[ks][0], h2u(d0));
            EX2_F16X2(pf[ks][1], h2u(d1));
            EX2_F16X2(pf[ks][2], h2u(d2));
            EX2_F16X2(pf[ks][3], h2u(d3));
            const float2 f0 = __half22float2(*(__half2*)&pf[ks][0]);
            const float2 f1 = __half22float2(*(__half2*)&pf[ks][1]);
            const float2 f2 = __half22float2(*(__half2*)&pf[ks][2]);
            const float2 f3 = __half22float2(*(__half2*)&pf[ks][3]);
            rs0 += f0.x + f0.y + f2.x + f2.y;
            rs1 += f1.x + f1.y + f3.x + f3.y;
        }
        #pragma unroll
        for (int o = 1; o < 4; o <<= 1) {
            rs0 += __shfl_xor_sync(0xffffffffu, rs0, o, 4);
            rs1 += __shfl_xor_sync(0xffffffffu, rs1, o, 4);
        }
        l0 = l0 * al0 + rs0;  m0 = mn0;
        l1 = l1 * al1 + rs1;  m1 = mn1;
        #pragma unroll
        for (int nt = 0; nt < 8; nt++) {
            oacc[nt][0] *= al0; oacc[nt][1] *= al0;
            oacc[nt][2] *= al1; oacc[nt][3] *= al1;
        }

        #pragma unroll
        for (int ks = 0; ks < 4; ks++) {
            const int kk = ks * 16;
            #pragma unroll
            for (int nt = 0; nt < 8; nt++) {
                uint32_t bf[2];
                bf[0] = *(const uint32_t*)&Vt[(nt * 8 + lr) * QSH + kk + 2 * lc];
                bf[1] = *(const uint32_t*)&Vt[(nt * 8 + lr) * QSH + kk + 2 * lc + 8];
                MMA_F16(oacc[nt], pf[ks], bf);
            }
        }
    }

    const float il0 = 1.0f / l0;
    const float il1 = 1.0f / l1;
    __half* ob = out + ((size_t)(b * Nn_ + q0 + rm)) * Cdim + h * Dd;
    #pragma unroll
    for (int nt = 0; nt < 8; nt++) {
        const int col = nt * 8 + 2 * lc;
        *(uint32_t*)(ob + (size_t)lr * Cdim + col) =
            h2u(__floats2half2_rn(oacc[nt][0] * il0, oacc[nt][1] * il0));
        *(uint32_t*)(ob + (size_t)(lr + 8) * Cdim + col) =
            h2u(__floats2half2_rn(oacc[nt][2] * il1, oacc[nt][3] * il1));
    }
}

// ---------------------------------------------------------------------------
extern "C" void kernel_launch(void* const* d_in, const int* in_sizes, int n_in,
                              void* d_out, int out_size)
{
    const float* x    = (const float*)d_in[0];
    const float* rcos = (const float*)d_in[1];
    const float* rsin = (const float*)d_in[2];
    const float* g1   = (const float*)d_in[3];
    const float* be1  = (const float*)d_in[4];
    const float* Wq   = (const float*)d_in[5];
    const float* bq   = (const float*)d_in[6];
    const float* Wk   = (const float*)d_in[7];
    const float* bk   = (const float*)d_in[8];
    const float* Wv   = (const float*)d_in[9];
    const float* bv   = (const float*)d_in[10];
    const float* Wo   = (const float*)d_in[11];
    const float* bo   = (const float*)d_in[12];
    const float* g2   = (const float*)d_in[13];
    const float* be2  = (const float*)d_in[14];
    const float* W1   = (const float*)d_in[15];
    const float* b1   = (const float*)d_in[16];
    const float* W2   = (const float*)d_in[17];
    const float* b2   = (const float*)d_in[18];
    float* out = (float*)d_out;

    unsigned char* base = nullptr;
    cudaGetSymbolAddress((void**)&base, g_scratch);
    __half* p_h   = (__half*)(base + OFF_H);
    __half* p_q   = (__half*)(base + OFF_Q);
    __half* p_k   = (__half*)(base + OFF_K);
    __half* p_v   = (__half*)(base + OFF_V);
    __half* p_att = (__half*)(base + OFF_ATT);
    __half* p_mlp = (__half*)(base + OFF_MLP);
    float*  p_x2  = (float*)(base + OFF_X2);
    __half* p_wq  = (__half*)(base + OFF_WQ);
    __half* p_wk  = (__half*)(base + OFF_WK);
    __half* p_wv  = (__half*)(base + OFF_WV);
    __half* p_wo  = (__half*)(base + OFF_WO);
    __half* p_w1  = (__half*)(base + OFF_W1);
    __half* p_w2  = (__half*)(base + OFF_W2);

    cudaFuncSetAttribute(flash_kernel,
                         cudaFuncAttributeMaxDynamicSharedMemorySize, FLASH_SMEM);
    cudaFuncSetAttribute(hgemm_kernel,
                         cudaFuncAttributeMaxDynamicSharedMemorySize, GEMM_SMEM);

    // 0. weights -> fp16
    const int nC4 = (Cdim * Cdim) / 4;
    const int nF4 = (Cdim * Fdim) / 4;
    ConvSet cs;
    cs.in[0] = (const float4*)Wq; cs.out[0] = (__half2*)p_wq;
    cs.in[1] = (const float4*)Wk; cs.out[1] = (__half2*)p_wk;
    cs.in[2] = (const float4*)Wv; cs.out[2] = (__half2*)p_wv;
    cs.in[3] = (const float4*)Wo; cs.out[3] = (__half2*)p_wo;
    cs.in[4] = (const float4*)W1; cs.out[4] = (__half2*)p_w1;
    cs.in[5] = (const float4*)W2; cs.out[5] = (__half2*)p_w2;
    cs.start[0] = 0;
    cs.start[1] = nC4;
    cs.start[2] = 2 * nC4;
    cs.start[3] = 3 * nC4;
    cs.start[4] = 4 * nC4;
    cs.start[5] = 4 * nC4 + nF4;
    cs.start[6] = 4 * nC4 + 2 * nF4;
    conv_half_kernel<<<3072, 256>>>(cs);

    // 1. LN1 -> half
    ln_kernel<<<Mrows, 256>>>(x, g1, be1, p_h);

    // 2. fused QKV projections -> half
    GemmSet qkv;
    qkv.W[0] = p_wq; qkv.W[1] = p_wk; qkv.W[2] = p_wv;
    qkv.bias[0] = bq; qkv.bias[1] = bk; qkv.bias[2] = bv;
    qkv.out[0] = p_q; qkv.out[1] = p_k; qkv.out[2] = p_v;
    hgemm_kernel<<<dim3(Cdim / 128, Mrows / 128, 3), 128, GEMM_SMEM>>>(
        p_h, qkv, nullptr, Mrows, Cdim, Cdim, 0, 1);

    // 3. RoPE
    rope2_kernel<<<dim3((Bb * Nn_ * Hh * 4) / 256, 1, 2), 256>>>(p_q, p_k, rcos, rsin);

    // 4. attention -> half
    flash_kernel<<<dim3(Nn_ / 128, Bb * Hh), 256, FLASH_SMEM>>>(p_q, p_k, p_v, p_att);

    // 5. output projection + fp32 residual -> fp32 x2
    GemmSet so;
    so.W[0] = p_wo; so.bias[0] = bo; so.out[0] = p_x2;
    so.W[1] = so.W[2] = nullptr; so.bias[1] = so.bias[2] = nullptr;
    so.out[1] = so.out[2] = nullptr;
    hgemm_kernel<<<dim3(Cdim / 128, Mrows / 128, 1), 128, GEMM_SMEM>>>(
        p_att, so, x, Mrows, Cdim, Cdim, 0, 0);

    // 6. LN2 -> half
    ln_kernel<<<Mrows, 256>>>(p_x2, g2, be2, p_h);

    // 7. MLP up + GELU -> half
    GemmSet s1;
    s1.W[0] = p_w1; s1.bias[0] = b1; s1.out[0] = p_mlp;
    s1.W[1] = s1.W[2] = nullptr; s1.bias[1] = s1.bias[2] = nullptr;
    s1.out[1] = s1.out[2] = nullptr;
    hgemm_kernel<<<dim3(Fdim / 128, Mrows / 128, 1), 128, GEMM_SMEM>>>(
        p_h, s1, nullptr, Mrows, Fdim, Cdim, 1, 1);

    // 8. MLP down + fp32 residual -> fp32 output
    GemmSet s2;
    s2.W[0] = p_w2; s2.bias[0] = b2; s2.out[0] = out;
    s2.W[1] = s2.W[2] = nullptr; s2.bias[1] = s2.bias[2] = nullptr;
    s2.out[1] = s2.out[2] = nullptr;
    hgemm_kernel<<<dim3(Cdim / 128, Mrows / 128, 1), 128, GEMM_SMEM>>>(
        p_mlp, s2, p_x2, Mrows, Cdim, Fdim, 0, 0);
}

// round 15
// speedup vs baseline: 2.0369x; 1.0206x over previous
#include <cuda_runtime.h>
#include <cuda_fp16.h>
#include <stdint.h>
#include <math.h>

// ---------------------------------------------------------------------------
// DiT block. Round 15: flash B-operand fragments via ldmatrix.x4
// (128 LDS -> 32 LDSM per warp per kv-tile). Rest unchanged from R14.
//   B=2, N=2048, C=1024, H=16, D=64, F=4096, M=B*N=4096
// ---------------------------------------------------------------------------

#define Mrows 4096
#define Cdim  1024
#define Fdim  4096
#define Bb    2
#define Hh    16
#define Dd    64
#define Nn_   2048

// byte offsets into scratch
#define OFF_H   ((size_t)0)
#define OFF_Q   ((size_t)8388608)
#define OFF_K   ((size_t)16777216)
#define OFF_V   ((size_t)25165824)
#define OFF_ATT ((size_t)33554432)
#define OFF_MLP ((size_t)41943040)
#define OFF_X2  ((size_t)75497472)
#define OFF_WQ  ((size_t)92274688)
#define OFF_WK  ((size_t)94371840)
#define OFF_WV  ((size_t)96468992)
#define OFF_WO  ((size_t)98566144)
#define OFF_W1  ((size_t)100663296)
#define OFF_W2  ((size_t)109051904)
__device__ __align__(1024) unsigned char g_scratch[117440512];

__device__ __forceinline__ uint32_t h2u(__half2 h) {
    return *reinterpret_cast<uint32_t*>(&h);
}

#define MMA_F16(d, a, b)                                                      \
    asm volatile(                                                             \
        "mma.sync.aligned.m16n8k16.row.col.f32.f16.f16.f32 "                  \
        "{%0,%1,%2,%3}, {%4,%5,%6,%7}, {%8,%9}, {%0,%1,%2,%3};"               \
        : "+f"(d[0]), "+f"(d[1]), "+f"(d[2]), "+f"(d[3])                      \
        : "r"(a[0]), "r"(a[1]), "r"(a[2]), "r"(a[3]), "r"(b[0]), "r"(b[1]))

#define CP_ASYNC16(dst_u32, src_ptr)                                          \
    asm volatile("cp.async.cg.shared.global [%0], [%1], 16;"                  \
                 :: "r"(dst_u32), "l"(src_ptr))
#define CP_COMMIT()  asm volatile("cp.async.commit_group;")
#define CP_WAIT(n)   asm volatile("cp.async.wait_group %0;" :: "n"(n))

#define EX2_F16X2(out_u32, in_u32)                                            \
    asm("ex2.approx.f16x2 %0, %1;" : "=r"(out_u32) : "r"(in_u32))

#define LDSM_X4(r0, r1, r2, r3, addr)                                         \
    asm volatile("ldmatrix.sync.aligned.m8n8.x4.shared.b16 "                  \
                 "{%0,%1,%2,%3}, [%4];"                                       \
                 : "=r"(r0), "=r"(r1), "=r"(r2), "=r"(r3) : "r"(addr))

// ---------------------------------------------------------------------------
// Weight conversion fp32 -> fp16 (RN), flat balanced grid-stride.
// ---------------------------------------------------------------------------
struct ConvSet {
    const float4* in[6];
    __half2*      out[6];
    int           start[7];
};

__global__ void __launch_bounds__(256) conv_half_kernel(ConvSet cs)
{
    const int total = cs.start[6];
    const int stride = gridDim.x * 256;
    for (int i = blockIdx.x * 256 + threadIdx.x; i < total; i += stride) {
        int z = 0;
        #pragma unroll
        for (int j = 1; j < 6; j++) z = (i >= cs.start[j]) ? j : z;
        const int li = i - cs.start[z];
        const float4 v = cs.in[z][li];
        __half2 h01 = __floats2half2_rn(v.x, v.y);
        __half2 h23 = __floats2half2_rn(v.z, v.w);
        uint2 u; u.x = h2u(h01); u.y = h2u(h23);
        *(uint2*)&cs.out[z][2 * li] = u;
    }
}

// ---------------------------------------------------------------------------
// LayerNorm: one block (256 thr) per row of 1024. fp32 in, fp16 out.
// ---------------------------------------------------------------------------
__global__ void __launch_bounds__(256) ln_kernel(
    const float* __restrict__ x, const float* __restrict__ g,
    const float* __restrict__ b, __half* __restrict__ out)
{
    __shared__ float red[16];
    const int row = blockIdx.x;
    const int t = threadIdx.x;
    const float4 xv = ((const float4*)(x + (size_t)row * Cdim))[t];
    float s  = xv.x + xv.y + xv.z + xv.w;
    float ss = xv.x*xv.x + xv.y*xv.y + xv.z*xv.z + xv.w*xv.w;
    #pragma unroll
    for (int o = 16; o > 0; o >>= 1) {
        s  += __shfl_xor_sync(0xffffffffu, s,  o);
        ss += __shfl_xor_sync(0xffffffffu, ss, o);
    }
    const int w = t >> 5;
    if ((t & 31) == 0) { red[w] = s; red[8 + w] = ss; }
    __syncthreads();
    float ts = 0.f, tss = 0.f;
    #pragma unroll
    for (int i = 0; i < 8; i++) { ts += red[i]; tss += red[8 + i]; }
    const float mean = ts * (1.0f / Cdim);
    const float var  = tss * (1.0f / Cdim) - mean * mean;
    const float inv  = rsqrtf(var + 1e-6f);
    const float4 gv = ((const float4*)g)[t];
    const float4 bv = ((const float4*)b)[t];
    __half2 h01 = __floats2half2_rn((xv.x - mean) * inv * gv.x + bv.x,
                                    (xv.y - mean) * inv * gv.y + bv.y);
    __half2 h23 = __floats2half2_rn((xv.z - mean) * inv * gv.z + bv.z,
                                    (xv.w - mean) * inv * gv.w + bv.w);
    uint2 u; u.x = h2u(h01); u.y = h2u(h23);
    *(uint2*)(out + (size_t)row * Cdim + 4 * t) = u;
}

// ---------------------------------------------------------------------------
// fp16 GEMM (unchanged from R14): 3-stage cp.async, 128x128 CTA tile, BK=32,
// 4 warps (2Mx2N), warp tile 64x64, ldmatrix fragments.
// ---------------------------------------------------------------------------
#define GSH 40
#define TBUFH (128 * GSH)
#define BOFFH (3 * TBUFH)
#define GEMM_SMEM (6 * TBUFH * 2)

struct GemmSet {
    const __half* W[3];
    const float*  bias[3];
    void*         out[3];
};

__global__ void __launch_bounds__(128, 2) hgemm_kernel(
    const __half* __restrict__ A, GemmSet gs, const float* __restrict__ residual,
    int M, int Nc, int K, int gelu, int out_half)
{
    extern __shared__ __half smh[];
    const uint32_t sbase = (uint32_t)__cvta_generic_to_shared(smh);

    const int z = blockIdx.z;
    const __half* __restrict__ Wp  = gs.W[z];
    const float* __restrict__ bias = gs.bias[z];
    void* __restrict__ outp        = gs.out[z];

    const int tid  = threadIdx.x;
    const int wid  = tid >> 5;
    const int lane = tid & 31;
    const int lr   = lane >> 2;
    const int lc   = lane & 3;
    const int warpM = (wid & 1) * 64;
    const int warpN = (wid >> 1) * 64;
    const int bm = blockIdx.y * 128, bn = blockIdx.x * 128;

    const int a_row  = warpM + (lane & 15);
    const int a_col8 = (lane >> 4) * 8;
    const int b_row  = (lane & 7) + ((lane >> 4) & 1) * 8;
    const int b_col8 = ((lane >> 3) & 1) * 8;

    float acc[4][8][4];
    #pragma unroll
    for (int i = 0; i < 4; i++)
        #pragma unroll
        for (int j = 0; j < 8; j++)
            #pragma unroll
            for (int r = 0; r < 4; r++) acc[i][j][r] = 0.f;

    const int nk = K >> 5;

    #define LOAD_TILE(stg, k0)                                                \
    do {                                                                      \
        _Pragma("unroll")                                                     \
        for (int p = 0; p < 4; p++) {                                         \
            const int id = tid + p * 128;                                     \
            const int row = id >> 2;                                          \
            const int kc = id & 3;                                            \
            const uint32_t da = sbase + (uint32_t)(((stg) * TBUFH + row * GSH + kc * 8) * 2); \
            CP_ASYNC16(da, A + (size_t)(bm + row) * K + (k0) + kc * 8);       \
        }                                                                     \
        _Pragma("unroll")                                                     \
        for (int p = 0; p < 4; p++) {                                         \
            const int id = tid + p * 128;                                     \
            const int row = id >> 2;                                          \
            const int kc = id & 3;                                            \
            const uint32_t db = sbase + (uint32_t)((BOFFH + (stg) * TBUFH + row * GSH + kc * 8) * 2); \
            CP_ASYNC16(db, Wp + (size_t)(bn + row) * K + (k0) + kc * 8);      \
        }                                                                     \
    } while (0)

    LOAD_TILE(0, 0);
    CP_COMMIT();
    if (nk > 1) { LOAD_TILE(1, 32); }
    CP_COMMIT();

    int stg = 0;
    for (int kt = 0; kt < nk; kt++) {
        if (kt + 1 < nk) { CP_WAIT(1); } else { CP_WAIT(0); }
        __syncthreads();

        if (kt + 2 < nk) {
            const int ns = (stg + 2 >= 3) ? stg - 1 : stg + 2;
            LOAD_TILE(ns, (kt + 2) << 5);
            CP_COMMIT();
        }

        const uint32_t aTile = sbase + (uint32_t)((stg * TBUFH) * 2);
        const uint32_t bTile = sbase + (uint32_t)((BOFFH + stg * TBUFH) * 2);
        #pragma unroll
        for (int ks = 0; ks < 2; ks++) {
            const int kk = ks * 16;
            uint32_t af[4][4], bf[8][2];
            #pragma unroll
            for (int i = 0; i < 4; i++) {
                const uint32_t addr = aTile +
                    (uint32_t)(((a_row + i * 16) * GSH + kk + a_col8) * 2);
                LDSM_X4(af[i][0], af[i][1], af[i][2], af[i][3], addr);
            }
            #pragma unroll
            for (int jp = 0; jp < 4; jp++) {
                const int cb = warpN + jp * 16;
                const uint32_t addr = bTile +
                    (uint32_t)(((cb + b_row) * GSH + kk + b_col8) * 2);
                LDSM_X4(bf[2 * jp][0], bf[2 * jp][1],
                        bf[2 * jp + 1][0], bf[2 * jp + 1][1], addr);
            }
            #pragma unroll
            for (int i = 0; i < 4; i++)
                #pragma unroll
                for (int j = 0; j < 8; j++)
                    MMA_F16(acc[i][j], af[i], bf[j]);
        }
        stg = (stg + 1 >= 3) ? 0 : stg + 1;
    }

    #pragma unroll
    for (int i = 0; i < 4; i++) {
        const int row0 = bm + warpM + i * 16 + lr;
        #pragma unroll
        for (int j = 0; j < 8; j++) {
            const int col = bn + warpN + j * 8 + (lc << 1);
            const float b0 = __ldg(&bias[col]);
            const float b1 = __ldg(&bias[col + 1]);
            float v0 = acc[i][j][0] + b0;
            float v1 = acc[i][j][1] + b1;
            float v2 = acc[i][j][2] + b0;
            float v3 = acc[i][j][3] + b1;
            if (gelu) {
                v0 = 0.5f * v0 * (1.0f + erff(v0 * 0.70710678118654752f));
                v1 = 0.5f * v1 * (1.0f + erff(v1 * 0.70710678118654752f));
                v2 = 0.5f * v2 * (1.0f + erff(v2 * 0.70710678118654752f));
                v3 = 0.5f * v3 * (1.0f + erff(v3 * 0.70710678118654752f));
            }
            if (residual) {
                v0 += residual[(size_t)row0 * Nc + col];
                v1 += residual[(size_t)row0 * Nc + col + 1];
                v2 += residual[(size_t)(row0 + 8) * Nc + col];
                v3 += residual[(size_t)(row0 + 8) * Nc + col + 1];
            }
            if (out_half) {
                __half* oh = (__half*)outp;
                *(uint32_t*)(oh + (size_t)row0 * Nc + col)       = h2u(__floats2half2_rn(v0, v1));
                *(uint32_t*)(oh + (size_t)(row0 + 8) * Nc + col) = h2u(__floats2half2_rn(v2, v3));
            } else {
                float* of = (float*)outp;
                *(float2*)(of + (size_t)row0 * Nc + col)       = make_float2(v0, v1);
                *(float2*)(of + (size_t)(row0 + 8) * Nc + col) = make_float2(v2, v3);
            }
        }
    }
}

// ---------------------------------------------------------------------------
// Vectorized RoPE (unchanged)
// ---------------------------------------------------------------------------
__global__ void __launch_bounds__(256) rope2_kernel(
    __half* __restrict__ qp, __half* __restrict__ kp,
    const float* __restrict__ cosb, const float* __restrict__ sinb)
{
    __half* t = blockIdx.z ? kp : qp;
    int idx = blockIdx.x * 256 + threadIdx.x;
    const int ci = idx & 3; idx >>= 2;
    const int h = idx & (Hh - 1); idx >>= 4;
    const int n = idx & (Nn_ - 1); idx >>= 11;
    const int b = idx;
    const int c = ci * 8;
    const size_t base = ((size_t)(b * Nn_ + n)) * Cdim + h * Dd;

    uint4 lo = *(uint4*)(t + base + c);
    uint4 hi = *(uint4*)(t + base + c + 32);
    const __half* xl = (const __half*)&lo;
    const __half* xh = (const __half*)&hi;

    const float* cb = cosb + n * Dd;
    const float* sb = sinb + n * Dd;
    float cl[8], sl[8], ch[8], sh[8];
    *(float4*)&cl[0] = *(const float4*)(cb + c);
    *(float4*)&cl[4] = *(const float4*)(cb + c + 4);
    *(float4*)&ch[0] = *(const float4*)(cb + c + 32);
    *(float4*)&ch[4] = *(const float4*)(cb + c + 36);
    *(float4*)&sl[0] = *(const float4*)(sb + c);
    *(float4*)&sl[4] = *(const float4*)(sb + c + 4);
    *(float4*)&sh[0] = *(const float4*)(sb + c + 32);
    *(float4*)&sh[4] = *(const float4*)(sb + c + 36);

    uint4 olo, ohi;
    __half* ol = (__half*)&olo;
    __half* oh = (__half*)&ohi;
    #pragma unroll
    for (int j = 0; j < 8; j++) {
        const float x1 = __half2float(xl[j]);
        const float x2 = __half2float(xh[j]);
        ol[j] = __float2half_rn(x1 * cl[j] - x2 * sl[j]);
        oh[j] = __float2half_rn(x2 * ch[j] + x1 * sh[j]);
    }
    *(uint4*)(t + base + c)      = olo;
    *(uint4*)(t + base + c + 32) = ohi;
}

// ---------------------------------------------------------------------------
// Flash attention: fp16 mma, ex2.f16x2, P in registers, ldmatrix B-fragments.
// smem (halves): Qs[128][72], Ks[64][72], Vt[64][72]
// ---------------------------------------------------------------------------
#define QSH 72
#define F_QS 0
#define F_KS (128 * QSH)
#define F_VS (F_KS + 64 * QSH)
#define FLASH_SMEM ((F_VS + 64 * QSH) * 2)

__global__ void __launch_bounds__(256) flash_kernel(
    const __half* __restrict__ q, const __half* __restrict__ k,
    const __half* __restrict__ v, __half* __restrict__ out)
{
    extern __shared__ __half smf[];
    __half* Qs = smf + F_QS;
    __half* Ks = smf + F_KS;
    __half* Vt = smf + F_VS;
    const uint32_t sfbase = (uint32_t)__cvta_generic_to_shared(smf);
    const uint32_t ksBase = sfbase + F_KS * 2;
    const uint32_t vtBase = sfbase + F_VS * 2;

    const int tid  = threadIdx.x;
    const int wid  = tid >> 5;
    const int lane = tid & 31;
    const int lr   = lane >> 2;
    const int lc   = lane & 3;
    const int rm   = wid * 16;

    // ldmatrix B-operand lane mapping (same as hgemm)
    const int b_row  = (lane & 7) + ((lane >> 4) & 1) * 8;
    const int b_col8 = ((lane >> 3) & 1) * 8;

    const int bh = blockIdx.y;
    const int b = bh >> 4;
    const int h = bh & 15;
    const int q0 = blockIdx.x * 128;
    const float qscale = 0.125f * 1.4426950408889634f;

    const __half* qb = q + ((size_t)(b * Nn_ + q0)) * Cdim + h * Dd;
    #pragma unroll
    for (int i = 0; i < 4; i++) {
        const int idx = tid + i * 256;
        const int r = idx >> 3;
        const int c = (idx & 7) * 8;
        uint4 u = *(const uint4*)(qb + (size_t)r * Cdim + c);
        __half2* hp = (__half2*)&u;
        #pragma unroll
        for (int j = 0; j < 4; j++) {
            float2 f = __half22float2(hp[j]);
            hp[j] = __floats2half2_rn(f.x * qscale, f.y * qscale);
        }
        *(uint4*)&Qs[r * QSH + c] = u;
    }
    __syncthreads();

    uint32_t qf[4][4];
    #pragma unroll
    for (int ks = 0; ks < 4; ks++) {
        const int kk = ks * 16;
        qf[ks][0] = *(const uint32_t*)&Qs[(rm + lr) * QSH + kk + 2 * lc];
        qf[ks][1] = *(const uint32_t*)&Qs[(rm + lr + 8) * QSH + kk + 2 * lc];
        qf[ks][2] = *(const uint32_t*)&Qs[(rm + lr) * QSH + kk + 2 * lc + 8];
        qf[ks][3] = *(const uint32_t*)&Qs[(rm + lr + 8) * QSH + kk + 2 * lc + 8];
    }

    int srow[2], scol[2];
    #pragma unroll
    for (int i = 0; i < 2; i++) {
        const int idx = tid + i * 256;
        srow[i] = idx >> 3;
        scol[i] = (idx & 7) * 8;
    }
    const __half* kb0 = k + ((size_t)(b * Nn_)) * Cdim + h * Dd;
    const __half* vb0 = v + ((size_t)(b * Nn_)) * Cdim + h * Dd;

    uint4 kreg[2], vreg[2];
    #pragma unroll
    for (int i = 0; i < 2; i++) {
        kreg[i] = *(const uint4*)(kb0 + (size_t)srow[i] * Cdim + scol[i]);
        vreg[i] = *(const uint4*)(vb0 + (size_t)srow[i] * Cdim + scol[i]);
    }

    float m0 = -1e30f, m1 = -1e30f, l0 = 0.f, l1 = 0.f;
    float oacc[8][4];
    #pragma unroll
    for (int nt = 0; nt < 8; nt++)
        #pragma unroll
        for (int r = 0; r < 4; r++) oacc[nt][r] = 0.f;

    for (int kv0 = 0; kv0 < Nn_; kv0 += 64) {
        __syncthreads();
        #pragma unroll
        for (int i = 0; i < 2; i++) {
            *(uint4*)&Ks[srow[i] * QSH + scol[i]] = kreg[i];
            const __half* vh = (const __half*)&vreg[i];
            #pragma unroll
            for (int j = 0; j < 8; j++)
                Vt[(scol[i] + j) * QSH + srow[i]] = vh[j];
        }
        __syncthreads();

        if (kv0 + 64 < Nn_) {
            const __half* kb = kb0 + (size_t)(kv0 + 64) * Cdim;
            const __half* vb = vb0 + (size_t)(kv0 + 64) * Cdim;
            #pragma unroll
            for (int i = 0; i < 2; i++) {
                kreg[i] = *(const uint4*)(kb + (size_t)srow[i] * Cdim + scol[i]);
                vreg[i] = *(const uint4*)(vb + (size_t)srow[i] * Cdim + scol[i]);
            }
        }

        // S = Qs @ Ks^T  (ldmatrix B fragments)
        float sacc[8][4];
        #pragma unroll
        for (int nt = 0; nt < 8; nt++)
            #pragma unroll
            for (int r = 0; r < 4; r++) sacc[nt][r] = 0.f;
        #pragma unroll
        for (int ks = 0; ks < 4; ks++) {
            const int kk = ks * 16;
            uint32_t bf[8][2];
            #pragma unroll
            for (int jp = 0; jp < 4; jp++) {
                const uint32_t addr = ksBase +
                    (uint32_t)(((jp * 16 + b_row) * QSH + kk + b_col8) * 2);
                LDSM_X4(bf[2 * jp][0], bf[2 * jp][1],
                        bf[2 * jp + 1][0], bf[2 * jp + 1][1], addr);
            }
            #pragma unroll
            for (int nt = 0; nt < 8; nt++)
                MMA_F16(sacc[nt], qf[ks], bf[nt]);
        }

        // online softmax; P via ex2.approx.f16x2
        float mx0 = -1e30f, mx1 = -1e30f;
        #pragma unroll
        for (int nt = 0; nt < 8; nt++) {
            mx0 = fmaxf(mx0, fmaxf(sacc[nt][0], sacc[nt][1]));
            mx1 = fmaxf(mx1, fmaxf(sacc[nt][2], sacc[nt][3]));
        }
        #pragma unroll
        for (int o = 1; o < 4; o <<= 1) {
            mx0 = fmaxf(mx0, __shfl_xor_sync(0xffffffffu, mx0, o, 4));
            mx1 = fmaxf(mx1, __shfl_xor_sync(0xffffffffu, mx1, o, 4));
        }
        const float mn0 = fmaxf(m0, mx0);
        const float mn1 = fmaxf(m1, mx1);
        const float al0 = exp2f(m0 - mn0);
        const float al1 = exp2f(m1 - mn1);
        float rs0 = 0.f, rs1 = 0.f;
        uint32_t pf[4][4];
        #pragma unroll
        for (int ks = 0; ks < 4; ks++) {
            const int ntA = 2 * ks, ntB = 2 * ks + 1;
            __half2 d0 = __floats2half2_rn(sacc[ntA][0] - mn0, sacc[ntA][1] - mn0);
            __half2 d1 = __floats2half2_rn(sacc[ntA][2] - mn1, sacc[ntA][3] - mn1);
            __half2 d2 = __floats2half2_rn(sacc[ntB][0] - mn0, sacc[ntB][1] - mn0);
            __half2 d3 = __floats2half2_rn(sacc[ntB][2] - mn1, sacc[ntB][3] - mn1);
            EX2_F16X2(pf[ks][0], h2u(d0));
            EX2_F16X2(pf[ks][1], h2u(d1));
            EX2_F16X2(pf[ks][2], h2u(d2));
            EX2_F16X2(pf[ks][3], h2u(d3));
            const float2 f0 = __half22float2(*(__half2*)&pf[ks][0]);
            const float2 f1 = __half22float2(*(__half2*)&pf[ks][1]);
            const float2 f2 = __half22float2(*(__half2*)&pf[ks][2]);
            const float2 f3 = __half22float2(*(__half2*)&pf[ks][3]);
            rs0 += f0.x + f0.y + f2.x + f2.y;
            rs1 += f1.x + f1.y + f3.x + f3.y;
        }
        #pragma unroll
        for (int o = 1; o < 4; o <<= 1) {
            rs0 += __shfl_xor_sync(0xffffffffu, rs0, o, 4);
            rs1 += __shfl_xor_sync(0xffffffffu, rs1, o, 4);
        }
        l0 = l0 * al0 + rs0;  m0 = mn0;
        l1 = l1 * al1 + rs1;  m1 = mn1;
        #pragma unroll
        for (int nt = 0; nt < 8; nt++) {
            oacc[nt][0] *= al0; oacc[nt][1] *= al0;
            oacc[nt][2] *= al1; oacc[nt][3] *= al1;
        }

        // O += P @ Vt  (ldmatrix B fragments)
        #pragma unroll
        for (int ks = 0; ks < 4; ks++) {
            const int kk = ks * 16;
            uint32_t bf[8][2];
            #pragma unroll
            for (int jp = 0; jp < 4; jp++) {
                const uint32_t addr = vtBase +
                    (uint32_t)(((jp * 16 + b_row) * QSH + kk + b_col8) * 2);
                LDSM_X4(bf[2 * jp][0], bf[2 * jp][1],
                        bf[2 * jp + 1][0], bf[2 * jp + 1][1], addr);
            }
            #pragma unroll
            for (int nt = 0; nt < 8; nt++)
                MMA_F16(oacc[nt], pf[ks], bf[nt]);
        }
    }

    const float il0 = 1.0f / l0;
    const float il1 = 1.0f / l1;
    __half* ob = out + ((size_t)(b * Nn_ + q0 + rm)) * Cdim + h * Dd;
    #pragma unroll
    for (int nt = 0; nt < 8; nt++) {
        const int col = nt * 8 + 2 * lc;
        *(uint32_t*)(ob + (size_t)lr * Cdim + col) =
            h2u(__floats2half2_rn(oacc[nt][0] * il0, oacc[nt][1] * il0));
        *(uint32_t*)(ob + (size_t)(lr + 8) * Cdim + col) =
            h2u(__floats2half2_rn(oacc[nt][2] * il1, oacc[nt][3] * il1));
    }
}

// ---------------------------------------------------------------------------
extern "C" void kernel_launch(void* const* d_in, const int* in_sizes, int n_in,
                              void* d_out, int out_size)
{
    const float* x    = (const float*)d_in[0];
    const float* rcos = (const float*)d_in[1];
    const float* rsin = (const float*)d_in[2];
    const float* g1   = (const float*)d_in[3];
    const float* be1  = (const float*)d_in[4];
    const float* Wq   = (const float*)d_in[5];
    const float* bq   = (const float*)d_in[6];
    const float* Wk   = (const float*)d_in[7];
    const float* bk   = (const float*)d_in[8];
    const float* Wv   = (const float*)d_in[9];
    const float* bv   = (const float*)d_in[10];
    const float* Wo   = (const float*)d_in[11];
    const float* bo   = (const float*)d_in[12];
    const float* g2   = (const float*)d_in[13];
    const float* be2  = (const float*)d_in[14];
    const float* W1   = (const float*)d_in[15];
    const float* b1   = (const float*)d_in[16];
    const float* W2   = (const float*)d_in[17];
    const float* b2   = (const float*)d_in[18];
    float* out = (float*)d_out;

    unsigned char* base = nullptr;
    cudaGetSymbolAddress((void**)&base, g_scratch);
    __half* p_h   = (__half*)(base + OFF_H);
    __half* p_q   = (__half*)(base + OFF_Q);
    __half* p_k   = (__half*)(base + OFF_K);
    __half* p_v   = (__half*)(base + OFF_V);
    __half* p_att = (__half*)(base + OFF_ATT);
    __half* p_mlp = (__half*)(base + OFF_MLP);
    float*  p_x2  = (float*)(base + OFF_X2);
    __half* p_wq  = (__half*)(base + OFF_WQ);
    __half* p_wk  = (__half*)(base + OFF_WK);
    __half* p_wv  = (__half*)(base + OFF_WV);
    __half* p_wo  = (__half*)(base + OFF_WO);
    __half* p_w1  = (__half*)(base + OFF_W1);
    __half* p_w2  = (__half*)(base + OFF_W2);

    cudaFuncSetAttribute(flash_kernel,
                         cudaFuncAttributeMaxDynamicSharedMemorySize, FLASH_SMEM);
    cudaFuncSetAttribute(hgemm_kernel,
                         cudaFuncAttributeMaxDynamicSharedMemorySize, GEMM_SMEM);

    // 0. weights -> fp16
    const int nC4 = (Cdim * Cdim) / 4;
    const int nF4 = (Cdim * Fdim) / 4;
    ConvSet cs;
    cs.in[0] = (const float4*)Wq; cs.out[0] = (__half2*)p_wq;
    cs.in[1] = (const float4*)Wk; cs.out[1] = (__half2*)p_wk;
    cs.in[2] = (const float4*)Wv; cs.out[2] = (__half2*)p_wv;
    cs.in[3] = (const float4*)Wo; cs.out[3] = (__half2*)p_wo;
    cs.in[4] = (const float4*)W1; cs.out[4] = (__half2*)p_w1;
    cs.in[5] = (const float4*)W2; cs.out[5] = (__half2*)p_w2;
    cs.start[0] = 0;
    cs.start[1] = nC4;
    cs.start[2] = 2 * nC4;
    cs.start[3] = 3 * nC4;
    cs.start[4] = 4 * nC4;
    cs.start[5] = 4 * nC4 + nF4;
    cs.start[6] = 4 * nC4 + 2 * nF4;
    conv_half_kernel<<<3072, 256>>>(cs);

    // 1. LN1 -> half
    ln_kernel<<<Mrows, 256>>>(x, g1, be1, p_h);

    // 2. fused QKV projections -> half
    GemmSet qkv;
    qkv.W[0] = p_wq; qkv.W[1] = p_wk; qkv.W[2] = p_wv;
    qkv.bias[0] = bq; qkv.bias[1] = bk; qkv.bias[2] = bv;
    qkv.out[0] = p_q; qkv.out[1] = p_k; qkv.out[2] = p_v;
    hgemm_kernel<<<dim3(Cdim / 128, Mrows / 128, 3), 128, GEMM_SMEM>>>(
        p_h, qkv, nullptr, Mrows, Cdim, Cdim, 0, 1);

    // 3. RoPE
    rope2_kernel<<<dim3((Bb * Nn_ * Hh * 4) / 256, 1, 2), 256>>>(p_q, p_k, rcos, rsin);

    // 4. attention -> half
    flash_kernel<<<dim3(Nn_ / 128, Bb * Hh), 256, FLASH_SMEM>>>(p_q, p_k, p_v, p_att);

    // 5. output projection + fp32 residual -> fp32 x2
    GemmSet so;
    so.W[0] = p_wo; so.bias[0] = bo; so.out[0] = p_x2;
    so.W[1] = so.W[2] = nullptr; so.bias[1] = so.bias[2] = nullptr;
    so.out[1] = so.out[2] = nullptr;
    hgemm_kernel<<<dim3(Cdim / 128, Mrows / 128, 1), 128, GEMM_SMEM>>>(
        p_att, so, x, Mrows, Cdim, Cdim, 0, 0);

    // 6. LN2 -> half
    ln_kernel<<<Mrows, 256>>>(p_x2, g2, be2, p_h);

    // 7. MLP up + GELU -> half
    GemmSet s1;
    s1.W[0] = p_w1; s1.bias[0] = b1; s1.out[0] = p_mlp;
    s1.W[1] = s1.W[2] = nullptr; s1.bias[1] = s1.bias[2] = nullptr;
    s1.out[1] = s1.out[2] = nullptr;
    hgemm_kernel<<<dim3(Fdim / 128, Mrows / 128, 1), 128, GEMM_SMEM>>>(
        p_h, s1, nullptr, Mrows, Fdim, Cdim, 1, 1);

    // 8. MLP down + fp32 residual -> fp32 output
    GemmSet s2;
    s2.W[0] = p_w2; s2.bias[0] = b2; s2.out[0] = out;
    s2.W[1] = s2.W[2] = nullptr; s2.bias[1] = s2.bias[2] = nullptr;
    s2.out[1] = s2.out[2] = nullptr;
    hgemm_kernel<<<dim3(Cdim / 128, Mrows / 128, 1), 128, GEMM_SMEM>>>(
        p_mlp, s2, p_x2, Mrows, Cdim, Fdim, 0, 0);
}

// round 16
// speedup vs baseline: 2.2879x; 1.1233x over previous
#include <cuda_runtime.h>
#include <cuda_fp16.h>
#include <stdint.h>
#include <math.h>

// ---------------------------------------------------------------------------
// DiT block. Round 16: flash K/V staged via 3-stage cp.async pipeline;
// V kept row-major, PV B-operands via ldmatrix.x4.trans (transpose deleted).
// Rest unchanged from R15.
//   B=2, N=2048, C=1024, H=16, D=64, F=4096, M=B*N=4096
// ---------------------------------------------------------------------------

#define Mrows 4096
#define Cdim  1024
#define Fdim  4096
#define Bb    2
#define Hh    16
#define Dd    64
#define Nn_   2048

// byte offsets into scratch
#define OFF_H   ((size_t)0)
#define OFF_Q   ((size_t)8388608)
#define OFF_K   ((size_t)16777216)
#define OFF_V   ((size_t)25165824)
#define OFF_ATT ((size_t)33554432)
#define OFF_MLP ((size_t)41943040)
#define OFF_X2  ((size_t)75497472)
#define OFF_WQ  ((size_t)92274688)
#define OFF_WK  ((size_t)94371840)
#define OFF_WV  ((size_t)96468992)
#define OFF_WO  ((size_t)98566144)
#define OFF_W1  ((size_t)100663296)
#define OFF_W2  ((size_t)109051904)
__device__ __align__(1024) unsigned char g_scratch[117440512];

__device__ __forceinline__ uint32_t h2u(__half2 h) {
    return *reinterpret_cast<uint32_t*>(&h);
}

#define MMA_F16(d, a, b)                                                      \
    asm volatile(                                                             \
        "mma.sync.aligned.m16n8k16.row.col.f32.f16.f16.f32 "                  \
        "{%0,%1,%2,%3}, {%4,%5,%6,%7}, {%8,%9}, {%0,%1,%2,%3};"               \
        : "+f"(d[0]), "+f"(d[1]), "+f"(d[2]), "+f"(d[3])                      \
        : "r"(a[0]), "r"(a[1]), "r"(a[2]), "r"(a[3]), "r"(b[0]), "r"(b[1]))

#define CP_ASYNC16(dst_u32, src_ptr)                                          \
    asm volatile("cp.async.cg.shared.global [%0], [%1], 16;"                  \
                 :: "r"(dst_u32), "l"(src_ptr))
#define CP_COMMIT()  asm volatile("cp.async.commit_group;")
#define CP_WAIT(n)   asm volatile("cp.async.wait_group %0;" :: "n"(n))

#define EX2_F16X2(out_u32, in_u32)                                            \
    asm("ex2.approx.f16x2 %0, %1;" : "=r"(out_u32) : "r"(in_u32))

#define LDSM_X4(r0, r1, r2, r3, addr)                                         \
    asm volatile("ldmatrix.sync.aligned.m8n8.x4.shared.b16 "                  \
                 "{%0,%1,%2,%3}, [%4];"                                       \
                 : "=r"(r0), "=r"(r1), "=r"(r2), "=r"(r3) : "r"(addr))

#define LDSM_X4_T(r0, r1, r2, r3, addr)                                       \
    asm volatile("ldmatrix.sync.aligned.m8n8.x4.trans.shared.b16 "            \
                 "{%0,%1,%2,%3}, [%4];"                                       \
                 : "=r"(r0), "=r"(r1), "=r"(r2), "=r"(r3) : "r"(addr))

// ---------------------------------------------------------------------------
// Weight conversion fp32 -> fp16 (RN), flat balanced grid-stride.
// ---------------------------------------------------------------------------
struct ConvSet {
    const float4* in[6];
    __half2*      out[6];
    int           start[7];
};

__global__ void __launch_bounds__(256) conv_half_kernel(ConvSet cs)
{
    const int total = cs.start[6];
    const int stride = gridDim.x * 256;
    for (int i = blockIdx.x * 256 + threadIdx.x; i < total; i += stride) {
        int z = 0;
        #pragma unroll
        for (int j = 1; j < 6; j++) z = (i >= cs.start[j]) ? j : z;
        const int li = i - cs.start[z];
        const float4 v = cs.in[z][li];
        __half2 h01 = __floats2half2_rn(v.x, v.y);
        __half2 h23 = __floats2half2_rn(v.z, v.w);
        uint2 u; u.x = h2u(h01); u.y = h2u(h23);
        *(uint2*)&cs.out[z][2 * li] = u;
    }
}

// ---------------------------------------------------------------------------
// LayerNorm: one block (256 thr) per row of 1024. fp32 in, fp16 out.
// ---------------------------------------------------------------------------
__global__ void __launch_bounds__(256) ln_kernel(
    const float* __restrict__ x, const float* __restrict__ g,
    const float* __restrict__ b, __half* __restrict__ out)
{
    __shared__ float red[16];
    const int row = blockIdx.x;
    const int t = threadIdx.x;
    const float4 xv = ((const float4*)(x + (size_t)row * Cdim))[t];
    float s  = xv.x + xv.y + xv.z + xv.w;
    float ss = xv.x*xv.x + xv.y*xv.y + xv.z*xv.z + xv.w*xv.w;
    #pragma unroll
    for (int o = 16; o > 0; o >>= 1) {
        s  += __shfl_xor_sync(0xffffffffu, s,  o);
        ss += __shfl_xor_sync(0xffffffffu, ss, o);
    }
    const int w = t >> 5;
    if ((t & 31) == 0) { red[w] = s; red[8 + w] = ss; }
    __syncthreads();
    float ts = 0.f, tss = 0.f;
    #pragma unroll
    for (int i = 0; i < 8; i++) { ts += red[i]; tss += red[8 + i]; }
    const float mean = ts * (1.0f / Cdim);
    const float var  = tss * (1.0f / Cdim) - mean * mean;
    const float inv  = rsqrtf(var + 1e-6f);
    const float4 gv = ((const float4*)g)[t];
    const float4 bv = ((const float4*)b)[t];
    __half2 h01 = __floats2half2_rn((xv.x - mean) * inv * gv.x + bv.x,
                                    (xv.y - mean) * inv * gv.y + bv.y);
    __half2 h23 = __floats2half2_rn((xv.z - mean) * inv * gv.z + bv.z,
                                    (xv.w - mean) * inv * gv.w + bv.w);
    uint2 u; u.x = h2u(h01); u.y = h2u(h23);
    *(uint2*)(out + (size_t)row * Cdim + 4 * t) = u;
}

// ---------------------------------------------------------------------------
// fp16 GEMM (unchanged from R15)
// ---------------------------------------------------------------------------
#define GSH 40
#define TBUFH (128 * GSH)
#define BOFFH (3 * TBUFH)
#define GEMM_SMEM (6 * TBUFH * 2)

struct GemmSet {
    const __half* W[3];
    const float*  bias[3];
    void*         out[3];
};

__global__ void __launch_bounds__(128, 2) hgemm_kernel(
    const __half* __restrict__ A, GemmSet gs, const float* __restrict__ residual,
    int M, int Nc, int K, int gelu, int out_half)
{
    extern __shared__ __half smh[];
    const uint32_t sbase = (uint32_t)__cvta_generic_to_shared(smh);

    const int z = blockIdx.z;
    const __half* __restrict__ Wp  = gs.W[z];
    const float* __restrict__ bias = gs.bias[z];
    void* __restrict__ outp        = gs.out[z];

    const int tid  = threadIdx.x;
    const int wid  = tid >> 5;
    const int lane = tid & 31;
    const int lr   = lane >> 2;
    const int lc   = lane & 3;
    const int warpM = (wid & 1) * 64;
    const int warpN = (wid >> 1) * 64;
    const int bm = blockIdx.y * 128, bn = blockIdx.x * 128;

    const int a_row  = warpM + (lane & 15);
    const int a_col8 = (lane >> 4) * 8;
    const int b_row  = (lane & 7) + ((lane >> 4) & 1) * 8;
    const int b_col8 = ((lane >> 3) & 1) * 8;

    float acc[4][8][4];
    #pragma unroll
    for (int i = 0; i < 4; i++)
        #pragma unroll
        for (int j = 0; j < 8; j++)
            #pragma unroll
            for (int r = 0; r < 4; r++) acc[i][j][r] = 0.f;

    const int nk = K >> 5;

    #define LOAD_TILE(stg, k0)                                                \
    do {                                                                      \
        _Pragma("unroll")                                                     \
        for (int p = 0; p < 4; p++) {                                         \
            const int id = tid + p * 128;                                     \
            const int row = id >> 2;                                          \
            const int kc = id & 3;                                            \
            const uint32_t da = sbase + (uint32_t)(((stg) * TBUFH + row * GSH + kc * 8) * 2); \
            CP_ASYNC16(da, A + (size_t)(bm + row) * K + (k0) + kc * 8);       \
        }                                                                     \
        _Pragma("unroll")                                                     \
        for (int p = 0; p < 4; p++) {                                         \
            const int id = tid + p * 128;                                     \
            const int row = id >> 2;                                          \
            const int kc = id & 3;                                            \
            const uint32_t db = sbase + (uint32_t)((BOFFH + (stg) * TBUFH + row * GSH + kc * 8) * 2); \
            CP_ASYNC16(db, Wp + (size_t)(bn + row) * K + (k0) + kc * 8);      \
        }                                                                     \
    } while (0)

    LOAD_TILE(0, 0);
    CP_COMMIT();
    if (nk > 1) { LOAD_TILE(1, 32); }
    CP_COMMIT();

    int stg = 0;
    for (int kt = 0; kt < nk; kt++) {
        if (kt + 1 < nk) { CP_WAIT(1); } else { CP_WAIT(0); }
        __syncthreads();

        if (kt + 2 < nk) {
            const int ns = (stg + 2 >= 3) ? stg - 1 : stg + 2;
            LOAD_TILE(ns, (kt + 2) << 5);
            CP_COMMIT();
        }

        const uint32_t aTile = sbase + (uint32_t)((stg * TBUFH) * 2);
        const uint32_t bTile = sbase + (uint32_t)((BOFFH + stg * TBUFH) * 2);
        #pragma unroll
        for (int ks = 0; ks < 2; ks++) {
            const int kk = ks * 16;
            uint32_t af[4][4], bf[8][2];
            #pragma unroll
            for (int i = 0; i < 4; i++) {
                const uint32_t addr = aTile +
                    (uint32_t)(((a_row + i * 16) * GSH + kk + a_col8) * 2);
                LDSM_X4(af[i][0], af[i][1], af[i][2], af[i][3], addr);
            }
            #pragma unroll
            for (int jp = 0; jp < 4; jp++) {
                const int cb = warpN + jp * 16;
                const uint32_t addr = bTile +
                    (uint32_t)(((cb + b_row) * GSH + kk + b_col8) * 2);
                LDSM_X4(bf[2 * jp][0], bf[2 * jp][1],
                        bf[2 * jp + 1][0], bf[2 * jp + 1][1], addr);
            }
            #pragma unroll
            for (int i = 0; i < 4; i++)
                #pragma unroll
                for (int j = 0; j < 8; j++)
                    MMA_F16(acc[i][j], af[i], bf[j]);
        }
        stg = (stg + 1 >= 3) ? 0 : stg + 1;
    }

    #pragma unroll
    for (int i = 0; i < 4; i++) {
        const int row0 = bm + warpM + i * 16 + lr;
        #pragma unroll
        for (int j = 0; j < 8; j++) {
            const int col = bn + warpN + j * 8 + (lc << 1);
            const float b0 = __ldg(&bias[col]);
            const float b1 = __ldg(&bias[col + 1]);
            float v0 = acc[i][j][0] + b0;
            float v1 = acc[i][j][1] + b1;
            float v2 = acc[i][j][2] + b0;
            float v3 = acc[i][j][3] + b1;
            if (gelu) {
                v0 = 0.5f * v0 * (1.0f + erff(v0 * 0.70710678118654752f));
                v1 = 0.5f * v1 * (1.0f + erff(v1 * 0.70710678118654752f));
                v2 = 0.5f * v2 * (1.0f + erff(v2 * 0.70710678118654752f));
                v3 = 0.5f * v3 * (1.0f + erff(v3 * 0.70710678118654752f));
            }
            if (residual) {
                v0 += residual[(size_t)row0 * Nc + col];
                v1 += residual[(size_t)row0 * Nc + col + 1];
                v2 += residual[(size_t)(row0 + 8) * Nc + col];
                v3 += residual[(size_t)(row0 + 8) * Nc + col + 1];
            }
            if (out_half) {
                __half* oh = (__half*)outp;
                *(uint32_t*)(oh + (size_t)row0 * Nc + col)       = h2u(__floats2half2_rn(v0, v1));
                *(uint32_t*)(oh + (size_t)(row0 + 8) * Nc + col) = h2u(__floats2half2_rn(v2, v3));
            } else {
                float* of = (float*)outp;
                *(float2*)(of + (size_t)row0 * Nc + col)       = make_float2(v0, v1);
                *(float2*)(of + (size_t)(row0 + 8) * Nc + col) = make_float2(v2, v3);
            }
        }
    }
}

// ---------------------------------------------------------------------------
// Vectorized RoPE (unchanged)
// ---------------------------------------------------------------------------
__global__ void __launch_bounds__(256) rope2_kernel(
    __half* __restrict__ qp, __half* __restrict__ kp,
    const float* __restrict__ cosb, const float* __restrict__ sinb)
{
    __half* t = blockIdx.z ? kp : qp;
    int idx = blockIdx.x * 256 + threadIdx.x;
    const int ci = idx & 3; idx >>= 2;
    const int h = idx & (Hh - 1); idx >>= 4;
    const int n = idx & (Nn_ - 1); idx >>= 11;
    const int b = idx;
    const int c = ci * 8;
    const size_t base = ((size_t)(b * Nn_ + n)) * Cdim + h * Dd;

    uint4 lo = *(uint4*)(t + base + c);
    uint4 hi = *(uint4*)(t + base + c + 32);
    const __half* xl = (const __half*)&lo;
    const __half* xh = (const __half*)&hi;

    const float* cb = cosb + n * Dd;
    const float* sb = sinb + n * Dd;
    float cl[8], sl[8], ch[8], sh[8];
    *(float4*)&cl[0] = *(const float4*)(cb + c);
    *(float4*)&cl[4] = *(const float4*)(cb + c + 4);
    *(float4*)&ch[0] = *(const float4*)(cb + c + 32);
    *(float4*)&ch[4] = *(const float4*)(cb + c + 36);
    *(float4*)&sl[0] = *(const float4*)(sb + c);
    *(float4*)&sl[4] = *(const float4*)(sb + c + 4);
    *(float4*)&sh[0] = *(const float4*)(sb + c + 32);
    *(float4*)&sh[4] = *(const float4*)(sb + c + 36);

    uint4 olo, ohi;
    __half* ol = (__half*)&olo;
    __half* oh = (__half*)&ohi;
    #pragma unroll
    for (int j = 0; j < 8; j++) {
        const float x1 = __half2float(xl[j]);
        const float x2 = __half2float(xh[j]);
        ol[j] = __float2half_rn(x1 * cl[j] - x2 * sl[j]);
        oh[j] = __float2half_rn(x2 * ch[j] + x1 * sh[j]);
    }
    *(uint4*)(t + base + c)      = olo;
    *(uint4*)(t + base + c + 32) = ohi;
}

// ---------------------------------------------------------------------------
// Flash attention: fp16 mma, ex2.f16x2, P in registers, ldmatrix fragments,
// 3-stage cp.async K/V pipeline, V row-major + ldmatrix.trans for PV.
// smem (halves): Qs[128][72] + 3 stages x (K[64][72] + V[64][72])
// ---------------------------------------------------------------------------
#define QSH 72
#define KV_ST (64 * QSH)
#define F_QS 0
#define F_KV (128 * QSH)
#define FLASH_SMEM ((128 * QSH + 3 * 2 * KV_ST) * 2)

__global__ void __launch_bounds__(256) flash_kernel(
    const __half* __restrict__ q, const __half* __restrict__ k,
    const __half* __restrict__ v, __half* __restrict__ out)
{
    extern __shared__ __half smf[];
    __half* Qs = smf + F_QS;
    const uint32_t sfbase = (uint32_t)__cvta_generic_to_shared(smf);

    const int tid  = threadIdx.x;
    const int wid  = tid >> 5;
    const int lane = tid & 31;
    const int lr   = lane >> 2;
    const int lc   = lane & 3;
    const int rm   = wid * 16;

    // ldmatrix lane mappings
    const int b_row  = (lane & 7) + ((lane >> 4) & 1) * 8;   // K (non-trans)
    const int b_col8 = ((lane >> 3) & 1) * 8;
    const int v_row  = (lane & 7) + ((lane >> 3) & 1) * 8;   // V (trans)
    const int v_col8 = ((lane >> 4) & 1) * 8;

    const int bh = blockIdx.y;
    const int b = bh >> 4;
    const int h = bh & 15;
    const int q0 = blockIdx.x * 128;
    const float qscale = 0.125f * 1.4426950408889634f;

    const __half* kb0 = k + ((size_t)(b * Nn_)) * Cdim + h * Dd;
    const __half* vb0 = v + ((size_t)(b * Nn_)) * Cdim + h * Dd;

    // K/V stage loader: 64x64 halves each = 512 chunks of 16B; 2 per thread.
    #define LOAD_KV(stg, kv0)                                                 \
    do {                                                                      \
        const uint32_t kBase = sfbase + (uint32_t)((F_KV + (stg) * 2 * KV_ST) * 2); \
        const uint32_t vBase = kBase + (uint32_t)(KV_ST * 2);                 \
        _Pragma("unroll")                                                     \
        for (int i = 0; i < 2; i++) {                                         \
            const int id = tid + i * 256;                                     \
            const int r = id >> 3;                                            \
            const int c = (id & 7) * 8;                                       \
            CP_ASYNC16(kBase + (uint32_t)((r * QSH + c) * 2),                 \
                       kb0 + (size_t)((kv0) + r) * Cdim + c);                 \
            CP_ASYNC16(vBase + (uint32_t)((r * QSH + c) * 2),                 \
                       vb0 + (size_t)((kv0) + r) * Cdim + c);                 \
        }                                                                     \
    } while (0)

    LOAD_KV(0, 0);
    CP_COMMIT();
    LOAD_KV(1, 64);
    CP_COMMIT();

    // load Q tile (scaled) while K/V stage 0/1 are in flight
    const __half* qb = q + ((size_t)(b * Nn_ + q0)) * Cdim + h * Dd;
    #pragma unroll
    for (int i = 0; i < 4; i++) {
        const int idx = tid + i * 256;
        const int r = idx >> 3;
        const int c = (idx & 7) * 8;
        uint4 u = *(const uint4*)(qb + (size_t)r * Cdim + c);
        __half2* hp = (__half2*)&u;
        #pragma unroll
        for (int j = 0; j < 4; j++) {
            float2 f = __half22float2(hp[j]);
            hp[j] = __floats2half2_rn(f.x * qscale, f.y * qscale);
        }
        *(uint4*)&Qs[r * QSH + c] = u;
    }
    __syncthreads();

    // hoist Q fragments
    uint32_t qf[4][4];
    #pragma unroll
    for (int ks = 0; ks < 4; ks++) {
        const int kk = ks * 16;
        qf[ks][0] = *(const uint32_t*)&Qs[(rm + lr) * QSH + kk + 2 * lc];
        qf[ks][1] = *(const uint32_t*)&Qs[(rm + lr + 8) * QSH + kk + 2 * lc];
        qf[ks][2] = *(const uint32_t*)&Qs[(rm + lr) * QSH + kk + 2 * lc + 8];
        qf[ks][3] = *(const uint32_t*)&Qs[(rm + lr + 8) * QSH + kk + 2 * lc + 8];
    }

    float m0 = -1e30f, m1 = -1e30f, l0 = 0.f, l1 = 0.f;
    float oacc[8][4];
    #pragma unroll
    for (int nt = 0; nt < 8; nt++)
        #pragma unroll
        for (int r = 0; r < 4; r++) oacc[nt][r] = 0.f;

    const int ntiles = Nn_ / 64;   // 32
    int stg = 0;
    for (int it = 0; it < ntiles; it++) {
        if (it + 1 < ntiles) { CP_WAIT(1); } else { CP_WAIT(0); }
        __syncthreads();

        if (it + 2 < ntiles) {
            const int ns = (stg + 2 >= 3) ? stg - 1 : stg + 2;
            LOAD_KV(ns, (it + 2) * 64);
            CP_COMMIT();
        }

        const uint32_t ksBase = sfbase + (uint32_t)((F_KV + stg * 2 * KV_ST) * 2);
        const uint32_t vsBase = ksBase + (uint32_t)(KV_ST * 2);

        // S = Q @ K^T
        float sacc[8][4];
        #pragma unroll
        for (int nt = 0; nt < 8; nt++)
            #pragma unroll
            for (int r = 0; r < 4; r++) sacc[nt][r] = 0.f;
        #pragma unroll
        for (int ks = 0; ks < 4; ks++) {
            const int kk = ks * 16;
            uint32_t bf[8][2];
            #pragma unroll
            for (int jp = 0; jp < 4; jp++) {
                const uint32_t addr = ksBase +
                    (uint32_t)(((jp * 16 + b_row) * QSH + kk + b_col8) * 2);
                LDSM_X4(bf[2 * jp][0], bf[2 * jp][1],
                        bf[2 * jp + 1][0], bf[2 * jp + 1][1], addr);
            }
            #pragma unroll
            for (int nt = 0; nt < 8; nt++)
                MMA_F16(sacc[nt], qf[ks], bf[nt]);
        }

        // online softmax; P via ex2.approx.f16x2
        float mx0 = -1e30f, mx1 = -1e30f;
        #pragma unroll
        for (int nt = 0; nt < 8; nt++) {
            mx0 = fmaxf(mx0, fmaxf(sacc[nt][0], sacc[nt][1]));
            mx1 = fmaxf(mx1, fmaxf(sacc[nt][2], sacc[nt][3]));
        }
        #pragma unroll
        for (int o = 1; o < 4; o <<= 1) {
            mx0 = fmaxf(mx0, __shfl_xor_sync(0xffffffffu, mx0, o, 4));
            mx1 = fmaxf(mx1, __shfl_xor_sync(0xffffffffu, mx1, o, 4));
        }
        const float mn0 = fmaxf(m0, mx0);
        const float mn1 = fmaxf(m1, mx1);
        const float al0 = exp2f(m0 - mn0);
        const float al1 = exp2f(m1 - mn1);
        float rs0 = 0.f, rs1 = 0.f;
        uint32_t pf[4][4];
        #pragma unroll
        for (int ks = 0; ks < 4; ks++) {
            const int ntA = 2 * ks, ntB = 2 * ks + 1;
            __half2 d0 = __floats2half2_rn(sacc[ntA][0] - mn0, sacc[ntA][1] - mn0);
            __half2 d1 = __floats2half2_rn(sacc[ntA][2] - mn1, sacc[ntA][3] - mn1);
            __half2 d2 = __floats2half2_rn(sacc[ntB][0] - mn0, sacc[ntB][1] - mn0);
            __half2 d3 = __floats2half2_rn(sacc[ntB][2] - mn1, sacc[ntB][3] - mn1);
            EX2_F16X2(pf[ks][0], h2u(d0));
            EX2_F16X2(pf[ks][1], h2u(d1));
            EX2_F16X2(pf[ks][2], h2u(d2));
            EX2_F16X2(pf[ks][3], h2u(d3));
            const float2 f0 = __half22float2(*(__half2*)&pf[ks][0]);
            const float2 f1 = __half22float2(*(__half2*)&pf[ks][1]);
            const float2 f2 = __half22float2(*(__half2*)&pf[ks][2]);
            const float2 f3 = __half22float2(*(__half2*)&pf[ks][3]);
            rs0 += f0.x + f0.y + f2.x + f2.y;
            rs1 += f1.x + f1.y + f3.x + f3.y;
        }
        #pragma unroll
        for (int o = 1; o < 4; o <<= 1) {
            rs0 += __shfl_xor_sync(0xffffffffu, rs0, o, 4);
            rs1 += __shfl_xor_sync(0xffffffffu, rs1, o, 4);
        }
        l0 = l0 * al0 + rs0;  m0 = mn0;
        l1 = l1 * al1 + rs1;  m1 = mn1;
        #pragma unroll
        for (int nt = 0; nt < 8; nt++) {
            oacc[nt][0] *= al0; oacc[nt][1] *= al0;
            oacc[nt][2] *= al1; oacc[nt][3] *= al1;
        }

        // O += P @ V (row-major V, trans ldmatrix -> B fragments)
        #pragma unroll
        for (int ks = 0; ks < 4; ks++) {
            const int kk = ks * 16;
            uint32_t bf[8][2];
            #pragma unroll
            for (int jp = 0; jp < 4; jp++) {
                const uint32_t addr = vsBase +
                    (uint32_t)(((kk + v_row) * QSH + jp * 16 + v_col8) * 2);
                LDSM_X4_T(bf[2 * jp][0], bf[2 * jp][1],
                          bf[2 * jp + 1][0], bf[2 * jp + 1][1], addr);
            }
            #pragma unroll
            for (int nt = 0; nt < 8; nt++)
                MMA_F16(oacc[nt], pf[ks], bf[nt]);
        }

        stg = (stg + 1 >= 3) ? 0 : stg + 1;
    }

    const float il0 = 1.0f / l0;
    const float il1 = 1.0f / l1;
    __half* ob = out + ((size_t)(b * Nn_ + q0 + rm)) * Cdim + h * Dd;
    #pragma unroll
    for (int nt = 0; nt < 8; nt++) {
        const int col = nt * 8 + 2 * lc;
        *(uint32_t*)(ob + (size_t)lr * Cdim + col) =
            h2u(__floats2half2_rn(oacc[nt][0] * il0, oacc[nt][1] * il0));
        *(uint32_t*)(ob + (size_t)(lr + 8) * Cdim + col) =
            h2u(__floats2half2_rn(oacc[nt][2] * il1, oacc[nt][3] * il1));
    }
}

// ---------------------------------------------------------------------------
extern "C" void kernel_launch(void* const* d_in, const int* in_sizes, int n_in,
                              void* d_out, int out_size)
{
    const float* x    = (const float*)d_in[0];
    const float* rcos = (const float*)d_in[1];
    const float* rsin = (const float*)d_in[2];
    const float* g1   = (const float*)d_in[3];
    const float* be1  = (const float*)d_in[4];
    const float* Wq   = (const float*)d_in[5];
    const float* bq   = (const float*)d_in[6];
    const float* Wk   = (const float*)d_in[7];
    const float* bk   = (const float*)d_in[8];
    const float* Wv   = (const float*)d_in[9];
    const float* bv   = (const float*)d_in[10];
    const float* Wo   = (const float*)d_in[11];
    const float* bo   = (const float*)d_in[12];
    const float* g2   = (const float*)d_in[13];
    const float* be2  = (const float*)d_in[14];
    const float* W1   = (const float*)d_in[15];
    const float* b1   = (const float*)d_in[16];
    const float* W2   = (const float*)d_in[17];
    const float* b2   = (const float*)d_in[18];
    float* out = (float*)d_out;

    unsigned char* base = nullptr;
    cudaGetSymbolAddress((void**)&base, g_scratch);
    __half* p_h   = (__half*)(base + OFF_H);
    __half* p_q   = (__half*)(base + OFF_Q);
    __half* p_k   = (__half*)(base + OFF_K);
    __half* p_v   = (__half*)(base + OFF_V);
    __half* p_att = (__half*)(base + OFF_ATT);
    __half* p_mlp = (__half*)(base + OFF_MLP);
    float*  p_x2  = (float*)(base + OFF_X2);
    __half* p_wq  = (__half*)(base + OFF_WQ);
    __half* p_wk  = (__half*)(base + OFF_WK);
    __half* p_wv  = (__half*)(base + OFF_WV);
    __half* p_wo  = (__half*)(base + OFF_WO);
    __half* p_w1  = (__half*)(base + OFF_W1);
    __half* p_w2  = (__half*)(base + OFF_W2);

    cudaFuncSetAttribute(flash_kernel,
                         cudaFuncAttributeMaxDynamicSharedMemorySize, FLASH_SMEM);
    cudaFuncSetAttribute(hgemm_kernel,
                         cudaFuncAttributeMaxDynamicSharedMemorySize, GEMM_SMEM);

    // 0. weights -> fp16
    const int nC4 = (Cdim * Cdim) / 4;
    const int nF4 = (Cdim * Fdim) / 4;
    ConvSet cs;
    cs.in[0] = (const float4*)Wq; cs.out[0] = (__half2*)p_wq;
    cs.in[1] = (const float4*)Wk; cs.out[1] = (__half2*)p_wk;
    cs.in[2] = (const float4*)Wv; cs.out[2] = (__half2*)p_wv;
    cs.in[3] = (const float4*)Wo; cs.out[3] = (__half2*)p_wo;
    cs.in[4] = (const float4*)W1; cs.out[4] = (__half2*)p_w1;
    cs.in[5] = (const float4*)W2; cs.out[5] = (__half2*)p_w2;
    cs.start[0] = 0;
    cs.start[1] = nC4;
    cs.start[2] = 2 * nC4;
    cs.start[3] = 3 * nC4;
    cs.start[4] = 4 * nC4;
    cs.start[5] = 4 * nC4 + nF4;
    cs.start[6] = 4 * nC4 + 2 * nF4;
    conv_half_kernel<<<3072, 256>>>(cs);

    // 1. LN1 -> half
    ln_kernel<<<Mrows, 256>>>(x, g1, be1, p_h);

    // 2. fused QKV projections -> half
    GemmSet qkv;
    qkv.W[0] = p_wq; qkv.W[1] = p_wk; qkv.W[2] = p_wv;
    qkv.bias[0] = bq; qkv.bias[1] = bk; qkv.bias[2] = bv;
    qkv.out[0] = p_q; qkv.out[1] = p_k; qkv.out[2] = p_v;
    hgemm_kernel<<<dim3(Cdim / 128, Mrows / 128, 3), 128, GEMM_SMEM>>>(
        p_h, qkv, nullptr, Mrows, Cdim, Cdim, 0, 1);

    // 3. RoPE
    rope2_kernel<<<dim3((Bb * Nn_ * Hh * 4) / 256, 1, 2), 256>>>(p_q, p_k, rcos, rsin);

    // 4. attention -> half
    flash_kernel<<<dim3(Nn_ / 128, Bb * Hh), 256, FLASH_SMEM>>>(p_q, p_k, p_v, p_att);

    // 5. output projection + fp32 residual -> fp32 x2
    GemmSet so;
    so.W[0] = p_wo; so.bias[0] = bo; so.out[0] = p_x2;
    so.W[1] = so.W[2] = nullptr; so.bias[1] = so.bias[2] = nullptr;
    so.out[1] = so.out[2] = nullptr;
    hgemm_kernel<<<dim3(Cdim / 128, Mrows / 128, 1), 128, GEMM_SMEM>>>(
        p_att, so, x, Mrows, Cdim, Cdim, 0, 0);

    // 6. LN2 -> half
    ln_kernel<<<Mrows, 256>>>(p_x2, g2, be2, p_h);

    // 7. MLP up + GELU -> half
    GemmSet s1;
    s1.W[0] = p_w1; s1.bias[0] = b1; s1.out[0] = p_mlp;
    s1.W[1] = s1.W[2] = nullptr; s1.bias[1] = s1.bias[2] = nullptr;
    s1.out[1] = s1.out[2] = nullptr;
    hgemm_kernel<<<dim3(Fdim / 128, Mrows / 128, 1), 128, GEMM_SMEM>>>(
        p_h, s1, nullptr, Mrows, Fdim, Cdim, 1, 1);

    // 8. MLP down + fp32 residual -> fp32 output
    GemmSet s2;
    s2.W[0] = p_w2; s2.bias[0] = b2; s2.out[0] = out;
    s2.W[1] = s2.W[2] = nullptr; s2.bias[1] = s2.bias[2] = nullptr;
    s2.out[1] = s2.out[2] = nullptr;
    hgemm_kernel<<<dim3(Cdim / 128, Mrows / 128, 1), 128, GEMM_SMEM>>>(
        p_mlp, s2, p_x2, Mrows, Cdim, Fdim, 0, 0);
}